// round 1
// baseline (speedup 1.0000x reference)
#include <cuda_runtime.h>
#include <cuda_bf16.h>
#include <math.h>

// Problem constants
#define B_  32
#define N_  1024
#define C_  1024
#define H_  16
#define HD_ 64
#define TOKENS (B_ * N_)        // 32768
#define TOKSTRIDE 3072          // 3*C per token in qkv buffer

// Scratch (device globals; no runtime allocation allowed)
__device__ float g_qkv[(size_t)TOKENS * TOKSTRIDE];   // [32768, 3072]
__device__ float g_attn[(size_t)TOKENS * C_];         // [32768, 1024]

// ---------------------------------------------------------------------------
// Classic fp32 SGEMM: C[M,N] = A[M,K] @ B[K,N] + bias[N]
// 128x128 tile, BK=8, 256 threads, 8x8 microtile.
// M % 128 == 0, N % 128 == 0, K % 8 == 0 (true for both calls).
// ---------------------------------------------------------------------------
#define BM 128
#define BN 128
#define BK 8

__global__ __launch_bounds__(256)
void sgemm_kernel(const float* __restrict__ A, const float* __restrict__ B,
                  const float* __restrict__ bias, float* __restrict__ C,
                  int M, int N, int K)
{
    __shared__ float As[BK][BM];
    __shared__ float Bs[BK][BN];

    const int tid  = threadIdx.x;
    const int row0 = blockIdx.y * BM;
    const int col0 = blockIdx.x * BN;
    const int ty   = tid >> 4;      // 0..15
    const int tx   = tid & 15;      // 0..15

    const int aRow = tid >> 1;          // 0..127
    const int aCol = (tid & 1) * 4;     // 0 or 4
    const int bRow = tid >> 5;          // 0..7
    const int bCol = (tid & 31) * 4;    // 0..124

    const float* Aptr = A + (size_t)(row0 + aRow) * K + aCol;
    const float* Bptr = B + (size_t)bRow * N + col0 + bCol;

    float acc[8][8];
#pragma unroll
    for (int i = 0; i < 8; i++)
#pragma unroll
        for (int j = 0; j < 8; j++) acc[i][j] = 0.0f;

    for (int k0 = 0; k0 < K; k0 += BK) {
        float4 av = *(const float4*)(Aptr + k0);
        float4 bv = *(const float4*)(Bptr + (size_t)k0 * N);

        As[aCol + 0][aRow] = av.x;
        As[aCol + 1][aRow] = av.y;
        As[aCol + 2][aRow] = av.z;
        As[aCol + 3][aRow] = av.w;
        *(float4*)&Bs[bRow][bCol] = bv;
        __syncthreads();

#pragma unroll
        for (int kk = 0; kk < BK; kk++) {
            float a[8], b[8];
            *(float4*)&a[0] = *(const float4*)&As[kk][ty * 8];
            *(float4*)&a[4] = *(const float4*)&As[kk][ty * 8 + 4];
            *(float4*)&b[0] = *(const float4*)&Bs[kk][tx * 8];
            *(float4*)&b[4] = *(const float4*)&Bs[kk][tx * 8 + 4];
#pragma unroll
            for (int i = 0; i < 8; i++)
#pragma unroll
                for (int j = 0; j < 8; j++)
                    acc[i][j] = fmaf(a[i], b[j], acc[i][j]);
        }
        __syncthreads();
    }

#pragma unroll
    for (int i = 0; i < 8; i++) {
        const int r = row0 + ty * 8 + i;
#pragma unroll
        for (int j = 0; j < 8; j += 4) {
            const int c = col0 + tx * 8 + j;
            float4 o;
            o.x = acc[i][j + 0] + bias[c + 0];
            o.y = acc[i][j + 1] + bias[c + 1];
            o.z = acc[i][j + 2] + bias[c + 2];
            o.w = acc[i][j + 3] + bias[c + 3];
            *(float4*)&C[(size_t)r * N + c] = o;
        }
    }
}

// ---------------------------------------------------------------------------
// Fused RMSNorm + 2D RoPE applied in place to q and k slices of g_qkv.
// One warp per (token, head, q/k). Lane holds dims 2*lane, 2*lane+1.
// ---------------------------------------------------------------------------
__global__ __launch_bounds__(256)
void normrope_kernel(float* __restrict__ qkv,
                     const float* __restrict__ q_gamma,
                     const float* __restrict__ k_gamma)
{
    const int gwarp = (blockIdx.x * blockDim.x + threadIdx.x) >> 5;
    const int lane  = threadIdx.x & 31;

    const int s   = gwarp & 1;          // 0=q, 1=k
    const int h   = (gwarp >> 1) & 15;
    const int tok = gwarp >> 5;         // 0..32767

    float* ptr = qkv + (size_t)tok * TOKSTRIDE + s * C_ + h * HD_;
    float2 v = ((float2*)ptr)[lane];

    // RMS over 64 dims
    float ss = v.x * v.x + v.y * v.y;
#pragma unroll
    for (int m = 16; m >= 1; m >>= 1)
        ss += __shfl_xor_sync(0xffffffffu, ss, m);
    const float inv = rsqrtf(ss * (1.0f / 64.0f) + 1e-6f);

    const float* gamma = s ? k_gamma : q_gamma;
    const int d0 = lane * 2;
    float n0 = v.x * inv * gamma[d0];
    float n1 = v.y * inv * gamma[d0 + 1];

    // rotate_half partner: d <-> d +/- 32  <=>  lane xor 16
    float p0 = __shfl_xor_sync(0xffffffffu, n0, 16);
    float p1 = __shfl_xor_sync(0xffffffffu, n1, 16);
    const bool lo = (d0 < 32);
    float r0 = lo ? -p0 : p0;
    float r1 = lo ? -p1 : p1;

    // angle: j = d (mod 32), freq = 10000^{-(j%16)/16}; t = row for d<32 else col
    const int n   = tok & (N_ - 1);
    const int row = n >> 5, col = n & 31;
    const float t = lo ? (float)row : (float)col;
    const int j0 = lo ? d0 : d0 - 32;
    const float LOG2_THETA = 13.28771237954945f;   // log2(10000)
    float f0 = exp2f(-(float)(j0 & 15)      * (1.0f / 16.0f) * LOG2_THETA);
    float f1 = exp2f(-(float)((j0 + 1) & 15) * (1.0f / 16.0f) * LOG2_THETA);
    float a0 = t * f0, a1 = t * f1;
    float s0, c0, s1, c1;
    sincosf(a0, &s0, &c0);
    sincosf(a1, &s1, &c1);

    float o0 = n0 * c0 + r0 * s0;
    float o1 = n1 * c1 + r1 * s1;
    ((float2*)ptr)[lane] = make_float2(o0, o1);
}

// ---------------------------------------------------------------------------
// fp32 flash attention: per CTA one (b,h) pair and a 128-query tile.
// BM=128 queries, BN=64 kv per step, hd=64. 128 threads: ty=tid/8 (rows*8),
// tx=tid%8 (cols*8). Online softmax in registers; P transposed via smem.
// ---------------------------------------------------------------------------
#define FA_BM 128
#define FA_BN 64
#define PADQ 4
#define PADK 4

struct FaSmem {
    float Qt[HD_][FA_BM + PADQ];     // Q transposed (dim-major), pre-scaled
    float Kt[HD_][FA_BN + PADK];     // K transposed (dim-major)
    float Vs[FA_BN][HD_ + PADK];     // V (kv-major)
    float Pt[FA_BN][FA_BM + PADQ];   // P transposed (kv-major)
};

__global__ __launch_bounds__(128)
void flash_kernel(const float* __restrict__ qkv, float* __restrict__ out)
{
    extern __shared__ char smem_raw[];
    FaSmem& sm = *reinterpret_cast<FaSmem*>(smem_raw);

    const int tid = threadIdx.x;
    const int ty  = tid >> 3;   // 0..15 -> rows ty*8
    const int tx  = tid & 7;    // 0..7  -> cols tx*8
    const int qtile = blockIdx.x;       // 0..7
    const int bh    = blockIdx.y;       // 0..511
    const int b = bh >> 4, h = bh & 15;

    const float* qbase = qkv + (size_t)b * N_ * TOKSTRIDE + h * HD_;
    const float* kbase = qbase + C_;
    const float* vbase = qbase + 2 * C_;

    // Load Q tile (pre-scaled by 1/sqrt(hd)) transposed into smem
    const float scale = 0.125f;
    for (int idx = tid; idx < FA_BM * (HD_ / 4); idx += 128) {
        int r  = idx >> 4;            // query row in tile
        int d4 = (idx & 15) * 4;
        float4 v = *(const float4*)(qbase + (size_t)(qtile * FA_BM + r) * TOKSTRIDE + d4);
        sm.Qt[d4 + 0][r] = v.x * scale;
        sm.Qt[d4 + 1][r] = v.y * scale;
        sm.Qt[d4 + 2][r] = v.z * scale;
        sm.Qt[d4 + 3][r] = v.w * scale;
    }

    float o[8][8];
    float m[8], l[8];
#pragma unroll
    for (int i = 0; i < 8; i++) {
        m[i] = -1e30f; l[i] = 0.0f;
#pragma unroll
        for (int j = 0; j < 8; j++) o[i][j] = 0.0f;
    }

    for (int kt = 0; kt < N_ / FA_BN; kt++) {
        __syncthreads();   // previous iteration done with Kt/Vs/Pt (also orders Qt on iter 0)

        // Load K (transposed) and V tiles
        for (int idx = tid; idx < FA_BN * (HD_ / 4); idx += 128) {
            int r  = idx >> 4;
            int d4 = (idx & 15) * 4;
            const float* krow = kbase + (size_t)(kt * FA_BN + r) * TOKSTRIDE + d4;
            float4 kv = *(const float4*)krow;
            sm.Kt[d4 + 0][r] = kv.x;
            sm.Kt[d4 + 1][r] = kv.y;
            sm.Kt[d4 + 2][r] = kv.z;
            sm.Kt[d4 + 3][r] = kv.w;
            float4 vv = *(const float4*)(vbase + (size_t)(kt * FA_BN + r) * TOKSTRIDE + d4);
            *(float4*)&sm.Vs[r][d4] = vv;
        }
        __syncthreads();

        // S = (Q*scale) @ K^T
        float s[8][8];
#pragma unroll
        for (int i = 0; i < 8; i++)
#pragma unroll
            for (int j = 0; j < 8; j++) s[i][j] = 0.0f;

#pragma unroll 4
        for (int d = 0; d < HD_; d++) {
            float qa[8], kb[8];
            *(float4*)&qa[0] = *(const float4*)&sm.Qt[d][ty * 8];
            *(float4*)&qa[4] = *(const float4*)&sm.Qt[d][ty * 8 + 4];
            *(float4*)&kb[0] = *(const float4*)&sm.Kt[d][tx * 8];
            *(float4*)&kb[4] = *(const float4*)&sm.Kt[d][tx * 8 + 4];
#pragma unroll
            for (int i = 0; i < 8; i++)
#pragma unroll
                for (int j = 0; j < 8; j++)
                    s[i][j] = fmaf(qa[i], kb[j], s[i][j]);
        }

        // Online softmax (reduce across the 8 tx lanes sharing each row)
#pragma unroll
        for (int i = 0; i < 8; i++) {
            float mx = s[i][0];
#pragma unroll
            for (int j = 1; j < 8; j++) mx = fmaxf(mx, s[i][j]);
            mx = fmaxf(mx, __shfl_xor_sync(0xffffffffu, mx, 1));
            mx = fmaxf(mx, __shfl_xor_sync(0xffffffffu, mx, 2));
            mx = fmaxf(mx, __shfl_xor_sync(0xffffffffu, mx, 4));
            float nm = fmaxf(m[i], mx);
            float alpha = __expf(m[i] - nm);
            float rs = 0.0f;
#pragma unroll
            for (int j = 0; j < 8; j++) {
                s[i][j] = __expf(s[i][j] - nm);
                rs += s[i][j];
            }
            rs += __shfl_xor_sync(0xffffffffu, rs, 1);
            rs += __shfl_xor_sync(0xffffffffu, rs, 2);
            rs += __shfl_xor_sync(0xffffffffu, rs, 4);
            l[i] = l[i] * alpha + rs;
            m[i] = nm;
#pragma unroll
            for (int j = 0; j < 8; j++) o[i][j] *= alpha;
        }

        // Store P transposed for PV GEMM
#pragma unroll
        for (int j = 0; j < 8; j++)
#pragma unroll
            for (int i = 0; i < 8; i++)
                sm.Pt[tx * 8 + j][ty * 8 + i] = s[i][j];
        __syncthreads();

        // O += P @ V
#pragma unroll 4
        for (int kk = 0; kk < FA_BN; kk++) {
            float pa[8], vb[8];
            *(float4*)&pa[0] = *(const float4*)&sm.Pt[kk][ty * 8];
            *(float4*)&pa[4] = *(const float4*)&sm.Pt[kk][ty * 8 + 4];
            *(float4*)&vb[0] = *(const float4*)&sm.Vs[kk][tx * 8];
            *(float4*)&vb[4] = *(const float4*)&sm.Vs[kk][tx * 8 + 4];
#pragma unroll
            for (int i = 0; i < 8; i++)
#pragma unroll
                for (int j = 0; j < 8; j++)
                    o[i][j] = fmaf(pa[i], vb[j], o[i][j]);
        }
    }

    // Epilogue: O /= l, write [token, h*64 + dim]
#pragma unroll
    for (int i = 0; i < 8; i++) {
        float inv = 1.0f / l[i];
        int q = qtile * FA_BM + ty * 8 + i;
        float* op = out + ((size_t)b * N_ + q) * C_ + h * HD_ + tx * 8;
        float4 v0 = make_float4(o[i][0] * inv, o[i][1] * inv, o[i][2] * inv, o[i][3] * inv);
        float4 v1 = make_float4(o[i][4] * inv, o[i][5] * inv, o[i][6] * inv, o[i][7] * inv);
        *(float4*)op = v0;
        *(float4*)(op + 4) = v1;
    }
}

// ---------------------------------------------------------------------------
// Launch
// ---------------------------------------------------------------------------
extern "C" void kernel_launch(void* const* d_in, const int* in_sizes, int n_in,
                              void* d_out, int out_size)
{
    const float* x       = (const float*)d_in[0];
    const float* qkv_w   = (const float*)d_in[1];
    const float* qkv_b   = (const float*)d_in[2];
    const float* proj_w  = (const float*)d_in[3];
    const float* proj_b  = (const float*)d_in[4];
    const float* q_gamma = (const float*)d_in[5];
    const float* k_gamma = (const float*)d_in[6];
    float* out = (float*)d_out;

    void* p_qkv = nullptr;
    void* p_attn = nullptr;
    cudaGetSymbolAddress(&p_qkv, g_qkv);
    cudaGetSymbolAddress(&p_attn, g_attn);
    float* qkv  = (float*)p_qkv;
    float* attn = (float*)p_attn;

    // 1. QKV GEMM: [32768,1024] @ [1024,3072]
    {
        dim3 grid(3 * C_ / BN, TOKENS / BM);
        sgemm_kernel<<<grid, 256>>>(x, qkv_w, qkv_b, qkv, TOKENS, 3 * C_, C_);
    }

    // 2. RMSNorm + RoPE on q,k (in place)
    {
        int warps = TOKENS * H_ * 2;              // 1,048,576
        int blocks = warps / 8;                   // 256 threads = 8 warps
        normrope_kernel<<<blocks, 256>>>(qkv, q_gamma, k_gamma);
    }

    // 3. Flash attention
    {
        size_t smem = sizeof(FaSmem);
        cudaFuncSetAttribute(flash_kernel, cudaFuncAttributeMaxDynamicSharedMemorySize,
                             (int)smem);
        dim3 grid(N_ / FA_BM, B_ * H_);
        flash_kernel<<<grid, 128, smem>>>(qkv, attn);
    }

    // 4. Output projection: [32768,1024] @ [1024,1024]
    {
        dim3 grid(C_ / BN, TOKENS / BM);
        sgemm_kernel<<<grid, 256>>>(attn, proj_w, proj_b, out, TOKENS, C_, C_);
    }
}

// round 2
// speedup vs baseline: 2.9247x; 2.9247x over previous
#include <cuda_runtime.h>
#include <cuda_bf16.h>
#include <math.h>
#include <stdint.h>

#define B_  32
#define N_  1024
#define C_  1024
#define H_  16
#define HD_ 64
#define TOKENS (B_ * N_)        // 32768
#define TOKSTRIDE 3072

// Scratch (static device globals; no runtime allocation)
__device__ float g_xr[(size_t)TOKENS * C_];          // tf32-rounded x
__device__ float g_wqkv[(size_t)C_ * 3 * C_];        // tf32-rounded qkv_w
__device__ float g_wproj[(size_t)C_ * C_];           // tf32-rounded proj_w
__device__ float g_qkv[(size_t)TOKENS * TOKSTRIDE];  // qkv activations
__device__ float g_attn[(size_t)TOKENS * C_];        // attention output

// ---------------------------------------------------------------------------
// Helpers
// ---------------------------------------------------------------------------
__device__ __forceinline__ float to_tf32(float x) {
    uint32_t u;
    asm("cvt.rna.tf32.f32 %0, %1;" : "=r"(u) : "f"(x));
    return __uint_as_float(u);
}

__device__ __forceinline__ void ldm_x4(uint32_t* r, const void* p) {
    uint32_t a = (uint32_t)__cvta_generic_to_shared(p);
    asm volatile("ldmatrix.sync.aligned.m8n8.x4.shared.b16 {%0,%1,%2,%3}, [%4];"
                 : "=r"(r[0]), "=r"(r[1]), "=r"(r[2]), "=r"(r[3]) : "r"(a));
}

__device__ __forceinline__ void mma_tf32(float* d, const uint32_t* a, const uint32_t* b) {
    asm volatile("mma.sync.aligned.m16n8k8.row.col.f32.tf32.tf32.f32 "
                 "{%0,%1,%2,%3}, {%4,%5,%6,%7}, {%8,%9}, {%0,%1,%2,%3};"
                 : "+f"(d[0]), "+f"(d[1]), "+f"(d[2]), "+f"(d[3])
                 : "r"(a[0]), "r"(a[1]), "r"(a[2]), "r"(a[3]), "r"(b[0]), "r"(b[1]));
}

__device__ __forceinline__ void cp16(void* dst, const void* src) {
    uint32_t d = (uint32_t)__cvta_generic_to_shared(dst);
    asm volatile("cp.async.cg.shared.global [%0], [%1], 16;" :: "r"(d), "l"(src));
}
__device__ __forceinline__ void cp_commit() { asm volatile("cp.async.commit_group;"); }
template <int NN>
__device__ __forceinline__ void cp_wait() { asm volatile("cp.async.wait_group %0;" :: "n"(NN)); }

// ---------------------------------------------------------------------------
// tf32 rounding prepass (elementwise, float4)
// ---------------------------------------------------------------------------
__global__ __launch_bounds__(256)
void round_tf32_kernel(const float* __restrict__ in, float* __restrict__ out) {
    int i = blockIdx.x * 256 + threadIdx.x;
    float4 v = ((const float4*)in)[i];
    v.x = to_tf32(v.x); v.y = to_tf32(v.y); v.z = to_tf32(v.z); v.w = to_tf32(v.w);
    ((float4*)out)[i] = v;
}

// ---------------------------------------------------------------------------
// tf32 tensor-core GEMM: C[M,N] = A[M,K] @ B[K,N] + bias
// CTA 128x128, BK=32, 256 threads (8 warps, 2x4), warp tile 64x32.
// A,B must be tf32-rounded fp32. cp.async double buffered.
// ---------------------------------------------------------------------------
__global__ __launch_bounds__(256)
void gemm_tf32_kernel(const float* __restrict__ A, const float* __restrict__ Bm,
                      const float* __restrict__ bias, float* __restrict__ C,
                      int M, int N, int K)
{
    extern __shared__ char sraw[];
    float (*As)[128][36] = (float(*)[128][36])sraw;                  // 2*128*36*4 = 36864
    float (*Bs)[32][132] = (float(*)[32][132])(sraw + 2 * 128 * 36 * 4); // 33792

    const int tid  = threadIdx.x;
    const int warp = tid >> 5, lane = tid & 31;
    const int wm = warp >> 2, wn = warp & 3;       // 2 x 4 warp grid
    const int g = lane >> 2, tq = lane & 3;
    const int row0 = blockIdx.y * 128;
    const int col0 = blockIdx.x * 128;

    const int ar  = tid >> 3;            // A: 32 rows per 256-pass? -> f>>3 pattern below
    const int KT = K / 32;

    // ---- stage loader (inlined twice) ----
#define LOAD_STAGE(S, KT0)                                                          \
    {                                                                               \
        _Pragma("unroll")                                                           \
        for (int i = 0; i < 4; i++) {                                               \
            int f = tid + i * 256;                                                  \
            int r_ = f >> 3, kb_ = f & 7;                                           \
            cp16(&As[S][r_][kb_ * 4],                                               \
                 A + (size_t)(row0 + r_) * K + (KT0) * 32 + kb_ * 4);               \
            int br_ = f >> 5, nb_ = f & 31;                                         \
            cp16(&Bs[S][br_][nb_ * 4],                                              \
                 Bm + (size_t)((KT0) * 32 + br_) * N + col0 + nb_ * 4);             \
        }                                                                           \
        cp_commit();                                                                \
    }

    float acc[4][4][4];
#pragma unroll
    for (int a = 0; a < 4; a++)
#pragma unroll
        for (int b = 0; b < 4; b++)
#pragma unroll
            for (int c = 0; c < 4; c++) acc[a][b][c] = 0.0f;

    LOAD_STAGE(0, 0);

    for (int kt = 0; kt < KT; kt++) {
        const int s = kt & 1;
        if (kt + 1 < KT) {
            LOAD_STAGE(s ^ 1, kt + 1);
            cp_wait<1>();
        } else {
            cp_wait<0>();
        }
        __syncthreads();

#pragma unroll
        for (int ks = 0; ks < 4; ks++) {
            const int k0 = ks * 8;
            uint32_t afr[4][4];
#pragma unroll
            for (int mt = 0; mt < 4; mt++)
                ldm_x4(afr[mt], &As[s][wm * 64 + mt * 16 + (lane & 15)][k0 + (lane >> 4) * 4]);
            uint32_t bfr[4][2];
#pragma unroll
            for (int nt = 0; nt < 4; nt++) {
                bfr[nt][0] = __float_as_uint(Bs[s][k0 + tq][wn * 32 + nt * 8 + g]);
                bfr[nt][1] = __float_as_uint(Bs[s][k0 + tq + 4][wn * 32 + nt * 8 + g]);
            }
#pragma unroll
            for (int mt = 0; mt < 4; mt++)
#pragma unroll
                for (int nt = 0; nt < 4; nt++)
                    mma_tf32(acc[mt][nt], afr[mt], bfr[nt]);
        }
        __syncthreads();
    }

    // Epilogue: bias + store (no rounding; consumers round as needed)
#pragma unroll
    for (int mt = 0; mt < 4; mt++) {
        const int r = row0 + wm * 64 + mt * 16 + g;
#pragma unroll
        for (int nt = 0; nt < 4; nt++) {
            const int c = col0 + wn * 32 + nt * 8 + 2 * tq;
            const float b0 = bias[c], b1 = bias[c + 1];
            float2 v0 = make_float2(acc[mt][nt][0] + b0, acc[mt][nt][1] + b1);
            float2 v1 = make_float2(acc[mt][nt][2] + b0, acc[mt][nt][3] + b1);
            *(float2*)&C[(size_t)r * N + c]       = v0;
            *(float2*)&C[(size_t)(r + 8) * N + c] = v1;
        }
    }
#undef LOAD_STAGE
}

// ---------------------------------------------------------------------------
// RMSNorm + 2D RoPE on q,k; tf32-round q,k,v in place.
// One warp per (token, head, {q,k,v}).
// ---------------------------------------------------------------------------
__global__ __launch_bounds__(256)
void normrope_kernel(float* __restrict__ qkv,
                     const float* __restrict__ q_gamma,
                     const float* __restrict__ k_gamma)
{
    const int gwarp = (blockIdx.x * blockDim.x + threadIdx.x) >> 5;
    const int lane  = threadIdx.x & 31;

    const int tok = gwarp / 48;
    const int rem = gwarp - tok * 48;
    const int s   = rem >> 4;           // 0=q, 1=k, 2=v
    const int h   = rem & 15;

    float* ptr = qkv + (size_t)tok * TOKSTRIDE + s * C_ + h * HD_;
    float2 v = ((float2*)ptr)[lane];

    if (s == 2) {   // v: just round to tf32
        ((float2*)ptr)[lane] = make_float2(to_tf32(v.x), to_tf32(v.y));
        return;
    }

    float ss = v.x * v.x + v.y * v.y;
#pragma unroll
    for (int m = 16; m >= 1; m >>= 1)
        ss += __shfl_xor_sync(0xffffffffu, ss, m);
    const float inv = rsqrtf(ss * (1.0f / 64.0f) + 1e-6f);

    const float* gamma = s ? k_gamma : q_gamma;
    const int d0 = lane * 2;
    float n0 = v.x * inv * gamma[d0];
    float n1 = v.y * inv * gamma[d0 + 1];

    float p0 = __shfl_xor_sync(0xffffffffu, n0, 16);
    float p1 = __shfl_xor_sync(0xffffffffu, n1, 16);
    const bool lo = (d0 < 32);
    float r0 = lo ? -p0 : p0;
    float r1 = lo ? -p1 : p1;

    const int n   = tok & (N_ - 1);
    const int row = n >> 5, col = n & 31;
    const float t = lo ? (float)row : (float)col;
    const int j0 = lo ? d0 : d0 - 32;
    const float LOG2_THETA = 13.28771237954945f;
    float f0 = exp2f(-(float)(j0 & 15)       * (1.0f / 16.0f) * LOG2_THETA);
    float f1 = exp2f(-(float)((j0 + 1) & 15) * (1.0f / 16.0f) * LOG2_THETA);
    float s0, c0, s1, c1;
    sincosf(t * f0, &s0, &c0);
    sincosf(t * f1, &s1, &c1);

    float o0 = to_tf32(n0 * c0 + r0 * s0);
    float o1 = to_tf32(n1 * c1 + r1 * s1);
    ((float2*)ptr)[lane] = make_float2(o0, o1);
}

// ---------------------------------------------------------------------------
// tf32 tensor-core flash attention.
// CTA: 256 queries x 64-kv tiles, hd=64. 8 warps, each warp owns 32 q rows.
// K/V double-buffered via cp.async. Q,K,V pre-rounded to tf32 (normrope).
// ---------------------------------------------------------------------------
struct FSmem {
    float Qs[256][68];      // pre-scaled Q
    float Ks[2][64][68];
    float Vs[2][64][68];
    float Ps[256][68];
};

__global__ __launch_bounds__(256, 1)
void flash_tf32_kernel(const float* __restrict__ qkv, float* __restrict__ out)
{
    extern __shared__ char sm_raw[];
    FSmem& sm = *reinterpret_cast<FSmem*>(sm_raw);

    const int tid  = threadIdx.x;
    const int warp = tid >> 5, lane = tid & 31;
    const int g = lane >> 2, tq = lane & 3;
    const int qtile = blockIdx.x;        // 0..3 (256 rows each)
    const int bh = blockIdx.y;           // 0..511
    const int b = bh >> 4, h = bh & 15;
    const int m0 = warp * 32;

    const float* qbase = qkv + (size_t)b * N_ * TOKSTRIDE + h * HD_;
    const float* kbase = qbase + C_;
    const float* vbase = qbase + 2 * C_;

    // Load Q tile (scale by 1/8: exact power of two, stays tf32)
    for (int i = tid; i < 4096; i += 256) {
        int r = i >> 4, d4 = (i & 15) * 4;
        float4 v = *(const float4*)(qbase + (size_t)(qtile * 256 + r) * TOKSTRIDE + d4);
        v.x *= 0.125f; v.y *= 0.125f; v.z *= 0.125f; v.w *= 0.125f;
        *(float4*)&sm.Qs[r][d4] = v;
    }

#define LOAD_KV(BUF, KT0)                                                           \
    {                                                                               \
        for (int i = tid; i < 1024; i += 256) {                                     \
            int r_ = i >> 4, d4_ = (i & 15) * 4;                                    \
            cp16(&sm.Ks[BUF][r_][d4_],                                              \
                 kbase + (size_t)((KT0) * 64 + r_) * TOKSTRIDE + d4_);              \
            cp16(&sm.Vs[BUF][r_][d4_],                                              \
                 vbase + (size_t)((KT0) * 64 + r_) * TOKSTRIDE + d4_);              \
        }                                                                           \
        cp_commit();                                                                \
    }

    LOAD_KV(0, 0);

    float o[2][8][4];
    float mr[2][2], lr[2][2];
#pragma unroll
    for (int a = 0; a < 2; a++) {
        mr[a][0] = mr[a][1] = -1e30f;
        lr[a][0] = lr[a][1] = 0.0f;
#pragma unroll
        for (int c = 0; c < 8; c++)
#pragma unroll
            for (int d = 0; d < 4; d++) o[a][c][d] = 0.0f;
    }

    for (int kt = 0; kt < 16; kt++) {
        const int buf = kt & 1;
        if (kt + 1 < 16) {
            LOAD_KV(buf ^ 1, kt + 1);
            cp_wait<1>();
        } else {
            cp_wait<0>();
        }
        __syncthreads();

        // ---- S = Q @ K^T ----
        float s[2][8][4];
#pragma unroll
        for (int a = 0; a < 2; a++)
#pragma unroll
            for (int c = 0; c < 8; c++)
#pragma unroll
                for (int d = 0; d < 4; d++) s[a][c][d] = 0.0f;

#pragma unroll
        for (int ks = 0; ks < 8; ks++) {
            const int k0 = ks * 8;
            uint32_t a[2][4];
            ldm_x4(a[0], &sm.Qs[m0 + (lane & 15)][k0 + (lane >> 4) * 4]);
            ldm_x4(a[1], &sm.Qs[m0 + 16 + (lane & 15)][k0 + (lane >> 4) * 4]);
            uint32_t bb[8][2];
#pragma unroll
            for (int p = 0; p < 4; p++) {
                uint32_t r4[4];
                ldm_x4(r4, &sm.Ks[buf][p * 16 + (lane >> 4) * 8 + (lane & 7)]
                                     [k0 + ((lane >> 3) & 1) * 4]);
                bb[2 * p][0] = r4[0]; bb[2 * p][1] = r4[1];
                bb[2 * p + 1][0] = r4[2]; bb[2 * p + 1][1] = r4[3];
            }
#pragma unroll
            for (int mt = 0; mt < 2; mt++)
#pragma unroll
                for (int nt = 0; nt < 8; nt++)
                    mma_tf32(s[mt][nt], a[mt], bb[nt]);
        }

        // ---- online softmax ----
#pragma unroll
        for (int mt = 0; mt < 2; mt++) {
#pragma unroll
            for (int hf = 0; hf < 2; hf++) {
                float mx = -1e30f;
#pragma unroll
                for (int nt = 0; nt < 8; nt++)
                    mx = fmaxf(mx, fmaxf(s[mt][nt][hf * 2], s[mt][nt][hf * 2 + 1]));
                mx = fmaxf(mx, __shfl_xor_sync(0xffffffffu, mx, 1));
                mx = fmaxf(mx, __shfl_xor_sync(0xffffffffu, mx, 2));
                const float mn = fmaxf(mr[mt][hf], mx);
                const float al = __expf(mr[mt][hf] - mn);
                mr[mt][hf] = mn;
                float rs = 0.0f;
#pragma unroll
                for (int nt = 0; nt < 8; nt++) {
                    float e0 = __expf(s[mt][nt][hf * 2]     - mn);
                    float e1 = __expf(s[mt][nt][hf * 2 + 1] - mn);
                    s[mt][nt][hf * 2] = e0; s[mt][nt][hf * 2 + 1] = e1;
                    rs += e0 + e1;
                }
                rs += __shfl_xor_sync(0xffffffffu, rs, 1);
                rs += __shfl_xor_sync(0xffffffffu, rs, 2);
                lr[mt][hf] = lr[mt][hf] * al + rs;
#pragma unroll
                for (int nt = 0; nt < 8; nt++) {
                    o[mt][nt][hf * 2]     *= al;
                    o[mt][nt][hf * 2 + 1] *= al;
                }
            }
        }

        // ---- store P (tf32-rounded) ----
#pragma unroll
        for (int mt = 0; mt < 2; mt++)
#pragma unroll
            for (int nt = 0; nt < 8; nt++) {
                const int r = m0 + mt * 16 + g, c = nt * 8 + 2 * tq;
                *(float2*)&sm.Ps[r][c] =
                    make_float2(to_tf32(s[mt][nt][0]), to_tf32(s[mt][nt][1]));
                *(float2*)&sm.Ps[r + 8][c] =
                    make_float2(to_tf32(s[mt][nt][2]), to_tf32(s[mt][nt][3]));
            }
        __syncwarp();

        // ---- O += P @ V ----
#pragma unroll
        for (int ks = 0; ks < 8; ks++) {
            const int k0 = ks * 8;
            uint32_t pa[2][4];
            ldm_x4(pa[0], &sm.Ps[m0 + (lane & 15)][k0 + (lane >> 4) * 4]);
            ldm_x4(pa[1], &sm.Ps[m0 + 16 + (lane & 15)][k0 + (lane >> 4) * 4]);
            uint32_t vb[8][2];
#pragma unroll
            for (int nt = 0; nt < 8; nt++) {
                vb[nt][0] = __float_as_uint(sm.Vs[buf][k0 + tq][nt * 8 + g]);
                vb[nt][1] = __float_as_uint(sm.Vs[buf][k0 + tq + 4][nt * 8 + g]);
            }
#pragma unroll
            for (int mt = 0; mt < 2; mt++)
#pragma unroll
                for (int nt = 0; nt < 8; nt++)
                    mma_tf32(o[mt][nt], pa[mt], vb[nt]);
        }
        __syncthreads();
    }

    // ---- epilogue: O /= l, round to tf32, store ----
#pragma unroll
    for (int mt = 0; mt < 2; mt++) {
        const float i0 = 1.0f / lr[mt][0];
        const float i1 = 1.0f / lr[mt][1];
        const int r = qtile * 256 + m0 + mt * 16 + g;
#pragma unroll
        for (int nt = 0; nt < 8; nt++) {
            const int c = h * 64 + nt * 8 + 2 * tq;
            *(float2*)&out[(size_t)(b * N_ + r) * C_ + c] =
                make_float2(to_tf32(o[mt][nt][0] * i0), to_tf32(o[mt][nt][1] * i0));
            *(float2*)&out[(size_t)(b * N_ + r + 8) * C_ + c] =
                make_float2(to_tf32(o[mt][nt][2] * i1), to_tf32(o[mt][nt][3] * i1));
        }
    }
#undef LOAD_KV
}

// ---------------------------------------------------------------------------
// Launch
// ---------------------------------------------------------------------------
extern "C" void kernel_launch(void* const* d_in, const int* in_sizes, int n_in,
                              void* d_out, int out_size)
{
    const float* x       = (const float*)d_in[0];
    const float* qkv_w   = (const float*)d_in[1];
    const float* qkv_b   = (const float*)d_in[2];
    const float* proj_w  = (const float*)d_in[3];
    const float* proj_b  = (const float*)d_in[4];
    const float* q_gamma = (const float*)d_in[5];
    const float* k_gamma = (const float*)d_in[6];
    float* out = (float*)d_out;

    void *p_xr, *p_wqkv, *p_wproj, *p_qkv, *p_attn;
    cudaGetSymbolAddress(&p_xr, g_xr);
    cudaGetSymbolAddress(&p_wqkv, g_wqkv);
    cudaGetSymbolAddress(&p_wproj, g_wproj);
    cudaGetSymbolAddress(&p_qkv, g_qkv);
    cudaGetSymbolAddress(&p_attn, g_attn);
    float* xr    = (float*)p_xr;
    float* wqkv  = (float*)p_wqkv;
    float* wproj = (float*)p_wproj;
    float* qkv   = (float*)p_qkv;
    float* attn  = (float*)p_attn;

    const int gemm_smem  = (2 * 128 * 36 + 2 * 32 * 132) * 4;   // 70656
    const int flash_smem = (int)sizeof(FSmem);                  // 208896
    cudaFuncSetAttribute(gemm_tf32_kernel,
                         cudaFuncAttributeMaxDynamicSharedMemorySize, gemm_smem);
    cudaFuncSetAttribute(flash_tf32_kernel,
                         cudaFuncAttributeMaxDynamicSharedMemorySize, flash_smem);

    // 0. tf32 rounding prepass
    round_tf32_kernel<<<(TOKENS * C_) / 1024, 256>>>(x, xr);
    round_tf32_kernel<<<(C_ * 3 * C_) / 1024, 256>>>(qkv_w, wqkv);
    round_tf32_kernel<<<(C_ * C_) / 1024, 256>>>(proj_w, wproj);

    // 1. QKV GEMM
    {
        dim3 grid(3 * C_ / 128, TOKENS / 128);
        gemm_tf32_kernel<<<grid, 256, gemm_smem>>>(xr, wqkv, qkv_b, qkv,
                                                   TOKENS, 3 * C_, C_);
    }

    // 2. RMSNorm + RoPE (+ tf32 rounding of q,k,v)
    {
        int warps = TOKENS * 48;
        normrope_kernel<<<warps / 8, 256>>>(qkv, q_gamma, k_gamma);
    }

    // 3. Flash attention (tf32 tensor cores)
    {
        dim3 grid(N_ / 256, B_ * H_);
        flash_tf32_kernel<<<grid, 256, flash_smem>>>(qkv, attn);
    }

    // 4. Output projection
    {
        dim3 grid(C_ / 128, TOKENS / 128);
        gemm_tf32_kernel<<<grid, 256, gemm_smem>>>(attn, wproj, proj_b, out,
                                                   TOKENS, C_, C_);
    }
}

// round 4
// speedup vs baseline: 3.0661x; 1.0483x over previous
#include <cuda_runtime.h>
#include <cuda_bf16.h>
#include <math.h>
#include <stdint.h>

#define B_  32
#define N_  1024
#define C_  1024
#define H_  16
#define HD_ 64
#define TOKENS (B_ * N_)        // 32768
#define TOKSTRIDE 3072

// Scratch (static device globals; no runtime allocation)
__device__ float g_xr[(size_t)TOKENS * C_];          // tf32-rounded x
__device__ float g_wqkv[(size_t)C_ * 3 * C_];        // tf32-rounded qkv_w [1024][3072]
__device__ float g_wproj[(size_t)C_ * C_];           // tf32-rounded proj_w [1024][1024]
__device__ float g_qkv[(size_t)TOKENS * TOKSTRIDE];  // qkv activations
__device__ float g_attn[(size_t)TOKENS * C_];        // attention output

// ---------------------------------------------------------------------------
// Helpers
// ---------------------------------------------------------------------------
__device__ __forceinline__ float to_tf32(float x) {
    uint32_t u;
    asm("cvt.rna.tf32.f32 %0, %1;" : "=r"(u) : "f"(x));
    return __uint_as_float(u);
}

__device__ __forceinline__ void ldm_x4(uint32_t* r, const void* p) {
    uint32_t a = (uint32_t)__cvta_generic_to_shared(p);
    asm volatile("ldmatrix.sync.aligned.m8n8.x4.shared.b16 {%0,%1,%2,%3}, [%4];"
                 : "=r"(r[0]), "=r"(r[1]), "=r"(r[2]), "=r"(r[3]) : "r"(a));
}

__device__ __forceinline__ void mma_tf32(float* d, const uint32_t* a, const uint32_t* b) {
    asm volatile("mma.sync.aligned.m16n8k8.row.col.f32.tf32.tf32.f32 "
                 "{%0,%1,%2,%3}, {%4,%5,%6,%7}, {%8,%9}, {%0,%1,%2,%3};"
                 : "+f"(d[0]), "+f"(d[1]), "+f"(d[2]), "+f"(d[3])
                 : "r"(a[0]), "r"(a[1]), "r"(a[2]), "r"(a[3]), "r"(b[0]), "r"(b[1]));
}

__device__ __forceinline__ void cp16(void* dst, const void* src) {
    uint32_t d = (uint32_t)__cvta_generic_to_shared(dst);
    asm volatile("cp.async.cg.shared.global [%0], [%1], 16;" :: "r"(d), "l"(src));
}
__device__ __forceinline__ void cp_commit() { asm volatile("cp.async.commit_group;"); }
template <int NN>
__device__ __forceinline__ void cp_wait() { asm volatile("cp.async.wait_group %0;" :: "n"(NN)); }

// ---------------------------------------------------------------------------
// tf32 rounding prepass (elementwise, float4)
// ---------------------------------------------------------------------------
__global__ __launch_bounds__(256)
void round_tf32_kernel(const float* __restrict__ in, float* __restrict__ out) {
    int i = blockIdx.x * 256 + threadIdx.x;
    float4 v = ((const float4*)in)[i];
    v.x = to_tf32(v.x); v.y = to_tf32(v.y); v.z = to_tf32(v.z); v.w = to_tf32(v.w);
    ((float4*)out)[i] = v;
}

// ---------------------------------------------------------------------------
// tf32 HMMA GEMM: C[M,N] = A[M,K] @ B[K,N] + bias
// CTA 128x128, BK=32, 256 threads (8 warps, 2x4), warp tile 64x32.
// 3-stage cp.async pipeline, 2 CTAs/SM (regs capped at 128).
// ---------------------------------------------------------------------------
__global__ __launch_bounds__(256, 2)
void gemm_tf32_kernel(const float* __restrict__ A, const float* __restrict__ Bm,
                      const float* __restrict__ bias, float* __restrict__ C,
                      int M, int N, int K)
{
    extern __shared__ char sraw[];
    float (*As)[128][36] = (float(*)[128][36])sraw;                      // 3*18432
    float (*Bs)[32][132] = (float(*)[32][132])(sraw + 3 * 128 * 36 * 4); // 3*16896

    const int tid  = threadIdx.x;
    const int warp = tid >> 5, lane = tid & 31;
    const int wm = warp >> 2, wn = warp & 3;       // 2 x 4 warp grid
    const int g = lane >> 2, tq = lane & 3;
    const int row0 = blockIdx.y * 128;
    const int col0 = blockIdx.x * 128;
    const int KT = K / 32;

#define LOAD_STAGE(S, KT0)                                                          \
    {                                                                               \
        _Pragma("unroll")                                                           \
        for (int i = 0; i < 4; i++) {                                               \
            int f = tid + i * 256;                                                  \
            int r_ = f >> 3, kb_ = f & 7;                                           \
            cp16(&As[S][r_][kb_ * 4],                                               \
                 A + (size_t)(row0 + r_) * K + (KT0) * 32 + kb_ * 4);               \
            int br_ = f >> 5, nb_ = f & 31;                                         \
            cp16(&Bs[S][br_][nb_ * 4],                                              \
                 Bm + (size_t)((KT0) * 32 + br_) * N + col0 + nb_ * 4);             \
        }                                                                           \
        cp_commit();                                                                \
    }

    float acc[4][4][4];
#pragma unroll
    for (int a = 0; a < 4; a++)
#pragma unroll
        for (int b = 0; b < 4; b++)
#pragma unroll
            for (int c = 0; c < 4; c++) acc[a][b][c] = 0.0f;

    LOAD_STAGE(0, 0);
    LOAD_STAGE(1, 1);

    for (int kt = 0; kt < KT; kt++) {
        const int s = kt % 3;
        if (kt + 1 < KT) { cp_wait<1>(); } else { cp_wait<0>(); }
        __syncthreads();

        if (kt + 2 < KT) { LOAD_STAGE((kt + 2) % 3, kt + 2); }

#pragma unroll
        for (int ks = 0; ks < 4; ks++) {
            const int k0 = ks * 8;
            uint32_t afr[4][4];
#pragma unroll
            for (int mt = 0; mt < 4; mt++)
                ldm_x4(afr[mt], &As[s][wm * 64 + mt * 16 + (lane & 15)][k0 + (lane >> 4) * 4]);
            uint32_t bfr[4][2];
#pragma unroll
            for (int nt = 0; nt < 4; nt++) {
                bfr[nt][0] = __float_as_uint(Bs[s][k0 + tq][wn * 32 + nt * 8 + g]);
                bfr[nt][1] = __float_as_uint(Bs[s][k0 + tq + 4][wn * 32 + nt * 8 + g]);
            }
#pragma unroll
            for (int mt = 0; mt < 4; mt++)
#pragma unroll
                for (int nt = 0; nt < 4; nt++)
                    mma_tf32(acc[mt][nt], afr[mt], bfr[nt]);
        }
        __syncthreads();
    }

    // Epilogue: bias + store
#pragma unroll
    for (int mt = 0; mt < 4; mt++) {
        const int r = row0 + wm * 64 + mt * 16 + g;
#pragma unroll
        for (int nt = 0; nt < 4; nt++) {
            const int c = col0 + wn * 32 + nt * 8 + 2 * tq;
            const float b0 = bias[c], b1 = bias[c + 1];
            float2 v0 = make_float2(acc[mt][nt][0] + b0, acc[mt][nt][1] + b1);
            float2 v1 = make_float2(acc[mt][nt][2] + b0, acc[mt][nt][3] + b1);
            *(float2*)&C[(size_t)r * N + c]       = v0;
            *(float2*)&C[(size_t)(r + 8) * N + c] = v1;
        }
    }
#undef LOAD_STAGE
}

#define GEMM_SMEM ((3 * 128 * 36 + 3 * 32 * 132) * 4)   // 105984

// ---------------------------------------------------------------------------
// RMSNorm + 2D RoPE on q,k; tf32-round q,k,v in place.
// ---------------------------------------------------------------------------
__global__ __launch_bounds__(256)
void normrope_kernel(float* __restrict__ qkv,
                     const float* __restrict__ q_gamma,
                     const float* __restrict__ k_gamma)
{
    const int gwarp = (blockIdx.x * blockDim.x + threadIdx.x) >> 5;
    const int lane  = threadIdx.x & 31;

    const int tok = gwarp / 48;
    const int rem = gwarp - tok * 48;
    const int s   = rem >> 4;           // 0=q, 1=k, 2=v
    const int h   = rem & 15;

    float* ptr = qkv + (size_t)tok * TOKSTRIDE + s * C_ + h * HD_;
    float2 v = ((float2*)ptr)[lane];

    if (s == 2) {
        ((float2*)ptr)[lane] = make_float2(to_tf32(v.x), to_tf32(v.y));
        return;
    }

    float ss = v.x * v.x + v.y * v.y;
#pragma unroll
    for (int m = 16; m >= 1; m >>= 1)
        ss += __shfl_xor_sync(0xffffffffu, ss, m);
    const float inv = rsqrtf(ss * (1.0f / 64.0f) + 1e-6f);

    const float* gamma = s ? k_gamma : q_gamma;
    const int d0 = lane * 2;
    float n0 = v.x * inv * gamma[d0];
    float n1 = v.y * inv * gamma[d0 + 1];

    float p0 = __shfl_xor_sync(0xffffffffu, n0, 16);
    float p1 = __shfl_xor_sync(0xffffffffu, n1, 16);
    const bool lo = (d0 < 32);
    float r0 = lo ? -p0 : p0;
    float r1 = lo ? -p1 : p1;

    const int n   = tok & (N_ - 1);
    const int row = n >> 5, col = n & 31;
    const float t = lo ? (float)row : (float)col;
    const int j0 = lo ? d0 : d0 - 32;
    const float LOG2_THETA = 13.28771237954945f;
    float f0 = exp2f(-(float)(j0 & 15)       * (1.0f / 16.0f) * LOG2_THETA);
    float f1 = exp2f(-(float)((j0 + 1) & 15) * (1.0f / 16.0f) * LOG2_THETA);
    float s0, c0, s1, c1;
    sincosf(t * f0, &s0, &c0);
    sincosf(t * f1, &s1, &c1);

    float o0 = to_tf32(n0 * c0 + r0 * s0);
    float o1 = to_tf32(n1 * c1 + r1 * s1);
    ((float2*)ptr)[lane] = make_float2(o0, o1);
}

// ---------------------------------------------------------------------------
// tf32 HMMA flash attention.
// CTA: 256 queries x 64-kv tiles, hd=64. 16 warps (512 thr), warp = 16 q rows.
// ---------------------------------------------------------------------------
struct FSmem {
    float Qs[256][68];
    float Ks[2][64][68];
    float Vs[2][64][68];
    float Ps[256][68];
};

__global__ __launch_bounds__(512, 1)
void flash_tf32_kernel(const float* __restrict__ qkv, float* __restrict__ out)
{
    extern __shared__ char sm_raw[];
    FSmem& sm = *reinterpret_cast<FSmem*>(sm_raw);

    const int tid  = threadIdx.x;
    const int warp = tid >> 5, lane = tid & 31;
    const int g = lane >> 2, tq = lane & 3;
    const int qtile = blockIdx.x;        // 0..3
    const int bh = blockIdx.y;           // 0..511
    const int b = bh >> 4, h = bh & 15;
    const int m0 = warp * 16;

    const float* qbase = qkv + (size_t)b * N_ * TOKSTRIDE + h * HD_;
    const float* kbase = qbase + C_;
    const float* vbase = qbase + 2 * C_;

    for (int i = tid; i < 4096; i += 512) {
        int r = i >> 4, d4 = (i & 15) * 4;
        float4 v = *(const float4*)(qbase + (size_t)(qtile * 256 + r) * TOKSTRIDE + d4);
        v.x *= 0.125f; v.y *= 0.125f; v.z *= 0.125f; v.w *= 0.125f;
        *(float4*)&sm.Qs[r][d4] = v;
    }

#define LOAD_KV(BUF, KT0)                                                           \
    {                                                                               \
        for (int i = tid; i < 1024; i += 512) {                                     \
            int r_ = i >> 4, d4_ = (i & 15) * 4;                                    \
            cp16(&sm.Ks[BUF][r_][d4_],                                              \
                 kbase + (size_t)((KT0) * 64 + r_) * TOKSTRIDE + d4_);              \
            cp16(&sm.Vs[BUF][r_][d4_],                                              \
                 vbase + (size_t)((KT0) * 64 + r_) * TOKSTRIDE + d4_);              \
        }                                                                           \
        cp_commit();                                                                \
    }

    LOAD_KV(0, 0);

    float o[8][4];
    float mr[2], lr[2];
    mr[0] = mr[1] = -1e30f;
    lr[0] = lr[1] = 0.0f;
#pragma unroll
    for (int c = 0; c < 8; c++)
#pragma unroll
        for (int d = 0; d < 4; d++) o[c][d] = 0.0f;

    for (int kt = 0; kt < 16; kt++) {
        const int buf = kt & 1;
        if (kt + 1 < 16) { LOAD_KV(buf ^ 1, kt + 1); cp_wait<1>(); }
        else             { cp_wait<0>(); }
        __syncthreads();

        // ---- S = Q @ K^T ----
        float s[8][4];
#pragma unroll
        for (int c = 0; c < 8; c++)
#pragma unroll
            for (int d = 0; d < 4; d++) s[c][d] = 0.0f;

#pragma unroll
        for (int ks = 0; ks < 8; ks++) {
            const int k0 = ks * 8;
            uint32_t a[4];
            ldm_x4(a, &sm.Qs[m0 + (lane & 15)][k0 + (lane >> 4) * 4]);
            uint32_t bb[8][2];
#pragma unroll
            for (int p = 0; p < 4; p++) {
                uint32_t r4[4];
                ldm_x4(r4, &sm.Ks[buf][p * 16 + (lane >> 4) * 8 + (lane & 7)]
                                     [k0 + ((lane >> 3) & 1) * 4]);
                bb[2 * p][0] = r4[0]; bb[2 * p][1] = r4[1];
                bb[2 * p + 1][0] = r4[2]; bb[2 * p + 1][1] = r4[3];
            }
#pragma unroll
            for (int nt = 0; nt < 8; nt++)
                mma_tf32(s[nt], a, bb[nt]);
        }

        // ---- online softmax ----
#pragma unroll
        for (int hf = 0; hf < 2; hf++) {
            float mx = -1e30f;
#pragma unroll
            for (int nt = 0; nt < 8; nt++)
                mx = fmaxf(mx, fmaxf(s[nt][hf * 2], s[nt][hf * 2 + 1]));
            mx = fmaxf(mx, __shfl_xor_sync(0xffffffffu, mx, 1));
            mx = fmaxf(mx, __shfl_xor_sync(0xffffffffu, mx, 2));
            const float mn = fmaxf(mr[hf], mx);
            const float al = __expf(mr[hf] - mn);
            mr[hf] = mn;
            float rs = 0.0f;
#pragma unroll
            for (int nt = 0; nt < 8; nt++) {
                float e0 = __expf(s[nt][hf * 2]     - mn);
                float e1 = __expf(s[nt][hf * 2 + 1] - mn);
                s[nt][hf * 2] = e0; s[nt][hf * 2 + 1] = e1;
                rs += e0 + e1;
            }
            rs += __shfl_xor_sync(0xffffffffu, rs, 1);
            rs += __shfl_xor_sync(0xffffffffu, rs, 2);
            lr[hf] = lr[hf] * al + rs;
#pragma unroll
            for (int nt = 0; nt < 8; nt++) {
                o[nt][hf * 2]     *= al;
                o[nt][hf * 2 + 1] *= al;
            }
        }

        // ---- store P (tf32-rounded) ----
#pragma unroll
        for (int nt = 0; nt < 8; nt++) {
            const int r = m0 + g, c = nt * 8 + 2 * tq;
            *(float2*)&sm.Ps[r][c]     = make_float2(to_tf32(s[nt][0]), to_tf32(s[nt][1]));
            *(float2*)&sm.Ps[r + 8][c] = make_float2(to_tf32(s[nt][2]), to_tf32(s[nt][3]));
        }
        __syncwarp();

        // ---- O += P @ V ----
#pragma unroll
        for (int ks = 0; ks < 8; ks++) {
            const int k0 = ks * 8;
            uint32_t pa[4];
            ldm_x4(pa, &sm.Ps[m0 + (lane & 15)][k0 + (lane >> 4) * 4]);
            uint32_t vb[8][2];
#pragma unroll
            for (int nt = 0; nt < 8; nt++) {
                vb[nt][0] = __float_as_uint(sm.Vs[buf][k0 + tq][nt * 8 + g]);
                vb[nt][1] = __float_as_uint(sm.Vs[buf][k0 + tq + 4][nt * 8 + g]);
            }
#pragma unroll
            for (int nt = 0; nt < 8; nt++)
                mma_tf32(o[nt], pa, vb[nt]);
        }
        __syncthreads();
    }

    // ---- epilogue ----
    {
        const float i0 = 1.0f / lr[0];
        const float i1 = 1.0f / lr[1];
        const int r = qtile * 256 + m0 + g;
#pragma unroll
        for (int nt = 0; nt < 8; nt++) {
            const int c = h * 64 + nt * 8 + 2 * tq;
            *(float2*)&out[(size_t)(b * N_ + r) * C_ + c] =
                make_float2(to_tf32(o[nt][0] * i0), to_tf32(o[nt][1] * i0));
            *(float2*)&out[(size_t)(b * N_ + r + 8) * C_ + c] =
                make_float2(to_tf32(o[nt][2] * i1), to_tf32(o[nt][3] * i1));
        }
    }
#undef LOAD_KV
}

// ---------------------------------------------------------------------------
// Launch
// ---------------------------------------------------------------------------
extern "C" void kernel_launch(void* const* d_in, const int* in_sizes, int n_in,
                              void* d_out, int out_size)
{
    const float* x       = (const float*)d_in[0];
    const float* qkv_w   = (const float*)d_in[1];
    const float* qkv_b   = (const float*)d_in[2];
    const float* proj_w  = (const float*)d_in[3];
    const float* proj_b  = (const float*)d_in[4];
    const float* q_gamma = (const float*)d_in[5];
    const float* k_gamma = (const float*)d_in[6];
    float* out = (float*)d_out;

    void *p_xr, *p_wqkv, *p_wproj, *p_qkv, *p_attn;
    cudaGetSymbolAddress(&p_xr, g_xr);
    cudaGetSymbolAddress(&p_wqkv, g_wqkv);
    cudaGetSymbolAddress(&p_wproj, g_wproj);
    cudaGetSymbolAddress(&p_qkv, g_qkv);
    cudaGetSymbolAddress(&p_attn, g_attn);
    float* xr    = (float*)p_xr;
    float* wqkv  = (float*)p_wqkv;
    float* wproj = (float*)p_wproj;
    float* qkv   = (float*)p_qkv;
    float* attn  = (float*)p_attn;

    const int flash_smem = (int)sizeof(FSmem);
    cudaFuncSetAttribute(gemm_tf32_kernel,
                         cudaFuncAttributeMaxDynamicSharedMemorySize, GEMM_SMEM);
    cudaFuncSetAttribute(flash_tf32_kernel,
                         cudaFuncAttributeMaxDynamicSharedMemorySize, flash_smem);

    // 0. tf32 rounding prepass
    round_tf32_kernel<<<(TOKENS * C_) / 1024, 256>>>(x, xr);
    round_tf32_kernel<<<(C_ * 3 * C_) / 1024, 256>>>(qkv_w, wqkv);
    round_tf32_kernel<<<(C_ * C_) / 1024, 256>>>(proj_w, wproj);

    // 1. QKV GEMM
    {
        dim3 grid(3 * C_ / 128, TOKENS / 128);
        gemm_tf32_kernel<<<grid, 256, GEMM_SMEM>>>(xr, wqkv, qkv_b, qkv,
                                                   TOKENS, 3 * C_, C_);
    }

    // 2. RMSNorm + RoPE (+ tf32 rounding of q,k,v)
    {
        int warps = TOKENS * 48;
        normrope_kernel<<<warps / 8, 256>>>(qkv, q_gamma, k_gamma);
    }

    // 3. Flash attention
    {
        dim3 grid(N_ / 256, B_ * H_);
        flash_tf32_kernel<<<grid, 512, flash_smem>>>(qkv, attn);
    }

    // 4. Output projection
    {
        dim3 grid(C_ / 128, TOKENS / 128);
        gemm_tf32_kernel<<<grid, 256, GEMM_SMEM>>>(attn, wproj, proj_b, out,
                                                   TOKENS, C_, C_);
    }
}

// round 5
// speedup vs baseline: 5.8093x; 1.8947x over previous
#include <cuda_runtime.h>
#include <cuda_fp16.h>
#include <math.h>
#include <stdint.h>

#define B_  32
#define N_  1024
#define C_  1024
#define H_  16
#define HD_ 64
#define TOKENS (B_ * N_)        // 32768
#define TOKSTRIDE 3072

// Scratch (static device globals; no runtime allocation)
__device__ __half g_xh[(size_t)TOKENS * C_];           // fp16 x
__device__ __half g_wqkvh[(size_t)C_ * 3 * C_];        // fp16 qkv_w [1024][3072]
__device__ __half g_wprojh[(size_t)C_ * C_];           // fp16 proj_w [1024][1024]
__device__ float  g_qkv[(size_t)TOKENS * TOKSTRIDE];   // qkv activations fp32
__device__ __half g_qkvh[(size_t)TOKENS * TOKSTRIDE];  // fp16 q(roped)/k(roped)/v
__device__ __half g_attnh[(size_t)TOKENS * C_];        // fp16 attention output

// ---------------------------------------------------------------------------
// Helpers
// ---------------------------------------------------------------------------
__device__ __forceinline__ void ldm_x4(uint32_t* r, const void* p) {
    uint32_t a = (uint32_t)__cvta_generic_to_shared(p);
    asm volatile("ldmatrix.sync.aligned.m8n8.x4.shared.b16 {%0,%1,%2,%3}, [%4];"
                 : "=r"(r[0]), "=r"(r[1]), "=r"(r[2]), "=r"(r[3]) : "r"(a));
}
__device__ __forceinline__ void ldm_x4_t(uint32_t* r, const void* p) {
    uint32_t a = (uint32_t)__cvta_generic_to_shared(p);
    asm volatile("ldmatrix.sync.aligned.m8n8.x4.trans.shared.b16 {%0,%1,%2,%3}, [%4];"
                 : "=r"(r[0]), "=r"(r[1]), "=r"(r[2]), "=r"(r[3]) : "r"(a));
}

__device__ __forceinline__ void mma_f16(float* d, const uint32_t* a, const uint32_t* b) {
    asm volatile("mma.sync.aligned.m16n8k16.row.col.f32.f16.f16.f32 "
                 "{%0,%1,%2,%3}, {%4,%5,%6,%7}, {%8,%9}, {%0,%1,%2,%3};"
                 : "+f"(d[0]), "+f"(d[1]), "+f"(d[2]), "+f"(d[3])
                 : "r"(a[0]), "r"(a[1]), "r"(a[2]), "r"(a[3]), "r"(b[0]), "r"(b[1]));
}

__device__ __forceinline__ void cp16(void* dst, const void* src) {
    uint32_t d = (uint32_t)__cvta_generic_to_shared(dst);
    asm volatile("cp.async.cg.shared.global [%0], [%1], 16;" :: "r"(d), "l"(src));
}
__device__ __forceinline__ void cp_commit() { asm volatile("cp.async.commit_group;"); }
template <int NN>
__device__ __forceinline__ void cp_wait() { asm volatile("cp.async.wait_group %0;" :: "n"(NN)); }

// ---------------------------------------------------------------------------
// fp32 -> fp16 conversion prepass (4 elems / thread)
// ---------------------------------------------------------------------------
__global__ __launch_bounds__(256)
void to_half_kernel(const float* __restrict__ in, __half* __restrict__ out) {
    int i = blockIdx.x * 256 + threadIdx.x;
    float4 v = ((const float4*)in)[i];
    half2 h0 = __floats2half2_rn(v.x, v.y);
    half2 h1 = __floats2half2_rn(v.z, v.w);
    ((half2*)out)[i * 2]     = h0;
    ((half2*)out)[i * 2 + 1] = h1;
}

// ---------------------------------------------------------------------------
// fp16 HMMA GEMM: C[M,N](fp32) = A[M,K](f16) @ B[K,N](f16) + bias
// CTA 128x128, BK=32, 256 threads (8 warps, 2x4), warp tile 64x32.
// 3-stage cp.async pipeline.
// ---------------------------------------------------------------------------
__global__ __launch_bounds__(256, 2)
void gemm_f16_kernel(const __half* __restrict__ A, const __half* __restrict__ Bm,
                     const float* __restrict__ bias, float* __restrict__ C,
                     int M, int N, int K)
{
    extern __shared__ char sraw[];
    __half (*As)[128][40]  = (__half(*)[128][40])sraw;                        // 3*10240
    __half (*Bs)[32][136]  = (__half(*)[32][136])(sraw + 3 * 128 * 40 * 2);   // 3*8704

    const int tid  = threadIdx.x;
    const int warp = tid >> 5, lane = tid & 31;
    const int wm = warp >> 2, wn = warp & 3;       // 2 x 4 warp grid
    const int g = lane >> 2, tq = lane & 3;
    const int row0 = blockIdx.y * 128;
    const int col0 = blockIdx.x * 128;
    const int KT = K / 32;

#define LOAD_STAGE(S, KT0)                                                          \
    {                                                                               \
        _Pragma("unroll")                                                           \
        for (int i = 0; i < 2; i++) {                                               \
            int f = tid + i * 256;                                                  \
            int r_ = f >> 2, u_ = f & 3;                                            \
            cp16(&As[S][r_][u_ * 8],                                                \
                 A + (size_t)(row0 + r_) * K + (KT0) * 32 + u_ * 8);                \
            int br_ = f >> 4, nb_ = f & 15;                                         \
            cp16(&Bs[S][br_][nb_ * 8],                                              \
                 Bm + (size_t)((KT0) * 32 + br_) * N + col0 + nb_ * 8);             \
        }                                                                           \
        cp_commit();                                                                \
    }

    float acc[4][4][4];
#pragma unroll
    for (int a = 0; a < 4; a++)
#pragma unroll
        for (int b = 0; b < 4; b++)
#pragma unroll
            for (int c = 0; c < 4; c++) acc[a][b][c] = 0.0f;

    LOAD_STAGE(0, 0);
    LOAD_STAGE(1, 1);

    for (int kt = 0; kt < KT; kt++) {
        const int s = kt % 3;
        if (kt + 1 < KT) { cp_wait<1>(); } else { cp_wait<0>(); }
        __syncthreads();

        if (kt + 2 < KT) { LOAD_STAGE((kt + 2) % 3, kt + 2); }

#pragma unroll
        for (int ks = 0; ks < 2; ks++) {
            const int k0 = ks * 16;
            uint32_t afr[4][4];
#pragma unroll
            for (int mt = 0; mt < 4; mt++)
                ldm_x4(afr[mt], &As[s][wm * 64 + mt * 16 + (lane & 15)]
                                     [k0 + (lane >> 4) * 8]);
            uint32_t bfr[4][2];
#pragma unroll
            for (int nt2 = 0; nt2 < 2; nt2++) {
                uint32_t r4[4];
                ldm_x4_t(r4, &Bs[s][k0 + (lane & 15)]
                                   [wn * 32 + nt2 * 16 + (lane >> 4) * 8]);
                bfr[nt2 * 2][0]     = r4[0]; bfr[nt2 * 2][1]     = r4[1];
                bfr[nt2 * 2 + 1][0] = r4[2]; bfr[nt2 * 2 + 1][1] = r4[3];
            }
#pragma unroll
            for (int mt = 0; mt < 4; mt++)
#pragma unroll
                for (int nt = 0; nt < 4; nt++)
                    mma_f16(acc[mt][nt], afr[mt], bfr[nt]);
        }
        __syncthreads();
    }

    // Epilogue: bias + store fp32
#pragma unroll
    for (int mt = 0; mt < 4; mt++) {
        const int r = row0 + wm * 64 + mt * 16 + g;
#pragma unroll
        for (int nt = 0; nt < 4; nt++) {
            const int c = col0 + wn * 32 + nt * 8 + 2 * tq;
            const float b0 = bias[c], b1 = bias[c + 1];
            float2 v0 = make_float2(acc[mt][nt][0] + b0, acc[mt][nt][1] + b1);
            float2 v1 = make_float2(acc[mt][nt][2] + b0, acc[mt][nt][3] + b1);
            *(float2*)&C[(size_t)r * N + c]       = v0;
            *(float2*)&C[(size_t)(r + 8) * N + c] = v1;
        }
    }
#undef LOAD_STAGE
}

#define GEMM_SMEM ((3 * 128 * 40 + 3 * 32 * 136) * 2)   // 56832

// ---------------------------------------------------------------------------
// RMSNorm + 2D RoPE on q,k (fp32 in), fp16 out for q,k,v.
// One warp per (token, head, {q,k,v}).
// ---------------------------------------------------------------------------
__global__ __launch_bounds__(256)
void normrope_kernel(const float* __restrict__ qkv, __half* __restrict__ qkvh,
                     const float* __restrict__ q_gamma,
                     const float* __restrict__ k_gamma)
{
    const int gwarp = (blockIdx.x * blockDim.x + threadIdx.x) >> 5;
    const int lane  = threadIdx.x & 31;

    const int tok = gwarp / 48;
    const int rem = gwarp - tok * 48;
    const int s   = rem >> 4;           // 0=q, 1=k, 2=v
    const int h   = rem & 15;

    const size_t off = (size_t)tok * TOKSTRIDE + s * C_ + h * HD_;
    float2 v = ((const float2*)(qkv + off))[lane];
    half2* outp = (half2*)(qkvh + off);

    if (s == 2) {
        outp[lane] = __floats2half2_rn(v.x, v.y);
        return;
    }

    float ss = v.x * v.x + v.y * v.y;
#pragma unroll
    for (int m = 16; m >= 1; m >>= 1)
        ss += __shfl_xor_sync(0xffffffffu, ss, m);
    const float inv = rsqrtf(ss * (1.0f / 64.0f) + 1e-6f);

    const float* gamma = s ? k_gamma : q_gamma;
    const int d0 = lane * 2;
    float n0 = v.x * inv * gamma[d0];
    float n1 = v.y * inv * gamma[d0 + 1];

    float p0 = __shfl_xor_sync(0xffffffffu, n0, 16);
    float p1 = __shfl_xor_sync(0xffffffffu, n1, 16);
    const bool lo = (d0 < 32);
    float r0 = lo ? -p0 : p0;
    float r1 = lo ? -p1 : p1;

    const int n   = tok & (N_ - 1);
    const int row = n >> 5, col = n & 31;
    const float t = lo ? (float)row : (float)col;
    const int j0 = lo ? d0 : d0 - 32;
    const float LOG2_THETA = 13.28771237954945f;
    float f0 = exp2f(-(float)(j0 & 15)       * (1.0f / 16.0f) * LOG2_THETA);
    float f1 = exp2f(-(float)((j0 + 1) & 15) * (1.0f / 16.0f) * LOG2_THETA);
    float s0, c0, s1, c1;
    sincosf(t * f0, &s0, &c0);
    sincosf(t * f1, &s1, &c1);

    outp[lane] = __floats2half2_rn(n0 * c0 + r0 * s0, n1 * c1 + r1 * s1);
}

// ---------------------------------------------------------------------------
// fp16 HMMA flash attention.
// CTA: 256 queries x 64-kv tiles, hd=64. 16 warps (512 thr), warp = 16 q rows.
// ---------------------------------------------------------------------------
struct FSmem {
    __half Qs[256][72];      // pre-scaled Q
    __half Ks[2][64][72];
    __half Vs[2][64][72];
    __half Ps[256][72];
};

__global__ __launch_bounds__(512, 1)
void flash_f16_kernel(const __half* __restrict__ qkvh, __half* __restrict__ out)
{
    extern __shared__ char sm_raw[];
    FSmem& sm = *reinterpret_cast<FSmem*>(sm_raw);

    const int tid  = threadIdx.x;
    const int warp = tid >> 5, lane = tid & 31;
    const int g = lane >> 2, tq = lane & 3;
    const int qtile = blockIdx.x;        // 0..3
    const int bh = blockIdx.y;           // 0..511
    const int b = bh >> 4, h = bh & 15;
    const int m0 = warp * 16;

    const __half* qbase = qkvh + (size_t)b * N_ * TOKSTRIDE + h * HD_;
    const __half* kbase = qbase + C_;
    const __half* vbase = qbase + 2 * C_;

    // Load Q tile (scale by 1/8, exact in fp16)
    const half2 hscale = __floats2half2_rn(0.125f, 0.125f);
    for (int i = tid; i < 4096; i += 512) {      // 4096 quads of 4 halves
        int r = i >> 4, d4 = (i & 15) * 4;
        half2 a = *(const half2*)(qbase + (size_t)(qtile * 256 + r) * TOKSTRIDE + d4);
        half2 c = *(const half2*)(qbase + (size_t)(qtile * 256 + r) * TOKSTRIDE + d4 + 2);
        *(half2*)&sm.Qs[r][d4]     = __hmul2(a, hscale);
        *(half2*)&sm.Qs[r][d4 + 2] = __hmul2(c, hscale);
    }

#define LOAD_KV(BUF, KT0)                                                           \
    {                                                                               \
        for (int i = tid; i < 1024; i += 512) {                                     \
            int r_ = i >> 3, u_ = (i & 7) * 8;                                      \
            if (i < 512)                                                            \
                cp16(&sm.Ks[BUF][r_][u_],                                           \
                     kbase + (size_t)((KT0) * 64 + r_) * TOKSTRIDE + u_);           \
            else                                                                    \
                cp16(&sm.Vs[BUF][r_ - 64][u_],                                      \
                     vbase + (size_t)((KT0) * 64 + r_ - 64) * TOKSTRIDE + u_);      \
        }                                                                           \
        cp_commit();                                                                \
    }

    LOAD_KV(0, 0);

    float o[8][4];
    float mr[2], lr[2];
    mr[0] = mr[1] = -1e30f;
    lr[0] = lr[1] = 0.0f;
#pragma unroll
    for (int c = 0; c < 8; c++)
#pragma unroll
        for (int d = 0; d < 4; d++) o[c][d] = 0.0f;

    const int ki = lane & 7, kq = lane >> 3;     // for K-frag addressing

    for (int kt = 0; kt < 16; kt++) {
        const int buf = kt & 1;
        if (kt + 1 < 16) { LOAD_KV(buf ^ 1, kt + 1); cp_wait<1>(); }
        else             { cp_wait<0>(); }
        __syncthreads();

        // ---- S = Q @ K^T ----
        float s[8][4];
#pragma unroll
        for (int c = 0; c < 8; c++)
#pragma unroll
            for (int d = 0; d < 4; d++) s[c][d] = 0.0f;

#pragma unroll
        for (int ks = 0; ks < 4; ks++) {
            const int k0 = ks * 16;
            uint32_t a[4];
            ldm_x4(a, &sm.Qs[m0 + (lane & 15)][k0 + (lane >> 4) * 8]);
#pragma unroll
            for (int nt2 = 0; nt2 < 4; nt2++) {
                uint32_t r4[4];
                // non-trans: rows = kv index, cols = k dim
                ldm_x4(r4, &sm.Ks[buf][nt2 * 16 + (kq >> 1) * 8 + ki]
                                      [k0 + (kq & 1) * 8]);
                uint32_t b0[2] = { r4[0], r4[1] };
                uint32_t b1[2] = { r4[2], r4[3] };
                mma_f16(s[nt2 * 2],     a, b0);
                mma_f16(s[nt2 * 2 + 1], a, b1);
            }
        }

        // ---- online softmax ----
#pragma unroll
        for (int hf = 0; hf < 2; hf++) {
            float mx = -1e30f;
#pragma unroll
            for (int nt = 0; nt < 8; nt++)
                mx = fmaxf(mx, fmaxf(s[nt][hf * 2], s[nt][hf * 2 + 1]));
            mx = fmaxf(mx, __shfl_xor_sync(0xffffffffu, mx, 1));
            mx = fmaxf(mx, __shfl_xor_sync(0xffffffffu, mx, 2));
            const float mn = fmaxf(mr[hf], mx);
            const float al = __expf(mr[hf] - mn);
            mr[hf] = mn;
            float rs = 0.0f;
#pragma unroll
            for (int nt = 0; nt < 8; nt++) {
                float e0 = __expf(s[nt][hf * 2]     - mn);
                float e1 = __expf(s[nt][hf * 2 + 1] - mn);
                s[nt][hf * 2] = e0; s[nt][hf * 2 + 1] = e1;
                rs += e0 + e1;
            }
            rs += __shfl_xor_sync(0xffffffffu, rs, 1);
            rs += __shfl_xor_sync(0xffffffffu, rs, 2);
            lr[hf] = lr[hf] * al + rs;
#pragma unroll
            for (int nt = 0; nt < 8; nt++) {
                o[nt][hf * 2]     *= al;
                o[nt][hf * 2 + 1] *= al;
            }
        }

        // ---- store P (fp16) ----
#pragma unroll
        for (int nt = 0; nt < 8; nt++) {
            const int r = m0 + g, c = nt * 8 + 2 * tq;
            *(half2*)&sm.Ps[r][c]     = __floats2half2_rn(s[nt][0], s[nt][1]);
            *(half2*)&sm.Ps[r + 8][c] = __floats2half2_rn(s[nt][2], s[nt][3]);
        }
        __syncwarp();

        // ---- O += P @ V ----
#pragma unroll
        for (int ks = 0; ks < 4; ks++) {
            const int k0 = ks * 16;
            uint32_t pa[4];
            ldm_x4(pa, &sm.Ps[m0 + (lane & 15)][k0 + (lane >> 4) * 8]);
#pragma unroll
            for (int nt2 = 0; nt2 < 4; nt2++) {
                uint32_t r4[4];
                ldm_x4_t(r4, &sm.Vs[buf][k0 + (lane & 15)]
                                        [nt2 * 16 + (lane >> 4) * 8]);
                uint32_t b0[2] = { r4[0], r4[1] };
                uint32_t b1[2] = { r4[2], r4[3] };
                mma_f16(o[nt2 * 2],     pa, b0);
                mma_f16(o[nt2 * 2 + 1], pa, b1);
            }
        }
        __syncthreads();
    }

    // ---- epilogue: O /= l, store fp16 ----
    {
        const float i0 = 1.0f / lr[0];
        const float i1 = 1.0f / lr[1];
        const int r = qtile * 256 + m0 + g;
#pragma unroll
        for (int nt = 0; nt < 8; nt++) {
            const int c = h * 64 + nt * 8 + 2 * tq;
            *(half2*)&out[(size_t)(b * N_ + r) * C_ + c] =
                __floats2half2_rn(o[nt][0] * i0, o[nt][1] * i0);
            *(half2*)&out[(size_t)(b * N_ + r + 8) * C_ + c] =
                __floats2half2_rn(o[nt][2] * i1, o[nt][3] * i1);
        }
    }
#undef LOAD_KV
}

// ---------------------------------------------------------------------------
// Launch
// ---------------------------------------------------------------------------
extern "C" void kernel_launch(void* const* d_in, const int* in_sizes, int n_in,
                              void* d_out, int out_size)
{
    const float* x       = (const float*)d_in[0];
    const float* qkv_w   = (const float*)d_in[1];
    const float* qkv_b   = (const float*)d_in[2];
    const float* proj_w  = (const float*)d_in[3];
    const float* proj_b  = (const float*)d_in[4];
    const float* q_gamma = (const float*)d_in[5];
    const float* k_gamma = (const float*)d_in[6];
    float* out = (float*)d_out;

    void *p_xh, *p_wqkvh, *p_wprojh, *p_qkv, *p_qkvh, *p_attnh;
    cudaGetSymbolAddress(&p_xh, g_xh);
    cudaGetSymbolAddress(&p_wqkvh, g_wqkvh);
    cudaGetSymbolAddress(&p_wprojh, g_wprojh);
    cudaGetSymbolAddress(&p_qkv, g_qkv);
    cudaGetSymbolAddress(&p_qkvh, g_qkvh);
    cudaGetSymbolAddress(&p_attnh, g_attnh);
    __half* xh     = (__half*)p_xh;
    __half* wqkvh  = (__half*)p_wqkvh;
    __half* wprojh = (__half*)p_wprojh;
    float*  qkv    = (float*)p_qkv;
    __half* qkvh   = (__half*)p_qkvh;
    __half* attnh  = (__half*)p_attnh;

    const int flash_smem = (int)sizeof(FSmem);
    cudaFuncSetAttribute(gemm_f16_kernel,
                         cudaFuncAttributeMaxDynamicSharedMemorySize, GEMM_SMEM);
    cudaFuncSetAttribute(flash_f16_kernel,
                         cudaFuncAttributeMaxDynamicSharedMemorySize, flash_smem);

    // 0. fp16 conversion prepass
    to_half_kernel<<<(TOKENS * C_) / 1024, 256>>>(x, xh);
    to_half_kernel<<<(C_ * 3 * C_) / 1024, 256>>>(qkv_w, wqkvh);
    to_half_kernel<<<(C_ * C_) / 1024, 256>>>(proj_w, wprojh);

    // 1. QKV GEMM (fp16 HMMA, fp32 out)
    {
        dim3 grid(3 * C_ / 128, TOKENS / 128);
        gemm_f16_kernel<<<grid, 256, GEMM_SMEM>>>(xh, wqkvh, qkv_b, qkv,
                                                  TOKENS, 3 * C_, C_);
    }

    // 2. RMSNorm + RoPE (fp32 in, fp16 out)
    {
        int warps = TOKENS * 48;
        normrope_kernel<<<warps / 8, 256>>>(qkv, qkvh, q_gamma, k_gamma);
    }

    // 3. Flash attention (fp16 HMMA, fp16 out)
    {
        dim3 grid(N_ / 256, B_ * H_);
        flash_f16_kernel<<<grid, 512, flash_smem>>>(qkvh, attnh);
    }

    // 4. Output projection (fp16 HMMA, fp32 out)
    {
        dim3 grid(C_ / 128, TOKENS / 128);
        gemm_f16_kernel<<<grid, 256, GEMM_SMEM>>>(attnh, wprojh, proj_b, out,
                                                  TOKENS, C_, C_);
    }
}

// round 6
// speedup vs baseline: 6.0408x; 1.0399x over previous
#include <cuda_runtime.h>
#include <cuda_fp16.h>
#include <math.h>
#include <stdint.h>

#define B_  32
#define N_  1024
#define C_  1024
#define H_  16
#define HD_ 64
#define TOKENS (B_ * N_)        // 32768
#define TOKSTRIDE 3072

// Scratch (static device globals; no runtime allocation)
__device__ __half g_xh[(size_t)TOKENS * C_];           // fp16 x
__device__ __half g_wqkvh[(size_t)C_ * 3 * C_];        // fp16 qkv_w [1024][3072]
__device__ __half g_wprojh[(size_t)C_ * C_];           // fp16 proj_w [1024][1024]
__device__ float  g_qkv[(size_t)TOKENS * TOKSTRIDE];   // qkv activations fp32
__device__ __half g_qkvh[(size_t)TOKENS * TOKSTRIDE];  // fp16 q(roped)/k(roped)/v
__device__ __half g_attnh[(size_t)TOKENS * C_];        // fp16 attention output

// ---------------------------------------------------------------------------
// Helpers
// ---------------------------------------------------------------------------
__device__ __forceinline__ void ldm_x4(uint32_t* r, const void* p) {
    uint32_t a = (uint32_t)__cvta_generic_to_shared(p);
    asm volatile("ldmatrix.sync.aligned.m8n8.x4.shared.b16 {%0,%1,%2,%3}, [%4];"
                 : "=r"(r[0]), "=r"(r[1]), "=r"(r[2]), "=r"(r[3]) : "r"(a));
}
__device__ __forceinline__ void ldm_x4_t(uint32_t* r, const void* p) {
    uint32_t a = (uint32_t)__cvta_generic_to_shared(p);
    asm volatile("ldmatrix.sync.aligned.m8n8.x4.trans.shared.b16 {%0,%1,%2,%3}, [%4];"
                 : "=r"(r[0]), "=r"(r[1]), "=r"(r[2]), "=r"(r[3]) : "r"(a));
}

__device__ __forceinline__ void mma_f16(float* d, const uint32_t* a, const uint32_t* b) {
    asm volatile("mma.sync.aligned.m16n8k16.row.col.f32.f16.f16.f32 "
                 "{%0,%1,%2,%3}, {%4,%5,%6,%7}, {%8,%9}, {%0,%1,%2,%3};"
                 : "+f"(d[0]), "+f"(d[1]), "+f"(d[2]), "+f"(d[3])
                 : "r"(a[0]), "r"(a[1]), "r"(a[2]), "r"(a[3]), "r"(b[0]), "r"(b[1]));
}

__device__ __forceinline__ void cp16(void* dst, const void* src) {
    uint32_t d = (uint32_t)__cvta_generic_to_shared(dst);
    asm volatile("cp.async.cg.shared.global [%0], [%1], 16;" :: "r"(d), "l"(src));
}
__device__ __forceinline__ void cp_commit() { asm volatile("cp.async.commit_group;"); }
template <int NN>
__device__ __forceinline__ void cp_wait() { asm volatile("cp.async.wait_group %0;" :: "n"(NN)); }

// ---------------------------------------------------------------------------
// fp32 -> fp16 conversion prepass
// ---------------------------------------------------------------------------
__global__ __launch_bounds__(256)
void to_half_kernel(const float* __restrict__ in, __half* __restrict__ out) {
    int i = blockIdx.x * 256 + threadIdx.x;
    float4 v = ((const float4*)in)[i];
    ((half2*)out)[i * 2]     = __floats2half2_rn(v.x, v.y);
    ((half2*)out)[i * 2 + 1] = __floats2half2_rn(v.z, v.w);
}

// ---------------------------------------------------------------------------
// fp16 HMMA GEMM: C[M,N](fp32) = A[M,K](f16) @ B[K,N](f16) + bias
// CTA 128x128, BK=32, 128 threads (4 warps, 2x2 of 64x64 warp tiles).
// 3-stage cp.async pipeline, 2 CTAs/SM.
// ---------------------------------------------------------------------------
__global__ __launch_bounds__(128, 2)
void gemm_f16_kernel(const __half* __restrict__ A, const __half* __restrict__ Bm,
                     const float* __restrict__ bias, float* __restrict__ C,
                     int M, int N, int K)
{
    extern __shared__ char sraw[];
    __half (*As)[128][40]  = (__half(*)[128][40])sraw;                        // 3*10240
    __half (*Bs)[32][136]  = (__half(*)[32][136])(sraw + 3 * 128 * 40 * 2);   // 3*8704

    const int tid  = threadIdx.x;
    const int warp = tid >> 5, lane = tid & 31;
    const int wm = warp >> 1, wn = warp & 1;       // 2 x 2 warp grid, 64x64 tiles
    const int g = lane >> 2, tq = lane & 3;
    const int row0 = blockIdx.y * 128;
    const int col0 = blockIdx.x * 128;
    const int KT = K / 32;

#define LOAD_STAGE(S, KT0)                                                          \
    {                                                                               \
        _Pragma("unroll")                                                           \
        for (int i = 0; i < 4; i++) {                                               \
            int f = tid + i * 128;                                                  \
            int r_ = f >> 2, u_ = f & 3;                                            \
            cp16(&As[S][r_][u_ * 8],                                                \
                 A + (size_t)(row0 + r_) * K + (KT0) * 32 + u_ * 8);                \
            int br_ = f >> 4, nb_ = f & 15;                                         \
            cp16(&Bs[S][br_][nb_ * 8],                                              \
                 Bm + (size_t)((KT0) * 32 + br_) * N + col0 + nb_ * 8);             \
        }                                                                           \
        cp_commit();                                                                \
    }

    float acc[4][8][4];
#pragma unroll
    for (int a = 0; a < 4; a++)
#pragma unroll
        for (int b = 0; b < 8; b++)
#pragma unroll
            for (int c = 0; c < 4; c++) acc[a][b][c] = 0.0f;

    LOAD_STAGE(0, 0);
    LOAD_STAGE(1, 1);

    for (int kt = 0; kt < KT; kt++) {
        const int s = kt % 3;
        if (kt + 1 < KT) { cp_wait<1>(); } else { cp_wait<0>(); }
        __syncthreads();

        if (kt + 2 < KT) { LOAD_STAGE((kt + 2) % 3, kt + 2); }

#pragma unroll
        for (int ks = 0; ks < 2; ks++) {
            const int k0 = ks * 16;
            uint32_t afr[4][4];
#pragma unroll
            for (int mt = 0; mt < 4; mt++)
                ldm_x4(afr[mt], &As[s][wm * 64 + mt * 16 + (lane & 15)]
                                     [k0 + (lane >> 4) * 8]);
            uint32_t bfr[8][2];
#pragma unroll
            for (int nt2 = 0; nt2 < 4; nt2++) {
                uint32_t r4[4];
                ldm_x4_t(r4, &Bs[s][k0 + (lane & 15)]
                                   [wn * 64 + nt2 * 16 + (lane >> 4) * 8]);
                bfr[nt2 * 2][0]     = r4[0]; bfr[nt2 * 2][1]     = r4[1];
                bfr[nt2 * 2 + 1][0] = r4[2]; bfr[nt2 * 2 + 1][1] = r4[3];
            }
#pragma unroll
            for (int mt = 0; mt < 4; mt++)
#pragma unroll
                for (int nt = 0; nt < 8; nt++)
                    mma_f16(acc[mt][nt], afr[mt], bfr[nt]);
        }
        __syncthreads();
    }

    // Epilogue: bias + store fp32
#pragma unroll
    for (int mt = 0; mt < 4; mt++) {
        const int r = row0 + wm * 64 + mt * 16 + g;
#pragma unroll
        for (int nt = 0; nt < 8; nt++) {
            const int c = col0 + wn * 64 + nt * 8 + 2 * tq;
            const float b0 = bias[c], b1 = bias[c + 1];
            float2 v0 = make_float2(acc[mt][nt][0] + b0, acc[mt][nt][1] + b1);
            float2 v1 = make_float2(acc[mt][nt][2] + b0, acc[mt][nt][3] + b1);
            *(float2*)&C[(size_t)r * N + c]       = v0;
            *(float2*)&C[(size_t)(r + 8) * N + c] = v1;
        }
    }
#undef LOAD_STAGE
}

#define GEMM_SMEM ((3 * 128 * 40 + 3 * 32 * 136) * 2)   // 56832

// ---------------------------------------------------------------------------
// RMSNorm + 2D RoPE on q,k (fp32 in), fp16 out for q,k,v.
// ---------------------------------------------------------------------------
__global__ __launch_bounds__(256)
void normrope_kernel(const float* __restrict__ qkv, __half* __restrict__ qkvh,
                     const float* __restrict__ q_gamma,
                     const float* __restrict__ k_gamma)
{
    const int gwarp = (blockIdx.x * blockDim.x + threadIdx.x) >> 5;
    const int lane  = threadIdx.x & 31;

    const int tok = gwarp / 48;
    const int rem = gwarp - tok * 48;
    const int s   = rem >> 4;           // 0=q, 1=k, 2=v
    const int h   = rem & 15;

    const size_t off = (size_t)tok * TOKSTRIDE + s * C_ + h * HD_;
    float2 v = ((const float2*)(qkv + off))[lane];
    half2* outp = (half2*)(qkvh + off);

    if (s == 2) {
        outp[lane] = __floats2half2_rn(v.x, v.y);
        return;
    }

    float ss = v.x * v.x + v.y * v.y;
#pragma unroll
    for (int m = 16; m >= 1; m >>= 1)
        ss += __shfl_xor_sync(0xffffffffu, ss, m);
    const float inv = rsqrtf(ss * (1.0f / 64.0f) + 1e-6f);

    const float* gamma = s ? k_gamma : q_gamma;
    const int d0 = lane * 2;
    float n0 = v.x * inv * gamma[d0];
    float n1 = v.y * inv * gamma[d0 + 1];

    float p0 = __shfl_xor_sync(0xffffffffu, n0, 16);
    float p1 = __shfl_xor_sync(0xffffffffu, n1, 16);
    const bool lo = (d0 < 32);
    float r0 = lo ? -p0 : p0;
    float r1 = lo ? -p1 : p1;

    const int n   = tok & (N_ - 1);
    const int row = n >> 5, col = n & 31;
    const float t = lo ? (float)row : (float)col;
    const int j0 = lo ? d0 : d0 - 32;
    const float LOG2_THETA = 13.28771237954945f;
    float f0 = exp2f(-(float)(j0 & 15)       * (1.0f / 16.0f) * LOG2_THETA);
    float f1 = exp2f(-(float)((j0 + 1) & 15) * (1.0f / 16.0f) * LOG2_THETA);
    float s0, c0, s1, c1;
    sincosf(t * f0, &s0, &c0);
    sincosf(t * f1, &s1, &c1);

    outp[lane] = __floats2half2_rn(n0 * c0 + r0 * s0, n1 * c1 + r1 * s1);
}

// ---------------------------------------------------------------------------
// fp16 HMMA flash attention.
// CTA: 256 queries x 64-kv tiles, hd=64. 8 warps (256 thr), warp = 32 q rows.
// ---------------------------------------------------------------------------
struct FSmem {
    __half Qs[256][72];      // pre-scaled Q
    __half Ks[2][64][72];
    __half Vs[2][64][72];
    __half Ps[256][72];
};

__global__ __launch_bounds__(256, 1)
void flash_f16_kernel(const __half* __restrict__ qkvh, __half* __restrict__ out)
{
    extern __shared__ char sm_raw[];
    FSmem& sm = *reinterpret_cast<FSmem*>(sm_raw);

    const int tid  = threadIdx.x;
    const int warp = tid >> 5, lane = tid & 31;
    const int g = lane >> 2, tq = lane & 3;
    const int qtile = blockIdx.x;        // 0..3
    const int bh = blockIdx.y;           // 0..511
    const int b = bh >> 4, h = bh & 15;
    const int m0 = warp * 32;

    const __half* qbase = qkvh + (size_t)b * N_ * TOKSTRIDE + h * HD_;
    const __half* kbase = qbase + C_;
    const __half* vbase = qbase + 2 * C_;

    // Load Q tile (scale by 1/8, exact in fp16)
    const half2 hscale = __floats2half2_rn(0.125f, 0.125f);
    for (int i = tid; i < 4096; i += 256) {
        int r = i >> 4, d4 = (i & 15) * 4;
        half2 a = *(const half2*)(qbase + (size_t)(qtile * 256 + r) * TOKSTRIDE + d4);
        half2 c = *(const half2*)(qbase + (size_t)(qtile * 256 + r) * TOKSTRIDE + d4 + 2);
        *(half2*)&sm.Qs[r][d4]     = __hmul2(a, hscale);
        *(half2*)&sm.Qs[r][d4 + 2] = __hmul2(c, hscale);
    }

#define LOAD_KV(BUF, KT0)                                                           \
    {                                                                               \
        for (int i = tid; i < 1024; i += 256) {                                     \
            int r_ = i >> 3, u_ = (i & 7) * 8;                                      \
            if (i < 512)                                                            \
                cp16(&sm.Ks[BUF][r_][u_],                                           \
                     kbase + (size_t)((KT0) * 64 + r_) * TOKSTRIDE + u_);           \
            else                                                                    \
                cp16(&sm.Vs[BUF][r_ - 64][u_],                                      \
                     vbase + (size_t)((KT0) * 64 + r_ - 64) * TOKSTRIDE + u_);      \
        }                                                                           \
        cp_commit();                                                                \
    }

    LOAD_KV(0, 0);

    float o[2][8][4];
    float mr[2][2], lr[2][2];
#pragma unroll
    for (int a = 0; a < 2; a++) {
        mr[a][0] = mr[a][1] = -1e30f;
        lr[a][0] = lr[a][1] = 0.0f;
#pragma unroll
        for (int c = 0; c < 8; c++)
#pragma unroll
            for (int d = 0; d < 4; d++) o[a][c][d] = 0.0f;
    }

    const int ki = lane & 7, kq = lane >> 3;     // for K-frag addressing

    for (int kt = 0; kt < 16; kt++) {
        const int buf = kt & 1;
        if (kt + 1 < 16) { LOAD_KV(buf ^ 1, kt + 1); cp_wait<1>(); }
        else             { cp_wait<0>(); }
        __syncthreads();

        // ---- S = Q @ K^T ----
        float s[2][8][4];
#pragma unroll
        for (int a = 0; a < 2; a++)
#pragma unroll
            for (int c = 0; c < 8; c++)
#pragma unroll
                for (int d = 0; d < 4; d++) s[a][c][d] = 0.0f;

#pragma unroll
        for (int ks = 0; ks < 4; ks++) {
            const int k0 = ks * 16;
            uint32_t a[2][4];
            ldm_x4(a[0], &sm.Qs[m0 + (lane & 15)][k0 + (lane >> 4) * 8]);
            ldm_x4(a[1], &sm.Qs[m0 + 16 + (lane & 15)][k0 + (lane >> 4) * 8]);
#pragma unroll
            for (int nt2 = 0; nt2 < 4; nt2++) {
                uint32_t r4[4];
                ldm_x4(r4, &sm.Ks[buf][nt2 * 16 + (kq >> 1) * 8 + ki]
                                      [k0 + (kq & 1) * 8]);
                uint32_t b0[2] = { r4[0], r4[1] };
                uint32_t b1[2] = { r4[2], r4[3] };
                mma_f16(s[0][nt2 * 2],     a[0], b0);
                mma_f16(s[0][nt2 * 2 + 1], a[0], b1);
                mma_f16(s[1][nt2 * 2],     a[1], b0);
                mma_f16(s[1][nt2 * 2 + 1], a[1], b1);
            }
        }

        // ---- online softmax ----
#pragma unroll
        for (int mt = 0; mt < 2; mt++) {
#pragma unroll
            for (int hf = 0; hf < 2; hf++) {
                float mx = -1e30f;
#pragma unroll
                for (int nt = 0; nt < 8; nt++)
                    mx = fmaxf(mx, fmaxf(s[mt][nt][hf * 2], s[mt][nt][hf * 2 + 1]));
                mx = fmaxf(mx, __shfl_xor_sync(0xffffffffu, mx, 1));
                mx = fmaxf(mx, __shfl_xor_sync(0xffffffffu, mx, 2));
                const float mn = fmaxf(mr[mt][hf], mx);
                const float al = __expf(mr[mt][hf] - mn);
                mr[mt][hf] = mn;
                float rs = 0.0f;
#pragma unroll
                for (int nt = 0; nt < 8; nt++) {
                    float e0 = __expf(s[mt][nt][hf * 2]     - mn);
                    float e1 = __expf(s[mt][nt][hf * 2 + 1] - mn);
                    s[mt][nt][hf * 2] = e0; s[mt][nt][hf * 2 + 1] = e1;
                    rs += e0 + e1;
                }
                rs += __shfl_xor_sync(0xffffffffu, rs, 1);
                rs += __shfl_xor_sync(0xffffffffu, rs, 2);
                lr[mt][hf] = lr[mt][hf] * al + rs;
#pragma unroll
                for (int nt = 0; nt < 8; nt++) {
                    o[mt][nt][hf * 2]     *= al;
                    o[mt][nt][hf * 2 + 1] *= al;
                }
            }
        }

        // ---- store P (fp16) ----
#pragma unroll
        for (int mt = 0; mt < 2; mt++)
#pragma unroll
            for (int nt = 0; nt < 8; nt++) {
                const int r = m0 + mt * 16 + g, c = nt * 8 + 2 * tq;
                *(half2*)&sm.Ps[r][c]     = __floats2half2_rn(s[mt][nt][0], s[mt][nt][1]);
                *(half2*)&sm.Ps[r + 8][c] = __floats2half2_rn(s[mt][nt][2], s[mt][nt][3]);
            }
        __syncwarp();

        // ---- O += P @ V ----
#pragma unroll
        for (int ks = 0; ks < 4; ks++) {
            const int k0 = ks * 16;
            uint32_t pa[2][4];
            ldm_x4(pa[0], &sm.Ps[m0 + (lane & 15)][k0 + (lane >> 4) * 8]);
            ldm_x4(pa[1], &sm.Ps[m0 + 16 + (lane & 15)][k0 + (lane >> 4) * 8]);
#pragma unroll
            for (int nt2 = 0; nt2 < 4; nt2++) {
                uint32_t r4[4];
                ldm_x4_t(r4, &sm.Vs[buf][k0 + (lane & 15)]
                                        [nt2 * 16 + (lane >> 4) * 8]);
                uint32_t b0[2] = { r4[0], r4[1] };
                uint32_t b1[2] = { r4[2], r4[3] };
                mma_f16(o[0][nt2 * 2],     pa[0], b0);
                mma_f16(o[0][nt2 * 2 + 1], pa[0], b1);
                mma_f16(o[1][nt2 * 2],     pa[1], b0);
                mma_f16(o[1][nt2 * 2 + 1], pa[1], b1);
            }
        }
        __syncthreads();
    }

    // ---- epilogue: O /= l, store fp16 ----
#pragma unroll
    for (int mt = 0; mt < 2; mt++) {
        const float i0 = 1.0f / lr[mt][0];
        const float i1 = 1.0f / lr[mt][1];
        const int r = qtile * 256 + m0 + mt * 16 + g;
#pragma unroll
        for (int nt = 0; nt < 8; nt++) {
            const int c = h * 64 + nt * 8 + 2 * tq;
            *(half2*)&out[(size_t)(b * N_ + r) * C_ + c] =
                __floats2half2_rn(o[mt][nt][0] * i0, o[mt][nt][1] * i0);
            *(half2*)&out[(size_t)(b * N_ + r + 8) * C_ + c] =
                __floats2half2_rn(o[mt][nt][2] * i1, o[mt][nt][3] * i1);
        }
    }
#undef LOAD_KV
}

// ---------------------------------------------------------------------------
// Launch
// ---------------------------------------------------------------------------
extern "C" void kernel_launch(void* const* d_in, const int* in_sizes, int n_in,
                              void* d_out, int out_size)
{
    const float* x       = (const float*)d_in[0];
    const float* qkv_w   = (const float*)d_in[1];
    const float* qkv_b   = (const float*)d_in[2];
    const float* proj_w  = (const float*)d_in[3];
    const float* proj_b  = (const float*)d_in[4];
    const float* q_gamma = (const float*)d_in[5];
    const float* k_gamma = (const float*)d_in[6];
    float* out = (float*)d_out;

    void *p_xh, *p_wqkvh, *p_wprojh, *p_qkv, *p_qkvh, *p_attnh;
    cudaGetSymbolAddress(&p_xh, g_xh);
    cudaGetSymbolAddress(&p_wqkvh, g_wqkvh);
    cudaGetSymbolAddress(&p_wprojh, g_wprojh);
    cudaGetSymbolAddress(&p_qkv, g_qkv);
    cudaGetSymbolAddress(&p_qkvh, g_qkvh);
    cudaGetSymbolAddress(&p_attnh, g_attnh);
    __half* xh     = (__half*)p_xh;
    __half* wqkvh  = (__half*)p_wqkvh;
    __half* wprojh = (__half*)p_wprojh;
    float*  qkv    = (float*)p_qkv;
    __half* qkvh   = (__half*)p_qkvh;
    __half* attnh  = (__half*)p_attnh;

    const int flash_smem = (int)sizeof(FSmem);
    cudaFuncSetAttribute(gemm_f16_kernel,
                         cudaFuncAttributeMaxDynamicSharedMemorySize, GEMM_SMEM);
    cudaFuncSetAttribute(flash_f16_kernel,
                         cudaFuncAttributeMaxDynamicSharedMemorySize, flash_smem);

    // 0. fp16 conversion prepass
    to_half_kernel<<<(TOKENS * C_) / 1024, 256>>>(x, xh);
    to_half_kernel<<<(C_ * 3 * C_) / 1024, 256>>>(qkv_w, wqkvh);
    to_half_kernel<<<(C_ * C_) / 1024, 256>>>(proj_w, wprojh);

    // 1. QKV GEMM (fp16 HMMA, fp32 out)
    {
        dim3 grid(3 * C_ / 128, TOKENS / 128);
        gemm_f16_kernel<<<grid, 128, GEMM_SMEM>>>(xh, wqkvh, qkv_b, qkv,
                                                  TOKENS, 3 * C_, C_);
    }

    // 2. RMSNorm + RoPE (fp32 in, fp16 out)
    {
        int warps = TOKENS * 48;
        normrope_kernel<<<warps / 8, 256>>>(qkv, qkvh, q_gamma, k_gamma);
    }

    // 3. Flash attention (fp16 HMMA, fp16 out)
    {
        dim3 grid(N_ / 256, B_ * H_);
        flash_f16_kernel<<<grid, 256, flash_smem>>>(qkvh, attnh);
    }

    // 4. Output projection (fp16 HMMA, fp32 out)
    {
        dim3 grid(C_ / 128, TOKENS / 128);
        gemm_f16_kernel<<<grid, 128, GEMM_SMEM>>>(attnh, wprojh, proj_b, out,
                                                  TOKENS, C_, C_);
    }
}

// round 7
// speedup vs baseline: 6.6510x; 1.1010x over previous
#include <cuda_runtime.h>
#include <cuda_fp16.h>
#include <math.h>
#include <stdint.h>

#define B_  32
#define N_  1024
#define C_  1024
#define H_  16
#define HD_ 64
#define TOKENS (B_ * N_)        // 32768
#define TOKSTRIDE 3072

// Scratch (static device globals; no runtime allocation)
__device__ __half g_xh[(size_t)TOKENS * C_];           // fp16 x
__device__ __half g_wqkvh[(size_t)C_ * 3 * C_];        // fp16 qkv_w [1024][3072]
__device__ __half g_wprojh[(size_t)C_ * C_];           // fp16 proj_w [1024][1024]
__device__ __half g_qkvh[(size_t)TOKENS * TOKSTRIDE];  // fp16 q(roped)/k(roped)/v
__device__ __half g_attnh[(size_t)TOKENS * C_];        // fp16 attention output
__device__ float2 g_ropetab[(size_t)N_ * HD_];         // (cos, sin) per (n, c)

// ---------------------------------------------------------------------------
// Helpers
// ---------------------------------------------------------------------------
__device__ __forceinline__ void ldm_x4(uint32_t* r, const void* p) {
    uint32_t a = (uint32_t)__cvta_generic_to_shared(p);
    asm volatile("ldmatrix.sync.aligned.m8n8.x4.shared.b16 {%0,%1,%2,%3}, [%4];"
                 : "=r"(r[0]), "=r"(r[1]), "=r"(r[2]), "=r"(r[3]) : "r"(a));
}
__device__ __forceinline__ void ldm_x4_t(uint32_t* r, const void* p) {
    uint32_t a = (uint32_t)__cvta_generic_to_shared(p);
    asm volatile("ldmatrix.sync.aligned.m8n8.x4.trans.shared.b16 {%0,%1,%2,%3}, [%4];"
                 : "=r"(r[0]), "=r"(r[1]), "=r"(r[2]), "=r"(r[3]) : "r"(a));
}

__device__ __forceinline__ void mma_f16(float* d, const uint32_t* a, const uint32_t* b) {
    asm volatile("mma.sync.aligned.m16n8k16.row.col.f32.f16.f16.f32 "
                 "{%0,%1,%2,%3}, {%4,%5,%6,%7}, {%8,%9}, {%0,%1,%2,%3};"
                 : "+f"(d[0]), "+f"(d[1]), "+f"(d[2]), "+f"(d[3])
                 : "r"(a[0]), "r"(a[1]), "r"(a[2]), "r"(a[3]), "r"(b[0]), "r"(b[1]));
}

__device__ __forceinline__ void cp16(void* dst, const void* src) {
    uint32_t d = (uint32_t)__cvta_generic_to_shared(dst);
    asm volatile("cp.async.cg.shared.global [%0], [%1], 16;" :: "r"(d), "l"(src));
}
__device__ __forceinline__ void cp_commit() { asm volatile("cp.async.commit_group;"); }
template <int NN>
__device__ __forceinline__ void cp_wait() { asm volatile("cp.async.wait_group %0;" :: "n"(NN)); }

// ---------------------------------------------------------------------------
// fp32 -> fp16 conversion prepass
// ---------------------------------------------------------------------------
__global__ __launch_bounds__(256)
void to_half_kernel(const float* __restrict__ in, __half* __restrict__ out) {
    int i = blockIdx.x * 256 + threadIdx.x;
    float4 v = ((const float4*)in)[i];
    ((half2*)out)[i * 2]     = __floats2half2_rn(v.x, v.y);
    ((half2*)out)[i * 2 + 1] = __floats2half2_rn(v.z, v.w);
}

// ---------------------------------------------------------------------------
// RoPE table: tab[n*64+c] = (cos, sin) of angle(n, c)
// ---------------------------------------------------------------------------
__global__ __launch_bounds__(256)
void ropetab_kernel(float2* __restrict__ tab) {
    int i = blockIdx.x * 256 + threadIdx.x;   // 0..65535
    int n = i >> 6, c = i & 63;
    const bool lo = (c < 32);
    const int j0 = c & 31;
    const float LOG2_THETA = 13.28771237954945f;
    float f = exp2f(-(float)(j0 & 15) * (1.0f / 16.0f) * LOG2_THETA);
    float t = lo ? (float)(n >> 5) : (float)(n & 31);
    float s, co;
    sincosf(t * f, &s, &co);
    tab[i] = make_float2(co, s);
}

// ---------------------------------------------------------------------------
// fp16 HMMA GEMM, CTA 128x128, BK=64, 128 threads (4 warps, 2x2 of 64x64).
// 3-stage cp.async pipeline, 2 CTAs/SM.
// MODE 0: C(fp32) = A@B + bias.
// MODE 1: QKV fused epilogue -> fp16 out with RMSNorm+RoPE on q,k sections.
// ---------------------------------------------------------------------------
template <int MODE>
__global__ __launch_bounds__(128, 2)
void gemm_f16_kernel(const __half* __restrict__ A, const __half* __restrict__ Bm,
                     const float* __restrict__ bias, float* __restrict__ Cf,
                     __half* __restrict__ Ch,
                     const float* __restrict__ q_gamma,
                     const float* __restrict__ k_gamma,
                     const float2* __restrict__ ropetab,
                     int M, int N, int K)
{
    extern __shared__ char sraw[];
    __half (*As)[128][72] = (__half(*)[128][72])sraw;                        // 3*18432
    __half (*Bs)[64][136] = (__half(*)[64][136])(sraw + 3 * 128 * 72 * 2);   // 3*17408

    const int tid  = threadIdx.x;
    const int warp = tid >> 5, lane = tid & 31;
    const int wm = warp >> 1, wn = warp & 1;       // 2 x 2 warp grid, 64x64 tiles
    const int g = lane >> 2, tq = lane & 3;
    const int row0 = blockIdx.y * 128;
    const int col0 = blockIdx.x * 128;
    const int KT = K / 64;

#define LOAD_STAGE(S, KT0)                                                          \
    {                                                                               \
        _Pragma("unroll")                                                           \
        for (int i = 0; i < 8; i++) {                                               \
            int f = tid + i * 128;                                                  \
            int r_ = f >> 3, u_ = f & 7;                                            \
            cp16(&As[S][r_][u_ * 8],                                                \
                 A + (size_t)(row0 + r_) * K + (KT0) * 64 + u_ * 8);                \
            int br_ = f >> 4, nb_ = f & 15;                                         \
            cp16(&Bs[S][br_][nb_ * 8],                                              \
                 Bm + (size_t)((KT0) * 64 + br_) * N + col0 + nb_ * 8);             \
        }                                                                           \
        cp_commit();                                                                \
    }

    float acc[4][8][4];
#pragma unroll
    for (int a = 0; a < 4; a++)
#pragma unroll
        for (int b = 0; b < 8; b++)
#pragma unroll
            for (int c = 0; c < 4; c++) acc[a][b][c] = 0.0f;

    LOAD_STAGE(0, 0);
    LOAD_STAGE(1, 1);

    for (int kt = 0; kt < KT; kt++) {
        const int s = kt % 3;
        if (kt + 1 < KT) { cp_wait<1>(); } else { cp_wait<0>(); }
        __syncthreads();

        if (kt + 2 < KT) { LOAD_STAGE((kt + 2) % 3, kt + 2); }

#pragma unroll
        for (int ks = 0; ks < 4; ks++) {
            const int k0 = ks * 16;
            uint32_t afr[4][4];
#pragma unroll
            for (int mt = 0; mt < 4; mt++)
                ldm_x4(afr[mt], &As[s][wm * 64 + mt * 16 + (lane & 15)]
                                     [k0 + (lane >> 4) * 8]);
            uint32_t bfr[8][2];
#pragma unroll
            for (int nt2 = 0; nt2 < 4; nt2++) {
                uint32_t r4[4];
                ldm_x4_t(r4, &Bs[s][k0 + (lane & 15)]
                                   [wn * 64 + nt2 * 16 + (lane >> 4) * 8]);
                bfr[nt2 * 2][0]     = r4[0]; bfr[nt2 * 2][1]     = r4[1];
                bfr[nt2 * 2 + 1][0] = r4[2]; bfr[nt2 * 2 + 1][1] = r4[3];
            }
#pragma unroll
            for (int mt = 0; mt < 4; mt++)
#pragma unroll
                for (int nt = 0; nt < 8; nt++)
                    mma_f16(acc[mt][nt], afr[mt], bfr[nt]);
        }
        __syncthreads();
    }

    if (MODE == 0) {
        // Plain epilogue: bias + fp32 store
#pragma unroll
        for (int mt = 0; mt < 4; mt++) {
            const int r = row0 + wm * 64 + mt * 16 + g;
#pragma unroll
            for (int nt = 0; nt < 8; nt++) {
                const int c = col0 + wn * 64 + nt * 8 + 2 * tq;
                const float b0 = bias[c], b1 = bias[c + 1];
                float2 v0 = make_float2(acc[mt][nt][0] + b0, acc[mt][nt][1] + b1);
                float2 v1 = make_float2(acc[mt][nt][2] + b0, acc[mt][nt][3] + b1);
                *(float2*)&Cf[(size_t)r * N + c]       = v0;
                *(float2*)&Cf[(size_t)(r + 8) * N + c] = v1;
            }
        }
    } else {
        // Fused QKV epilogue: this warp's 64 cols = exactly one head.
        const int gc  = col0 + wn * 64;      // global col base (multiple of 64)
        const int sec = gc >> 10;            // 0=q, 1=k, 2=v
        // Preload bias and gamma for this thread's 16 columns
        float br[8][2], gr[8][2];
        const float* gam = (sec == 1) ? k_gamma : q_gamma;
#pragma unroll
        for (int nt = 0; nt < 8; nt++) {
            const int cc = nt * 8 + 2 * tq;
            br[nt][0] = bias[gc + cc];
            br[nt][1] = bias[gc + cc + 1];
            if (sec < 2) {
                gr[nt][0] = gam[cc];
                gr[nt][1] = gam[cc + 1];
            }
        }

#pragma unroll
        for (int mt = 0; mt < 4; mt++) {
#pragma unroll
            for (int rh = 0; rh < 2; rh++) {
                const int tok = row0 + wm * 64 + mt * 16 + g + rh * 8;
                __half* outp = Ch + (size_t)tok * TOKSTRIDE + gc;
                float vv[8][2];
#pragma unroll
                for (int nt = 0; nt < 8; nt++) {
                    vv[nt][0] = acc[mt][nt][rh * 2]     + br[nt][0];
                    vv[nt][1] = acc[mt][nt][rh * 2 + 1] + br[nt][1];
                }
                if (sec == 2) {
#pragma unroll
                    for (int nt = 0; nt < 8; nt++)
                        *(half2*)&outp[nt * 8 + 2 * tq] =
                            __floats2half2_rn(vv[nt][0], vv[nt][1]);
                    continue;
                }
                // RMS over head (64 cols): 16 local + reduce over tq quad
                float ss = 0.0f;
#pragma unroll
                for (int nt = 0; nt < 8; nt++)
                    ss += vv[nt][0] * vv[nt][0] + vv[nt][1] * vv[nt][1];
                ss += __shfl_xor_sync(0xffffffffu, ss, 1);
                ss += __shfl_xor_sync(0xffffffffu, ss, 2);
                const float inv = rsqrtf(ss * (1.0f / 64.0f) + 1e-6f);
#pragma unroll
                for (int nt = 0; nt < 8; nt++) {
                    vv[nt][0] *= inv * gr[nt][0];
                    vv[nt][1] *= inv * gr[nt][1];
                }
                // RoPE: partner col = c +/- 32 = nt +/- 4 (thread-local)
                const int n = tok & (N_ - 1);
                const float2* tabn = ropetab + (size_t)n * HD_;
#pragma unroll
                for (int nt = 0; nt < 4; nt++) {
                    const int cc = nt * 8 + 2 * tq;
                    float2 t0 = tabn[cc], t1 = tabn[cc + 1];
                    float2 u0 = tabn[cc + 32], u1 = tabn[cc + 33];
                    float lo0 = vv[nt][0] * t0.x - vv[nt + 4][0] * t0.y;
                    float lo1 = vv[nt][1] * t1.x - vv[nt + 4][1] * t1.y;
                    float hi0 = vv[nt + 4][0] * u0.x + vv[nt][0] * u0.y;
                    float hi1 = vv[nt + 4][1] * u1.x + vv[nt][1] * u1.y;
                    *(half2*)&outp[cc]      = __floats2half2_rn(lo0, lo1);
                    *(half2*)&outp[cc + 32] = __floats2half2_rn(hi0, hi1);
                }
            }
        }
    }
#undef LOAD_STAGE
}

#define GEMM_SMEM ((3 * 128 * 72 + 3 * 64 * 136) * 2)   // 107520

// ---------------------------------------------------------------------------
// fp16 HMMA flash attention, fixed-max softmax (|s| <= 8 by construction).
// CTA: 256 queries x 64-kv tiles, hd=64. 8 warps, warp = 32 q rows.
// ---------------------------------------------------------------------------
struct FSmem {
    __half Qs[256][72];      // pre-scaled Q
    __half Ks[2][64][72];
    __half Vs[2][64][72];
    __half Ps[256][72];
};

__global__ __launch_bounds__(256, 1)
void flash_f16_kernel(const __half* __restrict__ qkvh, __half* __restrict__ out)
{
    extern __shared__ char sm_raw[];
    FSmem& sm = *reinterpret_cast<FSmem*>(sm_raw);

    const int tid  = threadIdx.x;
    const int warp = tid >> 5, lane = tid & 31;
    const int g = lane >> 2, tq = lane & 3;
    const int qtile = blockIdx.x;        // 0..3
    const int bh = blockIdx.y;           // 0..511
    const int b = bh >> 4, h = bh & 15;
    const int m0 = warp * 32;

    const __half* qbase = qkvh + (size_t)b * N_ * TOKSTRIDE + h * HD_;
    const __half* kbase = qbase + C_;
    const __half* vbase = qbase + 2 * C_;

    const half2 hscale = __floats2half2_rn(0.125f, 0.125f);
    for (int i = tid; i < 4096; i += 256) {
        int r = i >> 4, d4 = (i & 15) * 4;
        half2 a = *(const half2*)(qbase + (size_t)(qtile * 256 + r) * TOKSTRIDE + d4);
        half2 c = *(const half2*)(qbase + (size_t)(qtile * 256 + r) * TOKSTRIDE + d4 + 2);
        *(half2*)&sm.Qs[r][d4]     = __hmul2(a, hscale);
        *(half2*)&sm.Qs[r][d4 + 2] = __hmul2(c, hscale);
    }

#define LOAD_KV(BUF, KT0)                                                           \
    {                                                                               \
        for (int i = tid; i < 1024; i += 256) {                                     \
            int r_ = i >> 3, u_ = (i & 7) * 8;                                      \
            if (i < 512)                                                            \
                cp16(&sm.Ks[BUF][r_][u_],                                           \
                     kbase + (size_t)((KT0) * 64 + r_) * TOKSTRIDE + u_);           \
            else                                                                    \
                cp16(&sm.Vs[BUF][r_ - 64][u_],                                      \
                     vbase + (size_t)((KT0) * 64 + r_ - 64) * TOKSTRIDE + u_);      \
        }                                                                           \
        cp_commit();                                                                \
    }

    LOAD_KV(0, 0);

    float o[2][8][4];
    float lr[2][2];
#pragma unroll
    for (int a = 0; a < 2; a++) {
        lr[a][0] = lr[a][1] = 0.0f;
#pragma unroll
        for (int c = 0; c < 8; c++)
#pragma unroll
            for (int d = 0; d < 4; d++) o[a][c][d] = 0.0f;
    }

    const int ki = lane & 7, kq = lane >> 3;

    for (int kt = 0; kt < 16; kt++) {
        const int buf = kt & 1;
        if (kt + 1 < 16) { LOAD_KV(buf ^ 1, kt + 1); cp_wait<1>(); }
        else             { cp_wait<0>(); }
        __syncthreads();

        // ---- S = Q @ K^T ----
        float s[2][8][4];
#pragma unroll
        for (int a = 0; a < 2; a++)
#pragma unroll
            for (int c = 0; c < 8; c++)
#pragma unroll
                for (int d = 0; d < 4; d++) s[a][c][d] = 0.0f;

#pragma unroll
        for (int ks = 0; ks < 4; ks++) {
            const int k0 = ks * 16;
            uint32_t a[2][4];
            ldm_x4(a[0], &sm.Qs[m0 + (lane & 15)][k0 + (lane >> 4) * 8]);
            ldm_x4(a[1], &sm.Qs[m0 + 16 + (lane & 15)][k0 + (lane >> 4) * 8]);
#pragma unroll
            for (int nt2 = 0; nt2 < 4; nt2++) {
                uint32_t r4[4];
                ldm_x4(r4, &sm.Ks[buf][nt2 * 16 + (kq >> 1) * 8 + ki]
                                      [k0 + (kq & 1) * 8]);
                uint32_t b0[2] = { r4[0], r4[1] };
                uint32_t b1[2] = { r4[2], r4[3] };
                mma_f16(s[0][nt2 * 2],     a[0], b0);
                mma_f16(s[0][nt2 * 2 + 1], a[0], b1);
                mma_f16(s[1][nt2 * 2],     a[1], b0);
                mma_f16(s[1][nt2 * 2 + 1], a[1], b1);
            }
        }

        // ---- fixed-max softmax: P = exp(s - 8), l += sum ----
#pragma unroll
        for (int mt = 0; mt < 2; mt++) {
#pragma unroll
            for (int hf = 0; hf < 2; hf++) {
                float rs = 0.0f;
#pragma unroll
                for (int nt = 0; nt < 8; nt++) {
                    float e0 = __expf(s[mt][nt][hf * 2]     - 8.0f);
                    float e1 = __expf(s[mt][nt][hf * 2 + 1] - 8.0f);
                    s[mt][nt][hf * 2] = e0; s[mt][nt][hf * 2 + 1] = e1;
                    rs += e0 + e1;
                }
                rs += __shfl_xor_sync(0xffffffffu, rs, 1);
                rs += __shfl_xor_sync(0xffffffffu, rs, 2);
                lr[mt][hf] += rs;
            }
        }

        // ---- store P (fp16) ----
#pragma unroll
        for (int mt = 0; mt < 2; mt++)
#pragma unroll
            for (int nt = 0; nt < 8; nt++) {
                const int r = m0 + mt * 16 + g, c = nt * 8 + 2 * tq;
                *(half2*)&sm.Ps[r][c]     = __floats2half2_rn(s[mt][nt][0], s[mt][nt][1]);
                *(half2*)&sm.Ps[r + 8][c] = __floats2half2_rn(s[mt][nt][2], s[mt][nt][3]);
            }
        __syncwarp();

        // ---- O += P @ V ----
#pragma unroll
        for (int ks = 0; ks < 4; ks++) {
            const int k0 = ks * 16;
            uint32_t pa[2][4];
            ldm_x4(pa[0], &sm.Ps[m0 + (lane & 15)][k0 + (lane >> 4) * 8]);
            ldm_x4(pa[1], &sm.Ps[m0 + 16 + (lane & 15)][k0 + (lane >> 4) * 8]);
#pragma unroll
            for (int nt2 = 0; nt2 < 4; nt2++) {
                uint32_t r4[4];
                ldm_x4_t(r4, &sm.Vs[buf][k0 + (lane & 15)]
                                        [nt2 * 16 + (lane >> 4) * 8]);
                uint32_t b0[2] = { r4[0], r4[1] };
                uint32_t b1[2] = { r4[2], r4[3] };
                mma_f16(o[0][nt2 * 2],     pa[0], b0);
                mma_f16(o[0][nt2 * 2 + 1], pa[0], b1);
                mma_f16(o[1][nt2 * 2],     pa[1], b0);
                mma_f16(o[1][nt2 * 2 + 1], pa[1], b1);
            }
        }
        __syncthreads();
    }

    // ---- epilogue: O /= l, store fp16 ----
#pragma unroll
    for (int mt = 0; mt < 2; mt++) {
        const float i0 = 1.0f / lr[mt][0];
        const float i1 = 1.0f / lr[mt][1];
        const int r = qtile * 256 + m0 + mt * 16 + g;
#pragma unroll
        for (int nt = 0; nt < 8; nt++) {
            const int c = h * 64 + nt * 8 + 2 * tq;
            *(half2*)&out[(size_t)(b * N_ + r) * C_ + c] =
                __floats2half2_rn(o[mt][nt][0] * i0, o[mt][nt][1] * i0);
            *(half2*)&out[(size_t)(b * N_ + r + 8) * C_ + c] =
                __floats2half2_rn(o[mt][nt][2] * i1, o[mt][nt][3] * i1);
        }
    }
#undef LOAD_KV
}

// ---------------------------------------------------------------------------
// Launch
// ---------------------------------------------------------------------------
extern "C" void kernel_launch(void* const* d_in, const int* in_sizes, int n_in,
                              void* d_out, int out_size)
{
    const float* x       = (const float*)d_in[0];
    const float* qkv_w   = (const float*)d_in[1];
    const float* qkv_b   = (const float*)d_in[2];
    const float* proj_w  = (const float*)d_in[3];
    const float* proj_b  = (const float*)d_in[4];
    const float* q_gamma = (const float*)d_in[5];
    const float* k_gamma = (const float*)d_in[6];
    float* out = (float*)d_out;

    void *p_xh, *p_wqkvh, *p_wprojh, *p_qkvh, *p_attnh, *p_tab;
    cudaGetSymbolAddress(&p_xh, g_xh);
    cudaGetSymbolAddress(&p_wqkvh, g_wqkvh);
    cudaGetSymbolAddress(&p_wprojh, g_wprojh);
    cudaGetSymbolAddress(&p_qkvh, g_qkvh);
    cudaGetSymbolAddress(&p_attnh, g_attnh);
    cudaGetSymbolAddress(&p_tab, g_ropetab);
    __half* xh     = (__half*)p_xh;
    __half* wqkvh  = (__half*)p_wqkvh;
    __half* wprojh = (__half*)p_wprojh;
    __half* qkvh   = (__half*)p_qkvh;
    __half* attnh  = (__half*)p_attnh;
    float2* tab    = (float2*)p_tab;

    const int flash_smem = (int)sizeof(FSmem);
    cudaFuncSetAttribute(gemm_f16_kernel<0>,
                         cudaFuncAttributeMaxDynamicSharedMemorySize, GEMM_SMEM);
    cudaFuncSetAttribute(gemm_f16_kernel<1>,
                         cudaFuncAttributeMaxDynamicSharedMemorySize, GEMM_SMEM);
    cudaFuncSetAttribute(flash_f16_kernel,
                         cudaFuncAttributeMaxDynamicSharedMemorySize, flash_smem);

    // 0. prepass: fp16 conversion + rope table
    to_half_kernel<<<(TOKENS * C_) / 1024, 256>>>(x, xh);
    to_half_kernel<<<(C_ * 3 * C_) / 1024, 256>>>(qkv_w, wqkvh);
    to_half_kernel<<<(C_ * C_) / 1024, 256>>>(proj_w, wprojh);
    ropetab_kernel<<<(N_ * HD_) / 256, 256>>>(tab);

    // 1. QKV GEMM + fused RMSNorm/RoPE epilogue (fp16 out)
    {
        dim3 grid(3 * C_ / 128, TOKENS / 128);
        gemm_f16_kernel<1><<<grid, 128, GEMM_SMEM>>>(
            xh, wqkvh, qkv_b, nullptr, qkvh, q_gamma, k_gamma, tab,
            TOKENS, 3 * C_, C_);
    }

    // 2. Flash attention (fixed-max softmax)
    {
        dim3 grid(N_ / 256, B_ * H_);
        flash_f16_kernel<<<grid, 256, flash_smem>>>(qkvh, attnh);
    }

    // 3. Output projection (fp32 out)
    {
        dim3 grid(C_ / 128, TOKENS / 128);
        gemm_f16_kernel<0><<<grid, 128, GEMM_SMEM>>>(
            attnh, wprojh, proj_b, out, nullptr, nullptr, nullptr, nullptr,
            TOKENS, C_, C_);
    }
}

// round 8
// speedup vs baseline: 7.1576x; 1.0762x over previous
#include <cuda_runtime.h>
#include <cuda_fp16.h>
#include <math.h>
#include <stdint.h>

#define B_  32
#define N_  1024
#define C_  1024
#define H_  16
#define HD_ 64
#define TOKENS (B_ * N_)        // 32768
#define TOKSTRIDE 3072

// Scratch (static device globals; no runtime allocation)
__device__ __half g_xh[(size_t)TOKENS * C_];           // fp16 x
__device__ __half g_wqkvh[(size_t)C_ * 3 * C_];        // fp16 qkv_w [1024][3072]
__device__ __half g_wprojh[(size_t)C_ * C_];           // fp16 proj_w [1024][1024]
__device__ __half g_qkvh[(size_t)TOKENS * TOKSTRIDE];  // fp16 q(roped)/k(roped)/v
__device__ __half g_attnh[(size_t)TOKENS * C_];        // fp16 attention output
__device__ float2 g_ropetab[(size_t)N_ * HD_];         // (cos, sin) per (n, c)

// ---------------------------------------------------------------------------
// Helpers
// ---------------------------------------------------------------------------
__device__ __forceinline__ void ldm_x4(uint32_t* r, const void* p) {
    uint32_t a = (uint32_t)__cvta_generic_to_shared(p);
    asm volatile("ldmatrix.sync.aligned.m8n8.x4.shared.b16 {%0,%1,%2,%3}, [%4];"
                 : "=r"(r[0]), "=r"(r[1]), "=r"(r[2]), "=r"(r[3]) : "r"(a));
}
__device__ __forceinline__ void ldm_x4_t(uint32_t* r, const void* p) {
    uint32_t a = (uint32_t)__cvta_generic_to_shared(p);
    asm volatile("ldmatrix.sync.aligned.m8n8.x4.trans.shared.b16 {%0,%1,%2,%3}, [%4];"
                 : "=r"(r[0]), "=r"(r[1]), "=r"(r[2]), "=r"(r[3]) : "r"(a));
}

__device__ __forceinline__ void mma_f16(float* d, const uint32_t* a, const uint32_t* b) {
    asm volatile("mma.sync.aligned.m16n8k16.row.col.f32.f16.f16.f32 "
                 "{%0,%1,%2,%3}, {%4,%5,%6,%7}, {%8,%9}, {%0,%1,%2,%3};"
                 : "+f"(d[0]), "+f"(d[1]), "+f"(d[2]), "+f"(d[3])
                 : "r"(a[0]), "r"(a[1]), "r"(a[2]), "r"(a[3]), "r"(b[0]), "r"(b[1]));
}

__device__ __forceinline__ void cp16(void* dst, const void* src) {
    uint32_t d = (uint32_t)__cvta_generic_to_shared(dst);
    asm volatile("cp.async.cg.shared.global [%0], [%1], 16;" :: "r"(d), "l"(src));
}
__device__ __forceinline__ void cp_commit() { asm volatile("cp.async.commit_group;"); }
template <int NN>
__device__ __forceinline__ void cp_wait() { asm volatile("cp.async.wait_group %0;" :: "n"(NN)); }

__device__ __forceinline__ uint32_t packh2(float a, float b) {
    half2 h = __floats2half2_rn(a, b);
    return *(uint32_t*)&h;
}

// ---------------------------------------------------------------------------
// fp32 -> fp16 conversion prepass
// ---------------------------------------------------------------------------
__global__ __launch_bounds__(256)
void to_half_kernel(const float* __restrict__ in, __half* __restrict__ out) {
    int i = blockIdx.x * 256 + threadIdx.x;
    float4 v = ((const float4*)in)[i];
    ((half2*)out)[i * 2]     = __floats2half2_rn(v.x, v.y);
    ((half2*)out)[i * 2 + 1] = __floats2half2_rn(v.z, v.w);
}

// ---------------------------------------------------------------------------
// RoPE table: tab[n*64+c] = (cos, sin) of angle(n, c)
// ---------------------------------------------------------------------------
__global__ __launch_bounds__(256)
void ropetab_kernel(float2* __restrict__ tab) {
    int i = blockIdx.x * 256 + threadIdx.x;   // 0..65535
    int n = i >> 6, c = i & 63;
    const bool lo = (c < 32);
    const int j0 = c & 31;
    const float LOG2_THETA = 13.28771237954945f;
    float f = exp2f(-(float)(j0 & 15) * (1.0f / 16.0f) * LOG2_THETA);
    float t = lo ? (float)(n >> 5) : (float)(n & 31);
    float s, co;
    sincosf(t * f, &s, &co);
    tab[i] = make_float2(co, s);
}

// ---------------------------------------------------------------------------
// fp16 HMMA GEMM, CTA 128x128, BK=64, 128 threads (4 warps, 2x2 of 64x64).
// 3-stage cp.async pipeline, 2 CTAs/SM.
// MODE 0: C(fp32) = A@B + bias.
// MODE 1: QKV fused epilogue -> fp16 out with RMSNorm+RoPE on q,k sections.
// ---------------------------------------------------------------------------
template <int MODE>
__global__ __launch_bounds__(128, 2)
void gemm_f16_kernel(const __half* __restrict__ A, const __half* __restrict__ Bm,
                     const float* __restrict__ bias, float* __restrict__ Cf,
                     __half* __restrict__ Ch,
                     const float* __restrict__ q_gamma,
                     const float* __restrict__ k_gamma,
                     const float2* __restrict__ ropetab,
                     int M, int N, int K)
{
    extern __shared__ char sraw[];
    __half (*As)[128][72] = (__half(*)[128][72])sraw;
    __half (*Bs)[64][136] = (__half(*)[64][136])(sraw + 3 * 128 * 72 * 2);

    const int tid  = threadIdx.x;
    const int warp = tid >> 5, lane = tid & 31;
    const int wm = warp >> 1, wn = warp & 1;
    const int g = lane >> 2, tq = lane & 3;
    const int row0 = blockIdx.y * 128;
    const int col0 = blockIdx.x * 128;
    const int KT = K / 64;

#define LOAD_STAGE(S, KT0)                                                          \
    {                                                                               \
        _Pragma("unroll")                                                           \
        for (int i = 0; i < 8; i++) {                                               \
            int f = tid + i * 128;                                                  \
            int r_ = f >> 3, u_ = f & 7;                                            \
            cp16(&As[S][r_][u_ * 8],                                                \
                 A + (size_t)(row0 + r_) * K + (KT0) * 64 + u_ * 8);                \
            int br_ = f >> 4, nb_ = f & 15;                                         \
            cp16(&Bs[S][br_][nb_ * 8],                                              \
                 Bm + (size_t)((KT0) * 64 + br_) * N + col0 + nb_ * 8);             \
        }                                                                           \
        cp_commit();                                                                \
    }

    float acc[4][8][4];
#pragma unroll
    for (int a = 0; a < 4; a++)
#pragma unroll
        for (int b = 0; b < 8; b++)
#pragma unroll
            for (int c = 0; c < 4; c++) acc[a][b][c] = 0.0f;

    LOAD_STAGE(0, 0);
    LOAD_STAGE(1, 1);

    for (int kt = 0; kt < KT; kt++) {
        const int s = kt % 3;
        if (kt + 1 < KT) { cp_wait<1>(); } else { cp_wait<0>(); }
        __syncthreads();

        if (kt + 2 < KT) { LOAD_STAGE((kt + 2) % 3, kt + 2); }

#pragma unroll
        for (int ks = 0; ks < 4; ks++) {
            const int k0 = ks * 16;
            uint32_t afr[4][4];
#pragma unroll
            for (int mt = 0; mt < 4; mt++)
                ldm_x4(afr[mt], &As[s][wm * 64 + mt * 16 + (lane & 15)]
                                     [k0 + (lane >> 4) * 8]);
            uint32_t bfr[8][2];
#pragma unroll
            for (int nt2 = 0; nt2 < 4; nt2++) {
                uint32_t r4[4];
                ldm_x4_t(r4, &Bs[s][k0 + (lane & 15)]
                                   [wn * 64 + nt2 * 16 + (lane >> 4) * 8]);
                bfr[nt2 * 2][0]     = r4[0]; bfr[nt2 * 2][1]     = r4[1];
                bfr[nt2 * 2 + 1][0] = r4[2]; bfr[nt2 * 2 + 1][1] = r4[3];
            }
#pragma unroll
            for (int mt = 0; mt < 4; mt++)
#pragma unroll
                for (int nt = 0; nt < 8; nt++)
                    mma_f16(acc[mt][nt], afr[mt], bfr[nt]);
        }
        __syncthreads();
    }

    if (MODE == 0) {
#pragma unroll
        for (int mt = 0; mt < 4; mt++) {
            const int r = row0 + wm * 64 + mt * 16 + g;
#pragma unroll
            for (int nt = 0; nt < 8; nt++) {
                const int c = col0 + wn * 64 + nt * 8 + 2 * tq;
                const float b0 = bias[c], b1 = bias[c + 1];
                float2 v0 = make_float2(acc[mt][nt][0] + b0, acc[mt][nt][1] + b1);
                float2 v1 = make_float2(acc[mt][nt][2] + b0, acc[mt][nt][3] + b1);
                *(float2*)&Cf[(size_t)r * N + c]       = v0;
                *(float2*)&Cf[(size_t)(r + 8) * N + c] = v1;
            }
        }
    } else {
        const int gc  = col0 + wn * 64;
        const int sec = gc >> 10;            // 0=q, 1=k, 2=v
        float br[8][2], gr[8][2];
        const float* gam = (sec == 1) ? k_gamma : q_gamma;
#pragma unroll
        for (int nt = 0; nt < 8; nt++) {
            const int cc = nt * 8 + 2 * tq;
            br[nt][0] = bias[gc + cc];
            br[nt][1] = bias[gc + cc + 1];
            if (sec < 2) {
                gr[nt][0] = gam[cc];
                gr[nt][1] = gam[cc + 1];
            }
        }

#pragma unroll
        for (int mt = 0; mt < 4; mt++) {
#pragma unroll
            for (int rh = 0; rh < 2; rh++) {
                const int tok = row0 + wm * 64 + mt * 16 + g + rh * 8;
                __half* outp = Ch + (size_t)tok * TOKSTRIDE + gc;
                float vv[8][2];
#pragma unroll
                for (int nt = 0; nt < 8; nt++) {
                    vv[nt][0] = acc[mt][nt][rh * 2]     + br[nt][0];
                    vv[nt][1] = acc[mt][nt][rh * 2 + 1] + br[nt][1];
                }
                if (sec == 2) {
#pragma unroll
                    for (int nt = 0; nt < 8; nt++)
                        *(half2*)&outp[nt * 8 + 2 * tq] =
                            __floats2half2_rn(vv[nt][0], vv[nt][1]);
                    continue;
                }
                float ss = 0.0f;
#pragma unroll
                for (int nt = 0; nt < 8; nt++)
                    ss += vv[nt][0] * vv[nt][0] + vv[nt][1] * vv[nt][1];
                ss += __shfl_xor_sync(0xffffffffu, ss, 1);
                ss += __shfl_xor_sync(0xffffffffu, ss, 2);
                const float inv = rsqrtf(ss * (1.0f / 64.0f) + 1e-6f);
#pragma unroll
                for (int nt = 0; nt < 8; nt++) {
                    vv[nt][0] *= inv * gr[nt][0];
                    vv[nt][1] *= inv * gr[nt][1];
                }
                const int n = tok & (N_ - 1);
                const float2* tabn = ropetab + (size_t)n * HD_;
#pragma unroll
                for (int nt = 0; nt < 4; nt++) {
                    const int cc = nt * 8 + 2 * tq;
                    float2 t0 = tabn[cc], t1 = tabn[cc + 1];
                    float2 u0 = tabn[cc + 32], u1 = tabn[cc + 33];
                    float lo0 = vv[nt][0] * t0.x - vv[nt + 4][0] * t0.y;
                    float lo1 = vv[nt][1] * t1.x - vv[nt + 4][1] * t1.y;
                    float hi0 = vv[nt + 4][0] * u0.x + vv[nt][0] * u0.y;
                    float hi1 = vv[nt + 4][1] * u1.x + vv[nt][1] * u1.y;
                    *(half2*)&outp[cc]      = __floats2half2_rn(lo0, lo1);
                    *(half2*)&outp[cc + 32] = __floats2half2_rn(hi0, hi1);
                }
            }
        }
    }
#undef LOAD_STAGE
}

#define GEMM_SMEM ((3 * 128 * 72 + 3 * 64 * 136) * 2)   // 107520

// ---------------------------------------------------------------------------
// fp16 HMMA flash attention, fixed-max softmax, register-resident P (FA-2).
// CTA: 256 queries x 64-kv tiles, hd=64. 16 warps (512 thr), warp = 16 q rows.
// ---------------------------------------------------------------------------
struct FSmem {
    __half Qs[256][72];      // pre-scaled Q
    __half Ks[2][64][72];
    __half Vs[2][64][72];
};

__global__ __launch_bounds__(512, 1)
void flash_f16_kernel(const __half* __restrict__ qkvh, __half* __restrict__ out)
{
    extern __shared__ char sm_raw[];
    FSmem& sm = *reinterpret_cast<FSmem*>(sm_raw);

    const int tid  = threadIdx.x;
    const int warp = tid >> 5, lane = tid & 31;
    const int g = lane >> 2, tq = lane & 3;
    const int qtile = blockIdx.x;        // 0..3
    const int bh = blockIdx.y;           // 0..511
    const int b = bh >> 4, h = bh & 15;
    const int m0 = warp * 16;

    const __half* qbase = qkvh + (size_t)b * N_ * TOKSTRIDE + h * HD_;
    const __half* kbase = qbase + C_;
    const __half* vbase = qbase + 2 * C_;

    const half2 hscale = __floats2half2_rn(0.125f, 0.125f);
    for (int i = tid; i < 4096; i += 512) {
        int r = i >> 4, d4 = (i & 15) * 4;
        half2 a = *(const half2*)(qbase + (size_t)(qtile * 256 + r) * TOKSTRIDE + d4);
        half2 c = *(const half2*)(qbase + (size_t)(qtile * 256 + r) * TOKSTRIDE + d4 + 2);
        *(half2*)&sm.Qs[r][d4]     = __hmul2(a, hscale);
        *(half2*)&sm.Qs[r][d4 + 2] = __hmul2(c, hscale);
    }

#define LOAD_KV(BUF, KT0)                                                           \
    {                                                                               \
        for (int i = tid; i < 1024; i += 512) {                                     \
            int r_ = i >> 3, u_ = (i & 7) * 8;                                      \
            if (i < 512)                                                            \
                cp16(&sm.Ks[BUF][r_][u_],                                           \
                     kbase + (size_t)((KT0) * 64 + r_) * TOKSTRIDE + u_);           \
            else                                                                    \
                cp16(&sm.Vs[BUF][r_ - 64][u_],                                      \
                     vbase + (size_t)((KT0) * 64 + r_ - 64) * TOKSTRIDE + u_);      \
        }                                                                           \
        cp_commit();                                                                \
    }

    LOAD_KV(0, 0);

    float o[8][4];
    float lr[2];
    lr[0] = lr[1] = 0.0f;
#pragma unroll
    for (int c = 0; c < 8; c++)
#pragma unroll
        for (int d = 0; d < 4; d++) o[c][d] = 0.0f;

    const int ki = lane & 7, kq = lane >> 3;

    for (int kt = 0; kt < 16; kt++) {
        const int buf = kt & 1;
        if (kt + 1 < 16) { LOAD_KV(buf ^ 1, kt + 1); cp_wait<1>(); }
        else             { cp_wait<0>(); }
        __syncthreads();

        // ---- S = Q @ K^T ----
        float s[8][4];
#pragma unroll
        for (int c = 0; c < 8; c++)
#pragma unroll
            for (int d = 0; d < 4; d++) s[c][d] = 0.0f;

#pragma unroll
        for (int ks = 0; ks < 4; ks++) {
            const int k0 = ks * 16;
            uint32_t a[4];
            ldm_x4(a, &sm.Qs[m0 + (lane & 15)][k0 + (lane >> 4) * 8]);
#pragma unroll
            for (int nt2 = 0; nt2 < 4; nt2++) {
                uint32_t r4[4];
                ldm_x4(r4, &sm.Ks[buf][nt2 * 16 + (kq >> 1) * 8 + ki]
                                      [k0 + (kq & 1) * 8]);
                uint32_t b0[2] = { r4[0], r4[1] };
                uint32_t b1[2] = { r4[2], r4[3] };
                mma_f16(s[nt2 * 2],     a, b0);
                mma_f16(s[nt2 * 2 + 1], a, b1);
            }
        }

        // ---- fixed-max softmax: P = exp(s - 8), l += sum ----
#pragma unroll
        for (int hf = 0; hf < 2; hf++) {
            float rs = 0.0f;
#pragma unroll
            for (int nt = 0; nt < 8; nt++) {
                float e0 = __expf(s[nt][hf * 2]     - 8.0f);
                float e1 = __expf(s[nt][hf * 2 + 1] - 8.0f);
                s[nt][hf * 2] = e0; s[nt][hf * 2 + 1] = e1;
                rs += e0 + e1;
            }
            rs += __shfl_xor_sync(0xffffffffu, rs, 1);
            rs += __shfl_xor_sync(0xffffffffu, rs, 2);
            lr[hf] += rs;
        }

        // ---- pack P into A-fragments (register-resident, no smem) ----
        // S C-frag (rows g,g+8; cols 2tq,2tq+1 of n-tile nt) == PV A-frag:
        // k-chunk ks <- n-tiles 2ks (k=2tq) and 2ks+1 (k=8+2tq).
        uint32_t pa[4][4];
#pragma unroll
        for (int ks = 0; ks < 4; ks++) {
            pa[ks][0] = packh2(s[2 * ks][0],     s[2 * ks][1]);
            pa[ks][1] = packh2(s[2 * ks][2],     s[2 * ks][3]);
            pa[ks][2] = packh2(s[2 * ks + 1][0], s[2 * ks + 1][1]);
            pa[ks][3] = packh2(s[2 * ks + 1][2], s[2 * ks + 1][3]);
        }

        // ---- O += P @ V ----
#pragma unroll
        for (int ks = 0; ks < 4; ks++) {
            const int k0 = ks * 16;
#pragma unroll
            for (int nt2 = 0; nt2 < 4; nt2++) {
                uint32_t r4[4];
                ldm_x4_t(r4, &sm.Vs[buf][k0 + (lane & 15)]
                                        [nt2 * 16 + (lane >> 4) * 8]);
                uint32_t b0[2] = { r4[0], r4[1] };
                uint32_t b1[2] = { r4[2], r4[3] };
                mma_f16(o[nt2 * 2],     pa[ks], b0);
                mma_f16(o[nt2 * 2 + 1], pa[ks], b1);
            }
        }
        __syncthreads();
    }

    // ---- epilogue: O /= l, store fp16 ----
    {
        const float i0 = 1.0f / lr[0];
        const float i1 = 1.0f / lr[1];
        const int r = qtile * 256 + m0 + g;
#pragma unroll
        for (int nt = 0; nt < 8; nt++) {
            const int c = h * 64 + nt * 8 + 2 * tq;
            *(half2*)&out[(size_t)(b * N_ + r) * C_ + c] =
                __floats2half2_rn(o[nt][0] * i0, o[nt][1] * i0);
            *(half2*)&out[(size_t)(b * N_ + r + 8) * C_ + c] =
                __floats2half2_rn(o[nt][2] * i1, o[nt][3] * i1);
        }
    }
#undef LOAD_KV
}

// ---------------------------------------------------------------------------
// Launch
// ---------------------------------------------------------------------------
extern "C" void kernel_launch(void* const* d_in, const int* in_sizes, int n_in,
                              void* d_out, int out_size)
{
    const float* x       = (const float*)d_in[0];
    const float* qkv_w   = (const float*)d_in[1];
    const float* qkv_b   = (const float*)d_in[2];
    const float* proj_w  = (const float*)d_in[3];
    const float* proj_b  = (const float*)d_in[4];
    const float* q_gamma = (const float*)d_in[5];
    const float* k_gamma = (const float*)d_in[6];
    float* out = (float*)d_out;

    void *p_xh, *p_wqkvh, *p_wprojh, *p_qkvh, *p_attnh, *p_tab;
    cudaGetSymbolAddress(&p_xh, g_xh);
    cudaGetSymbolAddress(&p_wqkvh, g_wqkvh);
    cudaGetSymbolAddress(&p_wprojh, g_wprojh);
    cudaGetSymbolAddress(&p_qkvh, g_qkvh);
    cudaGetSymbolAddress(&p_attnh, g_attnh);
    cudaGetSymbolAddress(&p_tab, g_ropetab);
    __half* xh     = (__half*)p_xh;
    __half* wqkvh  = (__half*)p_wqkvh;
    __half* wprojh = (__half*)p_wprojh;
    __half* qkvh   = (__half*)p_qkvh;
    __half* attnh  = (__half*)p_attnh;
    float2* tab    = (float2*)p_tab;

    const int flash_smem = (int)sizeof(FSmem);
    cudaFuncSetAttribute(gemm_f16_kernel<0>,
                         cudaFuncAttributeMaxDynamicSharedMemorySize, GEMM_SMEM);
    cudaFuncSetAttribute(gemm_f16_kernel<1>,
                         cudaFuncAttributeMaxDynamicSharedMemorySize, GEMM_SMEM);
    cudaFuncSetAttribute(flash_f16_kernel,
                         cudaFuncAttributeMaxDynamicSharedMemorySize, flash_smem);

    // 0. prepass: fp16 conversion + rope table
    to_half_kernel<<<(TOKENS * C_) / 1024, 256>>>(x, xh);
    to_half_kernel<<<(C_ * 3 * C_) / 1024, 256>>>(qkv_w, wqkvh);
    to_half_kernel<<<(C_ * C_) / 1024, 256>>>(proj_w, wprojh);
    ropetab_kernel<<<(N_ * HD_) / 256, 256>>>(tab);

    // 1. QKV GEMM + fused RMSNorm/RoPE epilogue (fp16 out)
    {
        dim3 grid(3 * C_ / 128, TOKENS / 128);
        gemm_f16_kernel<1><<<grid, 128, GEMM_SMEM>>>(
            xh, wqkvh, qkv_b, nullptr, qkvh, q_gamma, k_gamma, tab,
            TOKENS, 3 * C_, C_);
    }

    // 2. Flash attention (register-P, fixed-max softmax)
    {
        dim3 grid(N_ / 256, B_ * H_);
        flash_f16_kernel<<<grid, 512, flash_smem>>>(qkvh, attnh);
    }

    // 3. Output projection (fp32 out)
    {
        dim3 grid(C_ / 128, TOKENS / 128);
        gemm_f16_kernel<0><<<grid, 128, GEMM_SMEM>>>(
            attnh, wprojh, proj_b, out, nullptr, nullptr, nullptr, nullptr,
            TOKENS, C_, C_);
    }
}

// round 9
// speedup vs baseline: 7.2126x; 1.0077x over previous
#include <cuda_runtime.h>
#include <cuda_fp16.h>
#include <math.h>
#include <stdint.h>

#define B_  32
#define N_  1024
#define C_  1024
#define H_  16
#define HD_ 64
#define TOKENS (B_ * N_)        // 32768
#define TOKSTRIDE 3072

// Scratch (static device globals; no runtime allocation)
__device__ __half g_xh[(size_t)TOKENS * C_];           // fp16 x
__device__ __half g_wqkvh[(size_t)C_ * 3 * C_];        // fp16 qkv_w [1024][3072]
__device__ __half g_wprojh[(size_t)C_ * C_];           // fp16 proj_w [1024][1024]
__device__ __half g_qkvh[(size_t)TOKENS * TOKSTRIDE];  // fp16 q(roped)/k(roped)/v
__device__ __half g_attnh[(size_t)TOKENS * C_];        // fp16 attention output
__device__ float2 g_ropetab[(size_t)N_ * HD_];         // (cos, sin) per (n, c)

// ---------------------------------------------------------------------------
// Helpers
// ---------------------------------------------------------------------------
__device__ __forceinline__ void ldm_x4(uint32_t* r, const void* p) {
    uint32_t a = (uint32_t)__cvta_generic_to_shared(p);
    asm volatile("ldmatrix.sync.aligned.m8n8.x4.shared.b16 {%0,%1,%2,%3}, [%4];"
                 : "=r"(r[0]), "=r"(r[1]), "=r"(r[2]), "=r"(r[3]) : "r"(a));
}
__device__ __forceinline__ void ldm_x4_t(uint32_t* r, const void* p) {
    uint32_t a = (uint32_t)__cvta_generic_to_shared(p);
    asm volatile("ldmatrix.sync.aligned.m8n8.x4.trans.shared.b16 {%0,%1,%2,%3}, [%4];"
                 : "=r"(r[0]), "=r"(r[1]), "=r"(r[2]), "=r"(r[3]) : "r"(a));
}

__device__ __forceinline__ void mma_f16(float* d, const uint32_t* a, const uint32_t* b) {
    asm volatile("mma.sync.aligned.m16n8k16.row.col.f32.f16.f16.f32 "
                 "{%0,%1,%2,%3}, {%4,%5,%6,%7}, {%8,%9}, {%0,%1,%2,%3};"
                 : "+f"(d[0]), "+f"(d[1]), "+f"(d[2]), "+f"(d[3])
                 : "r"(a[0]), "r"(a[1]), "r"(a[2]), "r"(a[3]), "r"(b[0]), "r"(b[1]));
}

__device__ __forceinline__ void cp16(void* dst, const void* src) {
    uint32_t d = (uint32_t)__cvta_generic_to_shared(dst);
    asm volatile("cp.async.cg.shared.global [%0], [%1], 16;" :: "r"(d), "l"(src));
}
__device__ __forceinline__ void cp_commit() { asm volatile("cp.async.commit_group;"); }
template <int NN>
__device__ __forceinline__ void cp_wait() { asm volatile("cp.async.wait_group %0;" :: "n"(NN)); }

__device__ __forceinline__ uint32_t packh2(float a, float b) {
    half2 h = __floats2half2_rn(a, b);
    return *(uint32_t*)&h;
}

// ---------------------------------------------------------------------------
// fp32 -> fp16 conversion prepass
// ---------------------------------------------------------------------------
__global__ __launch_bounds__(256)
void to_half_kernel(const float* __restrict__ in, __half* __restrict__ out) {
    int i = blockIdx.x * 256 + threadIdx.x;
    float4 v = ((const float4*)in)[i];
    ((half2*)out)[i * 2]     = __floats2half2_rn(v.x, v.y);
    ((half2*)out)[i * 2 + 1] = __floats2half2_rn(v.z, v.w);
}

// ---------------------------------------------------------------------------
// RoPE table: tab[n*64+c] = (cos, sin) of angle(n, c)
// ---------------------------------------------------------------------------
__global__ __launch_bounds__(256)
void ropetab_kernel(float2* __restrict__ tab) {
    int i = blockIdx.x * 256 + threadIdx.x;   // 0..65535
    int n = i >> 6, c = i & 63;
    const bool lo = (c < 32);
    const int j0 = c & 31;
    const float LOG2_THETA = 13.28771237954945f;
    float f = exp2f(-(float)(j0 & 15) * (1.0f / 16.0f) * LOG2_THETA);
    float t = lo ? (float)(n >> 5) : (float)(n & 31);
    float s, co;
    sincosf(t * f, &s, &co);
    tab[i] = make_float2(co, s);
}

// ---------------------------------------------------------------------------
// fp16 HMMA GEMM, CTA 128x128, BK=64, 128 threads (4 warps, 2x2 of 64x64).
// 3-stage cp.async pipeline, 2 CTAs/SM.
// MODE 0: C(fp32) = A@B + bias.
// MODE 1: QKV fused epilogue -> fp16 out with RMSNorm+RoPE on q,k sections.
// ---------------------------------------------------------------------------
template <int MODE>
__global__ __launch_bounds__(128, 2)
void gemm_f16_kernel(const __half* __restrict__ A, const __half* __restrict__ Bm,
                     const float* __restrict__ bias, float* __restrict__ Cf,
                     __half* __restrict__ Ch,
                     const float* __restrict__ q_gamma,
                     const float* __restrict__ k_gamma,
                     const float2* __restrict__ ropetab,
                     int M, int N, int K)
{
    extern __shared__ char sraw[];
    __half (*As)[128][72] = (__half(*)[128][72])sraw;
    __half (*Bs)[64][136] = (__half(*)[64][136])(sraw + 3 * 128 * 72 * 2);

    const int tid  = threadIdx.x;
    const int warp = tid >> 5, lane = tid & 31;
    const int wm = warp >> 1, wn = warp & 1;
    const int g = lane >> 2, tq = lane & 3;
    const int row0 = blockIdx.y * 128;
    const int col0 = blockIdx.x * 128;
    const int KT = K / 64;

#define LOAD_STAGE(S, KT0)                                                          \
    {                                                                               \
        _Pragma("unroll")                                                           \
        for (int i = 0; i < 8; i++) {                                               \
            int f = tid + i * 128;                                                  \
            int r_ = f >> 3, u_ = f & 7;                                            \
            cp16(&As[S][r_][u_ * 8],                                                \
                 A + (size_t)(row0 + r_) * K + (KT0) * 64 + u_ * 8);                \
            int br_ = f >> 4, nb_ = f & 15;                                         \
            cp16(&Bs[S][br_][nb_ * 8],                                              \
                 Bm + (size_t)((KT0) * 64 + br_) * N + col0 + nb_ * 8);             \
        }                                                                           \
        cp_commit();                                                                \
    }

    float acc[4][8][4];
#pragma unroll
    for (int a = 0; a < 4; a++)
#pragma unroll
        for (int b = 0; b < 8; b++)
#pragma unroll
            for (int c = 0; c < 4; c++) acc[a][b][c] = 0.0f;

    LOAD_STAGE(0, 0);
    LOAD_STAGE(1, 1);

    for (int kt = 0; kt < KT; kt++) {
        const int s = kt % 3;
        if (kt + 1 < KT) { cp_wait<1>(); } else { cp_wait<0>(); }
        __syncthreads();

        if (kt + 2 < KT) { LOAD_STAGE((kt + 2) % 3, kt + 2); }

#pragma unroll
        for (int ks = 0; ks < 4; ks++) {
            const int k0 = ks * 16;
            uint32_t afr[4][4];
#pragma unroll
            for (int mt = 0; mt < 4; mt++)
                ldm_x4(afr[mt], &As[s][wm * 64 + mt * 16 + (lane & 15)]
                                     [k0 + (lane >> 4) * 8]);
            uint32_t bfr[8][2];
#pragma unroll
            for (int nt2 = 0; nt2 < 4; nt2++) {
                uint32_t r4[4];
                ldm_x4_t(r4, &Bs[s][k0 + (lane & 15)]
                                   [wn * 64 + nt2 * 16 + (lane >> 4) * 8]);
                bfr[nt2 * 2][0]     = r4[0]; bfr[nt2 * 2][1]     = r4[1];
                bfr[nt2 * 2 + 1][0] = r4[2]; bfr[nt2 * 2 + 1][1] = r4[3];
            }
#pragma unroll
            for (int mt = 0; mt < 4; mt++)
#pragma unroll
                for (int nt = 0; nt < 8; nt++)
                    mma_f16(acc[mt][nt], afr[mt], bfr[nt]);
        }
        __syncthreads();
    }

    if (MODE == 0) {
#pragma unroll
        for (int mt = 0; mt < 4; mt++) {
            const int r = row0 + wm * 64 + mt * 16 + g;
#pragma unroll
            for (int nt = 0; nt < 8; nt++) {
                const int c = col0 + wn * 64 + nt * 8 + 2 * tq;
                const float b0 = bias[c], b1 = bias[c + 1];
                float2 v0 = make_float2(acc[mt][nt][0] + b0, acc[mt][nt][1] + b1);
                float2 v1 = make_float2(acc[mt][nt][2] + b0, acc[mt][nt][3] + b1);
                *(float2*)&Cf[(size_t)r * N + c]       = v0;
                *(float2*)&Cf[(size_t)(r + 8) * N + c] = v1;
            }
        }
    } else {
        const int gc  = col0 + wn * 64;
        const int sec = gc >> 10;            // 0=q, 1=k, 2=v
        float br[8][2], gr[8][2];
        const float* gam = (sec == 1) ? k_gamma : q_gamma;
#pragma unroll
        for (int nt = 0; nt < 8; nt++) {
            const int cc = nt * 8 + 2 * tq;
            br[nt][0] = bias[gc + cc];
            br[nt][1] = bias[gc + cc + 1];
            if (sec < 2) {
                gr[nt][0] = gam[cc];
                gr[nt][1] = gam[cc + 1];
            }
        }

#pragma unroll
        for (int mt = 0; mt < 4; mt++) {
#pragma unroll
            for (int rh = 0; rh < 2; rh++) {
                const int tok = row0 + wm * 64 + mt * 16 + g + rh * 8;
                __half* outp = Ch + (size_t)tok * TOKSTRIDE + gc;
                float vv[8][2];
#pragma unroll
                for (int nt = 0; nt < 8; nt++) {
                    vv[nt][0] = acc[mt][nt][rh * 2]     + br[nt][0];
                    vv[nt][1] = acc[mt][nt][rh * 2 + 1] + br[nt][1];
                }
                if (sec == 2) {
#pragma unroll
                    for (int nt = 0; nt < 8; nt++)
                        *(half2*)&outp[nt * 8 + 2 * tq] =
                            __floats2half2_rn(vv[nt][0], vv[nt][1]);
                    continue;
                }
                float ss = 0.0f;
#pragma unroll
                for (int nt = 0; nt < 8; nt++)
                    ss += vv[nt][0] * vv[nt][0] + vv[nt][1] * vv[nt][1];
                ss += __shfl_xor_sync(0xffffffffu, ss, 1);
                ss += __shfl_xor_sync(0xffffffffu, ss, 2);
                const float inv = rsqrtf(ss * (1.0f / 64.0f) + 1e-6f);
#pragma unroll
                for (int nt = 0; nt < 8; nt++) {
                    vv[nt][0] *= inv * gr[nt][0];
                    vv[nt][1] *= inv * gr[nt][1];
                }
                const int n = tok & (N_ - 1);
                const float2* tabn = ropetab + (size_t)n * HD_;
#pragma unroll
                for (int nt = 0; nt < 4; nt++) {
                    const int cc = nt * 8 + 2 * tq;
                    float2 t0 = tabn[cc], t1 = tabn[cc + 1];
                    float2 u0 = tabn[cc + 32], u1 = tabn[cc + 33];
                    float lo0 = vv[nt][0] * t0.x - vv[nt + 4][0] * t0.y;
                    float lo1 = vv[nt][1] * t1.x - vv[nt + 4][1] * t1.y;
                    float hi0 = vv[nt + 4][0] * u0.x + vv[nt][0] * u0.y;
                    float hi1 = vv[nt + 4][1] * u1.x + vv[nt][1] * u1.y;
                    *(half2*)&outp[cc]      = __floats2half2_rn(lo0, lo1);
                    *(half2*)&outp[cc + 32] = __floats2half2_rn(hi0, hi1);
                }
            }
        }
    }
#undef LOAD_STAGE
}

#define GEMM_SMEM ((3 * 128 * 72 + 3 * 64 * 136) * 2)   // 107520

// ---------------------------------------------------------------------------
// fp16 HMMA flash attention, fixed-max softmax, register-resident P (FA-2),
// register-resident Q fragments, 3-stage KV pipeline, 1 barrier/iter.
// CTA: 256 queries x 64-kv tiles, hd=64. 16 warps (512 thr), warp = 16 q rows.
// ---------------------------------------------------------------------------
struct FSmem {
    __half Qs[256][72];      // pre-scaled Q (staging only)
    __half Ks[3][64][72];
    __half Vs[3][64][72];
};

__global__ __launch_bounds__(512, 1)
void flash_f16_kernel(const __half* __restrict__ qkvh, __half* __restrict__ out)
{
    extern __shared__ char sm_raw[];
    FSmem& sm = *reinterpret_cast<FSmem*>(sm_raw);

    const int tid  = threadIdx.x;
    const int warp = tid >> 5, lane = tid & 31;
    const int g = lane >> 2, tq = lane & 3;
    const int qtile = blockIdx.x;        // 0..3
    const int bh = blockIdx.y;           // 0..511
    const int b = bh >> 4, h = bh & 15;
    const int m0 = warp * 16;

    const __half* qbase = qkvh + (size_t)b * N_ * TOKSTRIDE + h * HD_;
    const __half* kbase = qbase + C_;
    const __half* vbase = qbase + 2 * C_;

    const half2 hscale = __floats2half2_rn(0.125f, 0.125f);
    for (int i = tid; i < 4096; i += 512) {
        int r = i >> 4, d4 = (i & 15) * 4;
        half2 a = *(const half2*)(qbase + (size_t)(qtile * 256 + r) * TOKSTRIDE + d4);
        half2 c = *(const half2*)(qbase + (size_t)(qtile * 256 + r) * TOKSTRIDE + d4 + 2);
        *(half2*)&sm.Qs[r][d4]     = __hmul2(a, hscale);
        *(half2*)&sm.Qs[r][d4 + 2] = __hmul2(c, hscale);
    }

#define LOAD_KV(BUF, KT0)                                                           \
    {                                                                               \
        for (int i = tid; i < 1024; i += 512) {                                     \
            int r_ = i >> 3, u_ = (i & 7) * 8;                                      \
            if (i < 512)                                                            \
                cp16(&sm.Ks[BUF][r_][u_],                                           \
                     kbase + (size_t)((KT0) * 64 + r_) * TOKSTRIDE + u_);           \
            else                                                                    \
                cp16(&sm.Vs[BUF][r_ - 64][u_],                                      \
                     vbase + (size_t)((KT0) * 64 + r_ - 64) * TOKSTRIDE + u_);      \
        }                                                                           \
        cp_commit();                                                                \
    }

    LOAD_KV(0, 0);
    LOAD_KV(1, 1);
    __syncthreads();    // Qs visible to all warps

    // Hoist Q fragments (loop-invariant): aq[ks] covers k = ks*16..+16
    uint32_t aq[4][4];
#pragma unroll
    for (int ks = 0; ks < 4; ks++)
        ldm_x4(aq[ks], &sm.Qs[m0 + (lane & 15)][ks * 16 + (lane >> 4) * 8]);

    float o[8][4];
    float lr[2];
    lr[0] = lr[1] = 0.0f;
#pragma unroll
    for (int c = 0; c < 8; c++)
#pragma unroll
        for (int d = 0; d < 4; d++) o[c][d] = 0.0f;

    const int ki = lane & 7, kq = lane >> 3;

    for (int kt = 0; kt < 16; kt++) {
        const int buf = kt % 3;
        if (kt + 1 < 16) { cp_wait<1>(); } else { cp_wait<0>(); }
        __syncthreads();    // stage kt ready everywhere; stage (kt+2)%3 free

        if (kt + 2 < 16) { LOAD_KV((kt + 2) % 3, kt + 2); }

        // ---- S = Q @ K^T ----
        float s[8][4];
#pragma unroll
        for (int c = 0; c < 8; c++)
#pragma unroll
            for (int d = 0; d < 4; d++) s[c][d] = 0.0f;

#pragma unroll
        for (int ks = 0; ks < 4; ks++) {
            const int k0 = ks * 16;
#pragma unroll
            for (int nt2 = 0; nt2 < 4; nt2++) {
                uint32_t r4[4];
                ldm_x4(r4, &sm.Ks[buf][nt2 * 16 + (kq >> 1) * 8 + ki]
                                      [k0 + (kq & 1) * 8]);
                uint32_t b0[2] = { r4[0], r4[1] };
                uint32_t b1[2] = { r4[2], r4[3] };
                mma_f16(s[nt2 * 2],     aq[ks], b0);
                mma_f16(s[nt2 * 2 + 1], aq[ks], b1);
            }
        }

        // ---- fixed-max softmax: P = exp(s - 8), l += sum ----
#pragma unroll
        for (int hf = 0; hf < 2; hf++) {
            float rs = 0.0f;
#pragma unroll
            for (int nt = 0; nt < 8; nt++) {
                float e0 = __expf(s[nt][hf * 2]     - 8.0f);
                float e1 = __expf(s[nt][hf * 2 + 1] - 8.0f);
                s[nt][hf * 2] = e0; s[nt][hf * 2 + 1] = e1;
                rs += e0 + e1;
            }
            rs += __shfl_xor_sync(0xffffffffu, rs, 1);
            rs += __shfl_xor_sync(0xffffffffu, rs, 2);
            lr[hf] += rs;
        }

        // ---- pack P into A-fragments (register-resident) ----
        uint32_t pa[4][4];
#pragma unroll
        for (int ks = 0; ks < 4; ks++) {
            pa[ks][0] = packh2(s[2 * ks][0],     s[2 * ks][1]);
            pa[ks][1] = packh2(s[2 * ks][2],     s[2 * ks][3]);
            pa[ks][2] = packh2(s[2 * ks + 1][0], s[2 * ks + 1][1]);
            pa[ks][3] = packh2(s[2 * ks + 1][2], s[2 * ks + 1][3]);
        }

        // ---- O += P @ V ----
#pragma unroll
        for (int ks = 0; ks < 4; ks++) {
            const int k0 = ks * 16;
#pragma unroll
            for (int nt2 = 0; nt2 < 4; nt2++) {
                uint32_t r4[4];
                ldm_x4_t(r4, &sm.Vs[buf][k0 + (lane & 15)]
                                        [nt2 * 16 + (lane >> 4) * 8]);
                uint32_t b0[2] = { r4[0], r4[1] };
                uint32_t b1[2] = { r4[2], r4[3] };
                mma_f16(o[nt2 * 2],     pa[ks], b0);
                mma_f16(o[nt2 * 2 + 1], pa[ks], b1);
            }
        }
    }

    // ---- epilogue: O /= l, store fp16 ----
    {
        const float i0 = 1.0f / lr[0];
        const float i1 = 1.0f / lr[1];
        const int r = qtile * 256 + m0 + g;
#pragma unroll
        for (int nt = 0; nt < 8; nt++) {
            const int c = h * 64 + nt * 8 + 2 * tq;
            *(half2*)&out[(size_t)(b * N_ + r) * C_ + c] =
                __floats2half2_rn(o[nt][0] * i0, o[nt][1] * i0);
            *(half2*)&out[(size_t)(b * N_ + r + 8) * C_ + c] =
                __floats2half2_rn(o[nt][2] * i1, o[nt][3] * i1);
        }
    }
#undef LOAD_KV
}

// ---------------------------------------------------------------------------
// Launch
// ---------------------------------------------------------------------------
extern "C" void kernel_launch(void* const* d_in, const int* in_sizes, int n_in,
                              void* d_out, int out_size)
{
    const float* x       = (const float*)d_in[0];
    const float* qkv_w   = (const float*)d_in[1];
    const float* qkv_b   = (const float*)d_in[2];
    const float* proj_w  = (const float*)d_in[3];
    const float* proj_b  = (const float*)d_in[4];
    const float* q_gamma = (const float*)d_in[5];
    const float* k_gamma = (const float*)d_in[6];
    float* out = (float*)d_out;

    void *p_xh, *p_wqkvh, *p_wprojh, *p_qkvh, *p_attnh, *p_tab;
    cudaGetSymbolAddress(&p_xh, g_xh);
    cudaGetSymbolAddress(&p_wqkvh, g_wqkvh);
    cudaGetSymbolAddress(&p_wprojh, g_wprojh);
    cudaGetSymbolAddress(&p_qkvh, g_qkvh);
    cudaGetSymbolAddress(&p_attnh, g_attnh);
    cudaGetSymbolAddress(&p_tab, g_ropetab);
    __half* xh     = (__half*)p_xh;
    __half* wqkvh  = (__half*)p_wqkvh;
    __half* wprojh = (__half*)p_wprojh;
    __half* qkvh   = (__half*)p_qkvh;
    __half* attnh  = (__half*)p_attnh;
    float2* tab    = (float2*)p_tab;

    const int flash_smem = (int)sizeof(FSmem);
    cudaFuncSetAttribute(gemm_f16_kernel<0>,
                         cudaFuncAttributeMaxDynamicSharedMemorySize, GEMM_SMEM);
    cudaFuncSetAttribute(gemm_f16_kernel<1>,
                         cudaFuncAttributeMaxDynamicSharedMemorySize, GEMM_SMEM);
    cudaFuncSetAttribute(flash_f16_kernel,
                         cudaFuncAttributeMaxDynamicSharedMemorySize, flash_smem);

    // 0. prepass: fp16 conversion + rope table
    to_half_kernel<<<(TOKENS * C_) / 1024, 256>>>(x, xh);
    to_half_kernel<<<(C_ * 3 * C_) / 1024, 256>>>(qkv_w, wqkvh);
    to_half_kernel<<<(C_ * C_) / 1024, 256>>>(proj_w, wprojh);
    ropetab_kernel<<<(N_ * HD_) / 256, 256>>>(tab);

    // 1. QKV GEMM + fused RMSNorm/RoPE epilogue (fp16 out)
    {
        dim3 grid(3 * C_ / 128, TOKENS / 128);
        gemm_f16_kernel<1><<<grid, 128, GEMM_SMEM>>>(
            xh, wqkvh, qkv_b, nullptr, qkvh, q_gamma, k_gamma, tab,
            TOKENS, 3 * C_, C_);
    }

    // 2. Flash attention (register-P, register-Q, 3-stage KV)
    {
        dim3 grid(N_ / 256, B_ * H_);
        flash_f16_kernel<<<grid, 512, flash_smem>>>(qkvh, attnh);
    }

    // 3. Output projection (fp32 out)
    {
        dim3 grid(C_ / 128, TOKENS / 128);
        gemm_f16_kernel<0><<<grid, 128, GEMM_SMEM>>>(
            attnh, wprojh, proj_b, out, nullptr, nullptr, nullptr, nullptr,
            TOKENS, C_, C_);
    }
}

// round 10
// speedup vs baseline: 7.4734x; 1.0362x over previous
#include <cuda_runtime.h>
#include <cuda_fp16.h>
#include <math.h>
#include <stdint.h>

#define B_  32
#define N_  1024
#define C_  1024
#define H_  16
#define HD_ 64
#define TOKENS (B_ * N_)        // 32768
#define TOKSTRIDE 3072

// Scratch (static device globals; no runtime allocation)
__device__ __half g_xh[(size_t)TOKENS * C_];           // fp16 x
__device__ __half g_wqkvh[(size_t)C_ * 3 * C_];        // fp16 qkv_w [1024][3072]
__device__ __half g_wprojh[(size_t)C_ * C_];           // fp16 proj_w [1024][1024]
__device__ __half g_qkvh[(size_t)TOKENS * TOKSTRIDE];  // fp16 q(roped)/k(roped)/v
__device__ __half g_attnh[(size_t)TOKENS * C_];        // fp16 attention output
__device__ float2 g_ropetab[(size_t)N_ * HD_];         // (cos, sin) per (n, c)

// ---------------------------------------------------------------------------
// Helpers
// ---------------------------------------------------------------------------
__device__ __forceinline__ void ldm_x4(uint32_t* r, const void* p) {
    uint32_t a = (uint32_t)__cvta_generic_to_shared(p);
    asm volatile("ldmatrix.sync.aligned.m8n8.x4.shared.b16 {%0,%1,%2,%3}, [%4];"
                 : "=r"(r[0]), "=r"(r[1]), "=r"(r[2]), "=r"(r[3]) : "r"(a));
}
__device__ __forceinline__ void ldm_x4_t(uint32_t* r, const void* p) {
    uint32_t a = (uint32_t)__cvta_generic_to_shared(p);
    asm volatile("ldmatrix.sync.aligned.m8n8.x4.trans.shared.b16 {%0,%1,%2,%3}, [%4];"
                 : "=r"(r[0]), "=r"(r[1]), "=r"(r[2]), "=r"(r[3]) : "r"(a));
}

__device__ __forceinline__ void mma_f16(float* d, const uint32_t* a, const uint32_t* b) {
    asm volatile("mma.sync.aligned.m16n8k16.row.col.f32.f16.f16.f32 "
                 "{%0,%1,%2,%3}, {%4,%5,%6,%7}, {%8,%9}, {%0,%1,%2,%3};"
                 : "+f"(d[0]), "+f"(d[1]), "+f"(d[2]), "+f"(d[3])
                 : "r"(a[0]), "r"(a[1]), "r"(a[2]), "r"(a[3]), "r"(b[0]), "r"(b[1]));
}

__device__ __forceinline__ void cp16(void* dst, const void* src) {
    uint32_t d = (uint32_t)__cvta_generic_to_shared(dst);
    asm volatile("cp.async.cg.shared.global [%0], [%1], 16;" :: "r"(d), "l"(src));
}
__device__ __forceinline__ void cp_commit() { asm volatile("cp.async.commit_group;"); }
template <int NN>
__device__ __forceinline__ void cp_wait() { asm volatile("cp.async.wait_group %0;" :: "n"(NN)); }

__device__ __forceinline__ uint32_t packh2(float a, float b) {
    half2 h = __floats2half2_rn(a, b);
    return *(uint32_t*)&h;
}

// ---------------------------------------------------------------------------
// fp32 -> fp16 conversion prepass
// ---------------------------------------------------------------------------
__global__ __launch_bounds__(256)
void to_half_kernel(const float* __restrict__ in, __half* __restrict__ out) {
    int i = blockIdx.x * 256 + threadIdx.x;
    float4 v = ((const float4*)in)[i];
    ((half2*)out)[i * 2]     = __floats2half2_rn(v.x, v.y);
    ((half2*)out)[i * 2 + 1] = __floats2half2_rn(v.z, v.w);
}

// ---------------------------------------------------------------------------
// RoPE table: tab[n*64+c] = (cos, sin) of angle(n, c)
// ---------------------------------------------------------------------------
__global__ __launch_bounds__(256)
void ropetab_kernel(float2* __restrict__ tab) {
    int i = blockIdx.x * 256 + threadIdx.x;   // 0..65535
    int n = i >> 6, c = i & 63;
    const bool lo = (c < 32);
    const int j0 = c & 31;
    const float LOG2_THETA = 13.28771237954945f;
    float f = exp2f(-(float)(j0 & 15) * (1.0f / 16.0f) * LOG2_THETA);
    float t = lo ? (float)(n >> 5) : (float)(n & 31);
    float s, co;
    sincosf(t * f, &s, &co);
    tab[i] = make_float2(co, s);
}

// ---------------------------------------------------------------------------
// fp16 HMMA GEMM, CTA 128x128, BK=64, 128 threads (4 warps, 2x2 of 64x64).
// 3-stage cp.async pipeline, 2 CTAs/SM.
// MODE 0: C(fp32) = A@B + bias.
// MODE 1: QKV fused epilogue -> fp16 out with RMSNorm+RoPE on q,k sections.
// ---------------------------------------------------------------------------
template <int MODE>
__global__ __launch_bounds__(128, 2)
void gemm_f16_kernel(const __half* __restrict__ A, const __half* __restrict__ Bm,
                     const float* __restrict__ bias, float* __restrict__ Cf,
                     __half* __restrict__ Ch,
                     const float* __restrict__ q_gamma,
                     const float* __restrict__ k_gamma,
                     const float2* __restrict__ ropetab,
                     int M, int N, int K)
{
    extern __shared__ char sraw[];
    __half (*As)[128][72] = (__half(*)[128][72])sraw;
    __half (*Bs)[64][136] = (__half(*)[64][136])(sraw + 3 * 128 * 72 * 2);

    const int tid  = threadIdx.x;
    const int warp = tid >> 5, lane = tid & 31;
    const int wm = warp >> 1, wn = warp & 1;
    const int g = lane >> 2, tq = lane & 3;
    const int row0 = blockIdx.y * 128;
    const int col0 = blockIdx.x * 128;
    const int KT = K / 64;

#define LOAD_STAGE(S, KT0)                                                          \
    {                                                                               \
        _Pragma("unroll")                                                           \
        for (int i = 0; i < 8; i++) {                                               \
            int f = tid + i * 128;                                                  \
            int r_ = f >> 3, u_ = f & 7;                                            \
            cp16(&As[S][r_][u_ * 8],                                                \
                 A + (size_t)(row0 + r_) * K + (KT0) * 64 + u_ * 8);                \
            int br_ = f >> 4, nb_ = f & 15;                                         \
            cp16(&Bs[S][br_][nb_ * 8],                                              \
                 Bm + (size_t)((KT0) * 64 + br_) * N + col0 + nb_ * 8);             \
        }                                                                           \
        cp_commit();                                                                \
    }

    float acc[4][8][4];
#pragma unroll
    for (int a = 0; a < 4; a++)
#pragma unroll
        for (int b = 0; b < 8; b++)
#pragma unroll
            for (int c = 0; c < 4; c++) acc[a][b][c] = 0.0f;

    LOAD_STAGE(0, 0);
    LOAD_STAGE(1, 1);

    for (int kt = 0; kt < KT; kt++) {
        const int s = kt % 3;
        if (kt + 1 < KT) { cp_wait<1>(); } else { cp_wait<0>(); }
        __syncthreads();

        if (kt + 2 < KT) { LOAD_STAGE((kt + 2) % 3, kt + 2); }

#pragma unroll
        for (int ks = 0; ks < 4; ks++) {
            const int k0 = ks * 16;
            uint32_t afr[4][4];
#pragma unroll
            for (int mt = 0; mt < 4; mt++)
                ldm_x4(afr[mt], &As[s][wm * 64 + mt * 16 + (lane & 15)]
                                     [k0 + (lane >> 4) * 8]);
            uint32_t bfr[8][2];
#pragma unroll
            for (int nt2 = 0; nt2 < 4; nt2++) {
                uint32_t r4[4];
                ldm_x4_t(r4, &Bs[s][k0 + (lane & 15)]
                                   [wn * 64 + nt2 * 16 + (lane >> 4) * 8]);
                bfr[nt2 * 2][0]     = r4[0]; bfr[nt2 * 2][1]     = r4[1];
                bfr[nt2 * 2 + 1][0] = r4[2]; bfr[nt2 * 2 + 1][1] = r4[3];
            }
#pragma unroll
            for (int mt = 0; mt < 4; mt++)
#pragma unroll
                for (int nt = 0; nt < 8; nt++)
                    mma_f16(acc[mt][nt], afr[mt], bfr[nt]);
        }
        __syncthreads();
    }

    if (MODE == 0) {
#pragma unroll
        for (int mt = 0; mt < 4; mt++) {
            const int r = row0 + wm * 64 + mt * 16 + g;
#pragma unroll
            for (int nt = 0; nt < 8; nt++) {
                const int c = col0 + wn * 64 + nt * 8 + 2 * tq;
                const float b0 = bias[c], b1 = bias[c + 1];
                float2 v0 = make_float2(acc[mt][nt][0] + b0, acc[mt][nt][1] + b1);
                float2 v1 = make_float2(acc[mt][nt][2] + b0, acc[mt][nt][3] + b1);
                *(float2*)&Cf[(size_t)r * N + c]       = v0;
                *(float2*)&Cf[(size_t)(r + 8) * N + c] = v1;
            }
        }
    } else {
        const int gc  = col0 + wn * 64;
        const int sec = gc >> 10;            // 0=q, 1=k, 2=v
        float br[8][2], gr[8][2];
        const float* gam = (sec == 1) ? k_gamma : q_gamma;
#pragma unroll
        for (int nt = 0; nt < 8; nt++) {
            const int cc = nt * 8 + 2 * tq;
            br[nt][0] = bias[gc + cc];
            br[nt][1] = bias[gc + cc + 1];
            if (sec < 2) {
                gr[nt][0] = gam[cc];
                gr[nt][1] = gam[cc + 1];
            }
        }

#pragma unroll
        for (int mt = 0; mt < 4; mt++) {
#pragma unroll
            for (int rh = 0; rh < 2; rh++) {
                const int tok = row0 + wm * 64 + mt * 16 + g + rh * 8;
                __half* outp = Ch + (size_t)tok * TOKSTRIDE + gc;
                float vv[8][2];
#pragma unroll
                for (int nt = 0; nt < 8; nt++) {
                    vv[nt][0] = acc[mt][nt][rh * 2]     + br[nt][0];
                    vv[nt][1] = acc[mt][nt][rh * 2 + 1] + br[nt][1];
                }
                if (sec == 2) {
#pragma unroll
                    for (int nt = 0; nt < 8; nt++)
                        *(half2*)&outp[nt * 8 + 2 * tq] =
                            __floats2half2_rn(vv[nt][0], vv[nt][1]);
                    continue;
                }
                float ss = 0.0f;
#pragma unroll
                for (int nt = 0; nt < 8; nt++)
                    ss += vv[nt][0] * vv[nt][0] + vv[nt][1] * vv[nt][1];
                ss += __shfl_xor_sync(0xffffffffu, ss, 1);
                ss += __shfl_xor_sync(0xffffffffu, ss, 2);
                const float inv = rsqrtf(ss * (1.0f / 64.0f) + 1e-6f);
#pragma unroll
                for (int nt = 0; nt < 8; nt++) {
                    vv[nt][0] *= inv * gr[nt][0];
                    vv[nt][1] *= inv * gr[nt][1];
                }
                const int n = tok & (N_ - 1);
                const float2* tabn = ropetab + (size_t)n * HD_;
#pragma unroll
                for (int nt = 0; nt < 4; nt++) {
                    const int cc = nt * 8 + 2 * tq;
                    float2 t0 = tabn[cc], t1 = tabn[cc + 1];
                    float2 u0 = tabn[cc + 32], u1 = tabn[cc + 33];
                    float lo0 = vv[nt][0] * t0.x - vv[nt + 4][0] * t0.y;
                    float lo1 = vv[nt][1] * t1.x - vv[nt + 4][1] * t1.y;
                    float hi0 = vv[nt + 4][0] * u0.x + vv[nt][0] * u0.y;
                    float hi1 = vv[nt + 4][1] * u1.x + vv[nt][1] * u1.y;
                    *(half2*)&outp[cc]      = __floats2half2_rn(lo0, lo1);
                    *(half2*)&outp[cc + 32] = __floats2half2_rn(hi0, hi1);
                }
            }
        }
    }
#undef LOAD_STAGE
}

#define GEMM_SMEM ((3 * 128 * 72 + 3 * 64 * 136) * 2)   // 107520

// ---------------------------------------------------------------------------
// fp16 HMMA flash attention, fixed-max softmax, register-resident P (FA-2),
// hoisted Q fragments, 3-stage KV ring, 1 barrier/iter.
// CTA: 128 queries x 64-kv tiles. 4 warps (128 thr), warp = 32 q rows
// (2 m-tiles) -> 4 MMAs per K/V ldmatrix (GEMM-grade reuse). 2 CTAs/SM.
// ---------------------------------------------------------------------------
struct FSmem {
    __half Qs[128][72];      // pre-scaled Q (staging)
    __half Ks[3][64][72];
    __half Vs[3][64][72];
};

__global__ __launch_bounds__(128, 2)
void flash_f16_kernel(const __half* __restrict__ qkvh, __half* __restrict__ out)
{
    extern __shared__ char sm_raw[];
    FSmem& sm = *reinterpret_cast<FSmem*>(sm_raw);

    const int tid  = threadIdx.x;
    const int warp = tid >> 5, lane = tid & 31;
    const int g = lane >> 2, tq = lane & 3;
    const int qtile = blockIdx.x;        // 0..7 (128 rows each)
    const int bh = blockIdx.y;           // 0..511
    const int b = bh >> 4, h = bh & 15;
    const int m0 = warp * 32;            // warp covers rows m0..m0+31

    const __half* qbase = qkvh + (size_t)b * N_ * TOKSTRIDE + h * HD_;
    const __half* kbase = qbase + C_;
    const __half* vbase = qbase + 2 * C_;

    const half2 hscale = __floats2half2_rn(0.125f, 0.125f);
    for (int i = tid; i < 2048; i += 128) {     // 128 rows x 16 quads
        int r = i >> 4, d4 = (i & 15) * 4;
        half2 a = *(const half2*)(qbase + (size_t)(qtile * 128 + r) * TOKSTRIDE + d4);
        half2 c = *(const half2*)(qbase + (size_t)(qtile * 128 + r) * TOKSTRIDE + d4 + 2);
        *(half2*)&sm.Qs[r][d4]     = __hmul2(a, hscale);
        *(half2*)&sm.Qs[r][d4 + 2] = __hmul2(c, hscale);
    }

#define LOAD_KV(BUF, KT0)                                                           \
    {                                                                               \
        for (int i = tid; i < 1024; i += 128) {                                     \
            int r_ = i >> 3, u_ = (i & 7) * 8;                                      \
            if (i < 512)                                                            \
                cp16(&sm.Ks[BUF][r_][u_],                                           \
                     kbase + (size_t)((KT0) * 64 + r_) * TOKSTRIDE + u_);           \
            else                                                                    \
                cp16(&sm.Vs[BUF][r_ - 64][u_],                                      \
                     vbase + (size_t)((KT0) * 64 + r_ - 64) * TOKSTRIDE + u_);      \
        }                                                                           \
        cp_commit();                                                                \
    }

    LOAD_KV(0, 0);
    LOAD_KV(1, 1);
    __syncthreads();    // Qs visible to all warps

    // Hoist Q fragments: aq[mt][ks], mt = m-tile (16 rows), ks = k-chunk
    uint32_t aq[2][4][4];
#pragma unroll
    for (int mt = 0; mt < 2; mt++)
#pragma unroll
        for (int ks = 0; ks < 4; ks++)
            ldm_x4(aq[mt][ks], &sm.Qs[m0 + mt * 16 + (lane & 15)]
                                     [ks * 16 + (lane >> 4) * 8]);

    float o[2][8][4];
    float lr[2][2];
#pragma unroll
    for (int mt = 0; mt < 2; mt++) {
        lr[mt][0] = lr[mt][1] = 0.0f;
#pragma unroll
        for (int c = 0; c < 8; c++)
#pragma unroll
            for (int d = 0; d < 4; d++) o[mt][c][d] = 0.0f;
    }

    const int ki = lane & 7, kq = lane >> 3;

    for (int kt = 0; kt < 16; kt++) {
        const int buf = kt % 3;
        if (kt + 1 < 16) { cp_wait<1>(); } else { cp_wait<0>(); }
        __syncthreads();    // stage kt ready; stage (kt+2)%3 free

        if (kt + 2 < 16) { LOAD_KV((kt + 2) % 3, kt + 2); }

        // ---- S = Q @ K^T (each K ldsm feeds 4 MMAs) ----
        float s[2][8][4];
#pragma unroll
        for (int mt = 0; mt < 2; mt++)
#pragma unroll
            for (int c = 0; c < 8; c++)
#pragma unroll
                for (int d = 0; d < 4; d++) s[mt][c][d] = 0.0f;

#pragma unroll
        for (int ks = 0; ks < 4; ks++) {
            const int k0 = ks * 16;
#pragma unroll
            for (int nt2 = 0; nt2 < 4; nt2++) {
                uint32_t r4[4];
                ldm_x4(r4, &sm.Ks[buf][nt2 * 16 + (kq >> 1) * 8 + ki]
                                      [k0 + (kq & 1) * 8]);
                uint32_t b0[2] = { r4[0], r4[1] };
                uint32_t b1[2] = { r4[2], r4[3] };
                mma_f16(s[0][nt2 * 2],     aq[0][ks], b0);
                mma_f16(s[0][nt2 * 2 + 1], aq[0][ks], b1);
                mma_f16(s[1][nt2 * 2],     aq[1][ks], b0);
                mma_f16(s[1][nt2 * 2 + 1], aq[1][ks], b1);
            }
        }

        // ---- fixed-max softmax: P = exp(s - 8), l += sum ----
#pragma unroll
        for (int mt = 0; mt < 2; mt++)
#pragma unroll
            for (int hf = 0; hf < 2; hf++) {
                float rs = 0.0f;
#pragma unroll
                for (int nt = 0; nt < 8; nt++) {
                    float e0 = __expf(s[mt][nt][hf * 2]     - 8.0f);
                    float e1 = __expf(s[mt][nt][hf * 2 + 1] - 8.0f);
                    s[mt][nt][hf * 2] = e0; s[mt][nt][hf * 2 + 1] = e1;
                    rs += e0 + e1;
                }
                rs += __shfl_xor_sync(0xffffffffu, rs, 1);
                rs += __shfl_xor_sync(0xffffffffu, rs, 2);
                lr[mt][hf] += rs;
            }

        // ---- pack P into A-fragments (register-resident) ----
        uint32_t pa[2][4][4];
#pragma unroll
        for (int mt = 0; mt < 2; mt++)
#pragma unroll
            for (int ks = 0; ks < 4; ks++) {
                pa[mt][ks][0] = packh2(s[mt][2 * ks][0],     s[mt][2 * ks][1]);
                pa[mt][ks][1] = packh2(s[mt][2 * ks][2],     s[mt][2 * ks][3]);
                pa[mt][ks][2] = packh2(s[mt][2 * ks + 1][0], s[mt][2 * ks + 1][1]);
                pa[mt][ks][3] = packh2(s[mt][2 * ks + 1][2], s[mt][2 * ks + 1][3]);
            }

        // ---- O += P @ V (each V ldsm feeds 4 MMAs) ----
#pragma unroll
        for (int ks = 0; ks < 4; ks++) {
            const int k0 = ks * 16;
#pragma unroll
            for (int nt2 = 0; nt2 < 4; nt2++) {
                uint32_t r4[4];
                ldm_x4_t(r4, &sm.Vs[buf][k0 + (lane & 15)]
                                        [nt2 * 16 + (lane >> 4) * 8]);
                uint32_t b0[2] = { r4[0], r4[1] };
                uint32_t b1[2] = { r4[2], r4[3] };
                mma_f16(o[0][nt2 * 2],     pa[0][ks], b0);
                mma_f16(o[0][nt2 * 2 + 1], pa[0][ks], b1);
                mma_f16(o[1][nt2 * 2],     pa[1][ks], b0);
                mma_f16(o[1][nt2 * 2 + 1], pa[1][ks], b1);
            }
        }
    }

    // ---- epilogue: O /= l, store fp16 ----
#pragma unroll
    for (int mt = 0; mt < 2; mt++) {
        const float i0 = 1.0f / lr[mt][0];
        const float i1 = 1.0f / lr[mt][1];
        const int r = qtile * 128 + m0 + mt * 16 + g;
#pragma unroll
        for (int nt = 0; nt < 8; nt++) {
            const int c = h * 64 + nt * 8 + 2 * tq;
            *(half2*)&out[(size_t)(b * N_ + r) * C_ + c] =
                __floats2half2_rn(o[mt][nt][0] * i0, o[mt][nt][1] * i0);
            *(half2*)&out[(size_t)(b * N_ + r + 8) * C_ + c] =
                __floats2half2_rn(o[mt][nt][2] * i1, o[mt][nt][3] * i1);
        }
    }
#undef LOAD_KV
}

// ---------------------------------------------------------------------------
// Launch
// ---------------------------------------------------------------------------
extern "C" void kernel_launch(void* const* d_in, const int* in_sizes, int n_in,
                              void* d_out, int out_size)
{
    const float* x       = (const float*)d_in[0];
    const float* qkv_w   = (const float*)d_in[1];
    const float* qkv_b   = (const float*)d_in[2];
    const float* proj_w  = (const float*)d_in[3];
    const float* proj_b  = (const float*)d_in[4];
    const float* q_gamma = (const float*)d_in[5];
    const float* k_gamma = (const float*)d_in[6];
    float* out = (float*)d_out;

    void *p_xh, *p_wqkvh, *p_wprojh, *p_qkvh, *p_attnh, *p_tab;
    cudaGetSymbolAddress(&p_xh, g_xh);
    cudaGetSymbolAddress(&p_wqkvh, g_wqkvh);
    cudaGetSymbolAddress(&p_wprojh, g_wprojh);
    cudaGetSymbolAddress(&p_qkvh, g_qkvh);
    cudaGetSymbolAddress(&p_attnh, g_attnh);
    cudaGetSymbolAddress(&p_tab, g_ropetab);
    __half* xh     = (__half*)p_xh;
    __half* wqkvh  = (__half*)p_wqkvh;
    __half* wprojh = (__half*)p_wprojh;
    __half* qkvh   = (__half*)p_qkvh;
    __half* attnh  = (__half*)p_attnh;
    float2* tab    = (float2*)p_tab;

    const int flash_smem = (int)sizeof(FSmem);   // 73728
    cudaFuncSetAttribute(gemm_f16_kernel<0>,
                         cudaFuncAttributeMaxDynamicSharedMemorySize, GEMM_SMEM);
    cudaFuncSetAttribute(gemm_f16_kernel<1>,
                         cudaFuncAttributeMaxDynamicSharedMemorySize, GEMM_SMEM);
    cudaFuncSetAttribute(flash_f16_kernel,
                         cudaFuncAttributeMaxDynamicSharedMemorySize, flash_smem);

    // 0. prepass: fp16 conversion + rope table
    to_half_kernel<<<(TOKENS * C_) / 1024, 256>>>(x, xh);
    to_half_kernel<<<(C_ * 3 * C_) / 1024, 256>>>(qkv_w, wqkvh);
    to_half_kernel<<<(C_ * C_) / 1024, 256>>>(proj_w, wprojh);
    ropetab_kernel<<<(N_ * HD_) / 256, 256>>>(tab);

    // 1. QKV GEMM + fused RMSNorm/RoPE epilogue (fp16 out)
    {
        dim3 grid(3 * C_ / 128, TOKENS / 128);
        gemm_f16_kernel<1><<<grid, 128, GEMM_SMEM>>>(
            xh, wqkvh, qkv_b, nullptr, qkvh, q_gamma, k_gamma, tab,
            TOKENS, 3 * C_, C_);
    }

    // 2. Flash attention (32 q-rows/warp, reg-P, reg-Q, 3-stage KV)
    {
        dim3 grid(N_ / 128, B_ * H_);
        flash_f16_kernel<<<grid, 128, flash_smem>>>(qkvh, attnh);
    }

    // 3. Output projection (fp32 out)
    {
        dim3 grid(C_ / 128, TOKENS / 128);
        gemm_f16_kernel<0><<<grid, 128, GEMM_SMEM>>>(
            attnh, wprojh, proj_b, out, nullptr, nullptr, nullptr, nullptr,
            TOKENS, C_, C_);
    }
}

// round 11
// speedup vs baseline: 7.5580x; 1.0113x over previous
#include <cuda_runtime.h>
#include <cuda_fp16.h>
#include <math.h>
#include <stdint.h>

#define B_  32
#define N_  1024
#define C_  1024
#define H_  16
#define HD_ 64
#define TOKENS (B_ * N_)        // 32768
#define TOKSTRIDE 3072

// Scratch (static device globals; no runtime allocation)
__device__ __half g_xh[(size_t)TOKENS * C_];           // fp16 x
__device__ __half g_wqkvh[(size_t)C_ * 3 * C_];        // fp16 qkv_w [1024][3072]
__device__ __half g_wprojh[(size_t)C_ * C_];           // fp16 proj_w [1024][1024]
__device__ __half g_qkvh[(size_t)TOKENS * TOKSTRIDE];  // fp16 q(roped)/k(roped)/v
__device__ __half g_attnh[(size_t)TOKENS * C_];        // fp16 attention output
__device__ float2 g_ropetab[(size_t)N_ * HD_];         // (cos, sin) per (n, c)

// ---------------------------------------------------------------------------
// Helpers
// ---------------------------------------------------------------------------
__device__ __forceinline__ void ldm_x4(uint32_t* r, const void* p) {
    uint32_t a = (uint32_t)__cvta_generic_to_shared(p);
    asm volatile("ldmatrix.sync.aligned.m8n8.x4.shared.b16 {%0,%1,%2,%3}, [%4];"
                 : "=r"(r[0]), "=r"(r[1]), "=r"(r[2]), "=r"(r[3]) : "r"(a));
}
__device__ __forceinline__ void ldm_x4_t(uint32_t* r, const void* p) {
    uint32_t a = (uint32_t)__cvta_generic_to_shared(p);
    asm volatile("ldmatrix.sync.aligned.m8n8.x4.trans.shared.b16 {%0,%1,%2,%3}, [%4];"
                 : "=r"(r[0]), "=r"(r[1]), "=r"(r[2]), "=r"(r[3]) : "r"(a));
}

__device__ __forceinline__ void mma_f16(float* d, const uint32_t* a, const uint32_t* b) {
    asm volatile("mma.sync.aligned.m16n8k16.row.col.f32.f16.f16.f32 "
                 "{%0,%1,%2,%3}, {%4,%5,%6,%7}, {%8,%9}, {%0,%1,%2,%3};"
                 : "+f"(d[0]), "+f"(d[1]), "+f"(d[2]), "+f"(d[3])
                 : "r"(a[0]), "r"(a[1]), "r"(a[2]), "r"(a[3]), "r"(b[0]), "r"(b[1]));
}

__device__ __forceinline__ void cp16(void* dst, const void* src) {
    uint32_t d = (uint32_t)__cvta_generic_to_shared(dst);
    asm volatile("cp.async.cg.shared.global [%0], [%1], 16;" :: "r"(d), "l"(src));
}
__device__ __forceinline__ void cp_commit() { asm volatile("cp.async.commit_group;"); }
template <int NN>
__device__ __forceinline__ void cp_wait() { asm volatile("cp.async.wait_group %0;" :: "n"(NN)); }

__device__ __forceinline__ uint32_t packh2(float a, float b) {
    half2 h = __floats2half2_rn(a, b);
    return *(uint32_t*)&h;
}

// ---------------------------------------------------------------------------
// fp32 -> fp16 conversion prepass
// ---------------------------------------------------------------------------
__global__ __launch_bounds__(256)
void to_half_kernel(const float* __restrict__ in, __half* __restrict__ out) {
    int i = blockIdx.x * 256 + threadIdx.x;
    float4 v = ((const float4*)in)[i];
    ((half2*)out)[i * 2]     = __floats2half2_rn(v.x, v.y);
    ((half2*)out)[i * 2 + 1] = __floats2half2_rn(v.z, v.w);
}

// ---------------------------------------------------------------------------
// RoPE table: tab[n*64+c] = (cos, sin) of angle(n, c)
// ---------------------------------------------------------------------------
__global__ __launch_bounds__(256)
void ropetab_kernel(float2* __restrict__ tab) {
    int i = blockIdx.x * 256 + threadIdx.x;   // 0..65535
    int n = i >> 6, c = i & 63;
    const bool lo = (c < 32);
    const int j0 = c & 31;
    const float LOG2_THETA = 13.28771237954945f;
    float f = exp2f(-(float)(j0 & 15) * (1.0f / 16.0f) * LOG2_THETA);
    float t = lo ? (float)(n >> 5) : (float)(n & 31);
    float s, co;
    sincosf(t * f, &s, &co);
    tab[i] = make_float2(co, s);
}

// ---------------------------------------------------------------------------
// fp16 HMMA GEMM, CTA 128x128, BK=64, 128 threads (4 warps, 2x2 of 64x64).
// 2-stage cp.async pipeline, 3 CTAs/SM (12 warps/SM), regs capped at 170.
// B fragments loaded one-at-a-time to keep the live register set small.
// MODE 0: C(fp32) = A@B + bias.
// MODE 1: QKV fused epilogue -> fp16 out with RMSNorm+RoPE on q,k sections.
// ---------------------------------------------------------------------------
template <int MODE>
__global__ __launch_bounds__(128, 3)
void gemm_f16_kernel(const __half* __restrict__ A, const __half* __restrict__ Bm,
                     const float* __restrict__ bias, float* __restrict__ Cf,
                     __half* __restrict__ Ch,
                     const float* __restrict__ q_gamma,
                     const float* __restrict__ k_gamma,
                     const float2* __restrict__ ropetab,
                     int M, int N, int K)
{
    extern __shared__ char sraw[];
    __half (*As)[128][72] = (__half(*)[128][72])sraw;                        // 2*18432B
    __half (*Bs)[64][136] = (__half(*)[64][136])(sraw + 2 * 128 * 72 * 2);   // 2*17408B

    const int tid  = threadIdx.x;
    const int warp = tid >> 5, lane = tid & 31;
    const int wm = warp >> 1, wn = warp & 1;
    const int g = lane >> 2, tq = lane & 3;
    const int row0 = blockIdx.y * 128;
    const int col0 = blockIdx.x * 128;
    const int KT = K / 64;

#define LOAD_STAGE(S, KT0)                                                          \
    {                                                                               \
        _Pragma("unroll")                                                           \
        for (int i = 0; i < 8; i++) {                                               \
            int f = tid + i * 128;                                                  \
            int r_ = f >> 3, u_ = f & 7;                                            \
            cp16(&As[S][r_][u_ * 8],                                                \
                 A + (size_t)(row0 + r_) * K + (KT0) * 64 + u_ * 8);                \
            int br_ = f >> 4, nb_ = f & 15;                                         \
            cp16(&Bs[S][br_][nb_ * 8],                                              \
                 Bm + (size_t)((KT0) * 64 + br_) * N + col0 + nb_ * 8);             \
        }                                                                           \
        cp_commit();                                                                \
    }

    float acc[4][8][4];
#pragma unroll
    for (int a = 0; a < 4; a++)
#pragma unroll
        for (int b = 0; b < 8; b++)
#pragma unroll
            for (int c = 0; c < 4; c++) acc[a][b][c] = 0.0f;

    LOAD_STAGE(0, 0);
    LOAD_STAGE(1, 1);

    for (int kt = 0; kt < KT; kt++) {
        const int s = kt & 1;
        if (kt + 1 < KT) { cp_wait<1>(); } else { cp_wait<0>(); }
        __syncthreads();     // stage s fully loaded for ALL threads

#pragma unroll
        for (int ks = 0; ks < 4; ks++) {
            const int k0 = ks * 16;
            uint32_t afr[4][4];
#pragma unroll
            for (int mt = 0; mt < 4; mt++)
                ldm_x4(afr[mt], &As[s][wm * 64 + mt * 16 + (lane & 15)]
                                     [k0 + (lane >> 4) * 8]);
#pragma unroll
            for (int nt2 = 0; nt2 < 4; nt2++) {
                uint32_t r4[4];
                ldm_x4_t(r4, &Bs[s][k0 + (lane & 15)]
                                   [wn * 64 + nt2 * 16 + (lane >> 4) * 8]);
                uint32_t b0[2] = { r4[0], r4[1] };
                uint32_t b1[2] = { r4[2], r4[3] };
#pragma unroll
                for (int mt = 0; mt < 4; mt++) {
                    mma_f16(acc[mt][nt2 * 2],     afr[mt], b0);
                    mma_f16(acc[mt][nt2 * 2 + 1], afr[mt], b1);
                }
            }
        }

        if (kt + 2 < KT) {
            __syncthreads();            // all warps done reading stage s
            LOAD_STAGE(s, kt + 2);
        }
    }

    if (MODE == 0) {
#pragma unroll
        for (int mt = 0; mt < 4; mt++) {
            const int r = row0 + wm * 64 + mt * 16 + g;
#pragma unroll
            for (int nt = 0; nt < 8; nt++) {
                const int c = col0 + wn * 64 + nt * 8 + 2 * tq;
                const float b0 = bias[c], b1 = bias[c + 1];
                float2 v0 = make_float2(acc[mt][nt][0] + b0, acc[mt][nt][1] + b1);
                float2 v1 = make_float2(acc[mt][nt][2] + b0, acc[mt][nt][3] + b1);
                *(float2*)&Cf[(size_t)r * N + c]       = v0;
                *(float2*)&Cf[(size_t)(r + 8) * N + c] = v1;
            }
        }
    } else {
        const int gc  = col0 + wn * 64;
        const int sec = gc >> 10;            // 0=q, 1=k, 2=v
        float br[8][2], gr[8][2];
        const float* gam = (sec == 1) ? k_gamma : q_gamma;
#pragma unroll
        for (int nt = 0; nt < 8; nt++) {
            const int cc = nt * 8 + 2 * tq;
            br[nt][0] = bias[gc + cc];
            br[nt][1] = bias[gc + cc + 1];
            if (sec < 2) {
                gr[nt][0] = gam[cc];
                gr[nt][1] = gam[cc + 1];
            }
        }

#pragma unroll
        for (int mt = 0; mt < 4; mt++) {
#pragma unroll
            for (int rh = 0; rh < 2; rh++) {
                const int tok = row0 + wm * 64 + mt * 16 + g + rh * 8;
                __half* outp = Ch + (size_t)tok * TOKSTRIDE + gc;
                float vv[8][2];
#pragma unroll
                for (int nt = 0; nt < 8; nt++) {
                    vv[nt][0] = acc[mt][nt][rh * 2]     + br[nt][0];
                    vv[nt][1] = acc[mt][nt][rh * 2 + 1] + br[nt][1];
                }
                if (sec == 2) {
#pragma unroll
                    for (int nt = 0; nt < 8; nt++)
                        *(half2*)&outp[nt * 8 + 2 * tq] =
                            __floats2half2_rn(vv[nt][0], vv[nt][1]);
                    continue;
                }
                float ss = 0.0f;
#pragma unroll
                for (int nt = 0; nt < 8; nt++)
                    ss += vv[nt][0] * vv[nt][0] + vv[nt][1] * vv[nt][1];
                ss += __shfl_xor_sync(0xffffffffu, ss, 1);
                ss += __shfl_xor_sync(0xffffffffu, ss, 2);
                const float inv = rsqrtf(ss * (1.0f / 64.0f) + 1e-6f);
#pragma unroll
                for (int nt = 0; nt < 8; nt++) {
                    vv[nt][0] *= inv * gr[nt][0];
                    vv[nt][1] *= inv * gr[nt][1];
                }
                const int n = tok & (N_ - 1);
                const float2* tabn = ropetab + (size_t)n * HD_;
#pragma unroll
                for (int nt = 0; nt < 4; nt++) {
                    const int cc = nt * 8 + 2 * tq;
                    float2 t0 = tabn[cc], t1 = tabn[cc + 1];
                    float2 u0 = tabn[cc + 32], u1 = tabn[cc + 33];
                    float lo0 = vv[nt][0] * t0.x - vv[nt + 4][0] * t0.y;
                    float lo1 = vv[nt][1] * t1.x - vv[nt + 4][1] * t1.y;
                    float hi0 = vv[nt + 4][0] * u0.x + vv[nt][0] * u0.y;
                    float hi1 = vv[nt + 4][1] * u1.x + vv[nt][1] * u1.y;
                    *(half2*)&outp[cc]      = __floats2half2_rn(lo0, lo1);
                    *(half2*)&outp[cc + 32] = __floats2half2_rn(hi0, hi1);
                }
            }
        }
    }
#undef LOAD_STAGE
}

#define GEMM_SMEM ((2 * 128 * 72 + 2 * 64 * 136) * 2)   // 71680

// ---------------------------------------------------------------------------
// fp16 HMMA flash attention, fixed-max softmax, register-resident P (FA-2),
// hoisted Q fragments, 3-stage KV ring, 1 barrier/iter.
// CTA: 128 queries x 64-kv tiles. 4 warps (128 thr), warp = 32 q rows
// (2 m-tiles) -> 4 MMAs per K/V ldmatrix. 2 CTAs/SM.
// ---------------------------------------------------------------------------
struct FSmem {
    __half Qs[128][72];      // pre-scaled Q (staging)
    __half Ks[3][64][72];
    __half Vs[3][64][72];
};

__global__ __launch_bounds__(128, 2)
void flash_f16_kernel(const __half* __restrict__ qkvh, __half* __restrict__ out)
{
    extern __shared__ char sm_raw[];
    FSmem& sm = *reinterpret_cast<FSmem*>(sm_raw);

    const int tid  = threadIdx.x;
    const int warp = tid >> 5, lane = tid & 31;
    const int g = lane >> 2, tq = lane & 3;
    const int qtile = blockIdx.x;        // 0..7 (128 rows each)
    const int bh = blockIdx.y;           // 0..511
    const int b = bh >> 4, h = bh & 15;
    const int m0 = warp * 32;            // warp covers rows m0..m0+31

    const __half* qbase = qkvh + (size_t)b * N_ * TOKSTRIDE + h * HD_;
    const __half* kbase = qbase + C_;
    const __half* vbase = qbase + 2 * C_;

    const half2 hscale = __floats2half2_rn(0.125f, 0.125f);
    for (int i = tid; i < 2048; i += 128) {     // 128 rows x 16 quads
        int r = i >> 4, d4 = (i & 15) * 4;
        half2 a = *(const half2*)(qbase + (size_t)(qtile * 128 + r) * TOKSTRIDE + d4);
        half2 c = *(const half2*)(qbase + (size_t)(qtile * 128 + r) * TOKSTRIDE + d4 + 2);
        *(half2*)&sm.Qs[r][d4]     = __hmul2(a, hscale);
        *(half2*)&sm.Qs[r][d4 + 2] = __hmul2(c, hscale);
    }

#define LOAD_KV(BUF, KT0)                                                           \
    {                                                                               \
        for (int i = tid; i < 1024; i += 128) {                                     \
            int r_ = i >> 3, u_ = (i & 7) * 8;                                      \
            if (i < 512)                                                            \
                cp16(&sm.Ks[BUF][r_][u_],                                           \
                     kbase + (size_t)((KT0) * 64 + r_) * TOKSTRIDE + u_);           \
            else                                                                    \
                cp16(&sm.Vs[BUF][r_ - 64][u_],                                      \
                     vbase + (size_t)((KT0) * 64 + r_ - 64) * TOKSTRIDE + u_);      \
        }                                                                           \
        cp_commit();                                                                \
    }

    LOAD_KV(0, 0);
    LOAD_KV(1, 1);
    __syncthreads();    // Qs visible to all warps

    // Hoist Q fragments: aq[mt][ks], mt = m-tile (16 rows), ks = k-chunk
    uint32_t aq[2][4][4];
#pragma unroll
    for (int mt = 0; mt < 2; mt++)
#pragma unroll
        for (int ks = 0; ks < 4; ks++)
            ldm_x4(aq[mt][ks], &sm.Qs[m0 + mt * 16 + (lane & 15)]
                                     [ks * 16 + (lane >> 4) * 8]);

    float o[2][8][4];
    float lr[2][2];
#pragma unroll
    for (int mt = 0; mt < 2; mt++) {
        lr[mt][0] = lr[mt][1] = 0.0f;
#pragma unroll
        for (int c = 0; c < 8; c++)
#pragma unroll
            for (int d = 0; d < 4; d++) o[mt][c][d] = 0.0f;
    }

    const int ki = lane & 7, kq = lane >> 3;

    for (int kt = 0; kt < 16; kt++) {
        const int buf = kt % 3;
        if (kt + 1 < 16) { cp_wait<1>(); } else { cp_wait<0>(); }
        __syncthreads();    // stage kt ready; stage (kt+2)%3 free

        if (kt + 2 < 16) { LOAD_KV((kt + 2) % 3, kt + 2); }

        // ---- S = Q @ K^T (each K ldsm feeds 4 MMAs) ----
        float s[2][8][4];
#pragma unroll
        for (int mt = 0; mt < 2; mt++)
#pragma unroll
            for (int c = 0; c < 8; c++)
#pragma unroll
                for (int d = 0; d < 4; d++) s[mt][c][d] = 0.0f;

#pragma unroll
        for (int ks = 0; ks < 4; ks++) {
            const int k0 = ks * 16;
#pragma unroll
            for (int nt2 = 0; nt2 < 4; nt2++) {
                uint32_t r4[4];
                ldm_x4(r4, &sm.Ks[buf][nt2 * 16 + (kq >> 1) * 8 + ki]
                                      [k0 + (kq & 1) * 8]);
                uint32_t b0[2] = { r4[0], r4[1] };
                uint32_t b1[2] = { r4[2], r4[3] };
                mma_f16(s[0][nt2 * 2],     aq[0][ks], b0);
                mma_f16(s[0][nt2 * 2 + 1], aq[0][ks], b1);
                mma_f16(s[1][nt2 * 2],     aq[1][ks], b0);
                mma_f16(s[1][nt2 * 2 + 1], aq[1][ks], b1);
            }
        }

        // ---- fixed-max softmax: P = exp(s - 8), l += sum ----
#pragma unroll
        for (int mt = 0; mt < 2; mt++)
#pragma unroll
            for (int hf = 0; hf < 2; hf++) {
                float rs = 0.0f;
#pragma unroll
                for (int nt = 0; nt < 8; nt++) {
                    float e0 = __expf(s[mt][nt][hf * 2]     - 8.0f);
                    float e1 = __expf(s[mt][nt][hf * 2 + 1] - 8.0f);
                    s[mt][nt][hf * 2] = e0; s[mt][nt][hf * 2 + 1] = e1;
                    rs += e0 + e1;
                }
                rs += __shfl_xor_sync(0xffffffffu, rs, 1);
                rs += __shfl_xor_sync(0xffffffffu, rs, 2);
                lr[mt][hf] += rs;
            }

        // ---- pack P into A-fragments (register-resident) ----
        uint32_t pa[2][4][4];
#pragma unroll
        for (int mt = 0; mt < 2; mt++)
#pragma unroll
            for (int ks = 0; ks < 4; ks++) {
                pa[mt][ks][0] = packh2(s[mt][2 * ks][0],     s[mt][2 * ks][1]);
                pa[mt][ks][1] = packh2(s[mt][2 * ks][2],     s[mt][2 * ks][3]);
                pa[mt][ks][2] = packh2(s[mt][2 * ks + 1][0], s[mt][2 * ks + 1][1]);
                pa[mt][ks][3] = packh2(s[mt][2 * ks + 1][2], s[mt][2 * ks + 1][3]);
            }

        // ---- O += P @ V (each V ldsm feeds 4 MMAs) ----
#pragma unroll
        for (int ks = 0; ks < 4; ks++) {
            const int k0 = ks * 16;
#pragma unroll
            for (int nt2 = 0; nt2 < 4; nt2++) {
                uint32_t r4[4];
                ldm_x4_t(r4, &sm.Vs[buf][k0 + (lane & 15)]
                                        [nt2 * 16 + (lane >> 4) * 8]);
                uint32_t b0[2] = { r4[0], r4[1] };
                uint32_t b1[2] = { r4[2], r4[3] };
                mma_f16(o[0][nt2 * 2],     pa[0][ks], b0);
                mma_f16(o[0][nt2 * 2 + 1], pa[0][ks], b1);
                mma_f16(o[1][nt2 * 2],     pa[1][ks], b0);
                mma_f16(o[1][nt2 * 2 + 1], pa[1][ks], b1);
            }
        }
    }

    // ---- epilogue: O /= l, store fp16 ----
#pragma unroll
    for (int mt = 0; mt < 2; mt++) {
        const float i0 = 1.0f / lr[mt][0];
        const float i1 = 1.0f / lr[mt][1];
        const int r = qtile * 128 + m0 + mt * 16 + g;
#pragma unroll
        for (int nt = 0; nt < 8; nt++) {
            const int c = h * 64 + nt * 8 + 2 * tq;
            *(half2*)&out[(size_t)(b * N_ + r) * C_ + c] =
                __floats2half2_rn(o[mt][nt][0] * i0, o[mt][nt][1] * i0);
            *(half2*)&out[(size_t)(b * N_ + r + 8) * C_ + c] =
                __floats2half2_rn(o[mt][nt][2] * i1, o[mt][nt][3] * i1);
        }
    }
#undef LOAD_KV
}

// ---------------------------------------------------------------------------
// Launch
// ---------------------------------------------------------------------------
extern "C" void kernel_launch(void* const* d_in, const int* in_sizes, int n_in,
                              void* d_out, int out_size)
{
    const float* x       = (const float*)d_in[0];
    const float* qkv_w   = (const float*)d_in[1];
    const float* qkv_b   = (const float*)d_in[2];
    const float* proj_w  = (const float*)d_in[3];
    const float* proj_b  = (const float*)d_in[4];
    const float* q_gamma = (const float*)d_in[5];
    const float* k_gamma = (const float*)d_in[6];
    float* out = (float*)d_out;

    void *p_xh, *p_wqkvh, *p_wprojh, *p_qkvh, *p_attnh, *p_tab;
    cudaGetSymbolAddress(&p_xh, g_xh);
    cudaGetSymbolAddress(&p_wqkvh, g_wqkvh);
    cudaGetSymbolAddress(&p_wprojh, g_wprojh);
    cudaGetSymbolAddress(&p_qkvh, g_qkvh);
    cudaGetSymbolAddress(&p_attnh, g_attnh);
    cudaGetSymbolAddress(&p_tab, g_ropetab);
    __half* xh     = (__half*)p_xh;
    __half* wqkvh  = (__half*)p_wqkvh;
    __half* wprojh = (__half*)p_wprojh;
    __half* qkvh   = (__half*)p_qkvh;
    __half* attnh  = (__half*)p_attnh;
    float2* tab    = (float2*)p_tab;

    const int flash_smem = (int)sizeof(FSmem);   // 73728
    cudaFuncSetAttribute(gemm_f16_kernel<0>,
                         cudaFuncAttributeMaxDynamicSharedMemorySize, GEMM_SMEM);
    cudaFuncSetAttribute(gemm_f16_kernel<1>,
                         cudaFuncAttributeMaxDynamicSharedMemorySize, GEMM_SMEM);
    cudaFuncSetAttribute(flash_f16_kernel,
                         cudaFuncAttributeMaxDynamicSharedMemorySize, flash_smem);

    // 0. prepass: fp16 conversion + rope table
    to_half_kernel<<<(TOKENS * C_) / 1024, 256>>>(x, xh);
    to_half_kernel<<<(C_ * 3 * C_) / 1024, 256>>>(qkv_w, wqkvh);
    to_half_kernel<<<(C_ * C_) / 1024, 256>>>(proj_w, wprojh);
    ropetab_kernel<<<(N_ * HD_) / 256, 256>>>(tab);

    // 1. QKV GEMM + fused RMSNorm/RoPE epilogue (fp16 out)
    {
        dim3 grid(3 * C_ / 128, TOKENS / 128);
        gemm_f16_kernel<1><<<grid, 128, GEMM_SMEM>>>(
            xh, wqkvh, qkv_b, nullptr, qkvh, q_gamma, k_gamma, tab,
            TOKENS, 3 * C_, C_);
    }

    // 2. Flash attention (32 q-rows/warp, reg-P, reg-Q, 3-stage KV)
    {
        dim3 grid(N_ / 128, B_ * H_);
        flash_f16_kernel<<<grid, 128, flash_smem>>>(qkvh, attnh);
    }

    // 3. Output projection (fp32 out)
    {
        dim3 grid(C_ / 128, TOKENS / 128);
        gemm_f16_kernel<0><<<grid, 128, GEMM_SMEM>>>(
            attnh, wprojh, proj_b, out, nullptr, nullptr, nullptr, nullptr,
            TOKENS, C_, C_);
    }
}